// round 2
// baseline (speedup 1.0000x reference)
#include <cuda_runtime.h>
#include <math.h>

// Problem constants
#define Bb 4
#define Ll 2048
#define Dd 2048
#define Mm 64
#define Rr 128
#define BL (Bb*Ll)
#define OSCALE 0.125f   // 1/sqrt(64)

// ---------------- scratch (device globals; no allocation allowed) ----------
__device__ float g_shift[BL*Dd];     // silu(conv(x))  (also the residual)
__device__ float g_u[BL*Dd];         // ch * x
__device__ float g_zp[BL*384];       // [token][0..127]=rk, [128..255]=mg(pre-bias), [256..383]=h
__device__ float g_gates[BL*192];    // [token][0..63]=r, [64..127]=k_hat, [128..191]=exp(g)

// ---------------- f32x2 packed math helpers --------------------------------
__device__ __forceinline__ float2 ffma2(float2 a, float2 b, float2 c) {
    unsigned long long au = *reinterpret_cast<unsigned long long*>(&a);
    unsigned long long bu = *reinterpret_cast<unsigned long long*>(&b);
    unsigned long long cu = *reinterpret_cast<unsigned long long*>(&c);
    unsigned long long du;
    asm("fma.rn.f32x2 %0, %1, %2, %3;" : "=l"(du) : "l"(au), "l"(bu), "l"(cu));
    return *reinterpret_cast<float2*>(&du);
}
__device__ __forceinline__ float2 fmul2(float2 a, float2 b) {
    unsigned long long au = *reinterpret_cast<unsigned long long*>(&a);
    unsigned long long bu = *reinterpret_cast<unsigned long long*>(&b);
    unsigned long long du;
    asm("mul.rn.f32x2 %0, %1, %2;" : "=l"(du) : "l"(au), "l"(bu));
    return *reinterpret_cast<float2*>(&du);
}

__device__ __forceinline__ float sigmoidf_(float x) { return 1.f / (1.f + expf(-x)); }
__device__ __forceinline__ float softplusf_(float x) {
    return fmaxf(x, 0.f) + log1pf(expf(-fabsf(x)));
}

// ---------------- K1: causal depthwise conv (W=4) + SiLU -------------------
// grid (D/256, L/8, B), block 256. Each thread: one d, 8 consecutive t.
__global__ void conv_silu_kernel(const float* __restrict__ x,
                                 const float* __restrict__ cw,
                                 const float* __restrict__ cb) {
    int d  = blockIdx.x * 256 + threadIdx.x;
    int t0 = blockIdx.y * 8;
    int b  = blockIdx.z;
    float4 w = *reinterpret_cast<const float4*>(cw + d * 4);
    float bias = cb[d];
    const float* xb = x + ((size_t)b * Ll) * Dd + d;
    float* sp = g_shift + ((size_t)b * Ll) * Dd + d;
    float xm3 = (t0 - 3 >= 0) ? xb[(size_t)(t0 - 3) * Dd] : 0.f;
    float xm2 = (t0 - 2 >= 0) ? xb[(size_t)(t0 - 2) * Dd] : 0.f;
    float xm1 = (t0 - 1 >= 0) ? xb[(size_t)(t0 - 1) * Dd] : 0.f;
#pragma unroll
    for (int i = 0; i < 8; i++) {
        int t = t0 + i;
        float xt = xb[(size_t)t * Dd];
        float y = xm3 * w.x + xm2 * w.y + xm1 * w.z + xt * w.w + bias;
        sp[(size_t)t * Dd] = y * sigmoidf_(y);
        xm3 = xm2; xm2 = xm1; xm1 = xt;
    }
}

// ---------------- K2: projections GEMM --------------------------------------
// grid (BL/64, 3), block 256. Tile: 64 tokens x 128 outputs, K=2048 (BK=16).
// group 0: rk = shift @ in_proj_w^T ; group 1: mg = shift @ mem_gate_w^T ;
// group 2: h  = x     @ ch_gate_w0^T.
__global__ __launch_bounds__(256) void proj_gemm_kernel(
    const float* __restrict__ x,
    const float* __restrict__ w_inproj,
    const float* __restrict__ w_memgate,
    const float* __restrict__ w_ch0) {
    const int g = blockIdx.y;
    const float* A  = (g == 2) ? x : g_shift;
    const float* Wp = (g == 0) ? w_inproj : (g == 1) ? w_memgate : w_ch0;
    const int tok0 = blockIdx.x * 64;

    __shared__ float As[16 * 68];
    __shared__ float Bs[16 * 132];

    const int tid = threadIdx.x;
    const int tg = tid >> 4, ng = tid & 15;          // compute mapping
    const int a_tok = tok0 + (tid >> 2);
    const int a_k   = (tid & 3) * 4;
    const int b_n   = tid >> 1;
    const int b_k   = (tid & 1) * 8;

    float2 acc[4][4];
#pragma unroll
    for (int i = 0; i < 4; i++)
#pragma unroll
        for (int j = 0; j < 4; j++) acc[i][j] = make_float2(0.f, 0.f);

    const float* Aptr = A + (size_t)a_tok * Dd + a_k;
    const float* Bptr = Wp + (size_t)b_n * Dd + b_k;

    float4 av  = *reinterpret_cast<const float4*>(Aptr);
    float4 bv0 = *reinterpret_cast<const float4*>(Bptr);
    float4 bv1 = *reinterpret_cast<const float4*>(Bptr + 4);

    const int NT = Dd / 16;
    for (int kt = 0; kt < NT; ++kt) {
        {   // stage to smem (A transposed [k][tok], B transposed [k][n])
            float* as = As + a_k * 68 + (tid >> 2);
            as[0] = av.x; as[68] = av.y; as[2 * 68] = av.z; as[3 * 68] = av.w;
            float* bs = Bs + b_k * 132 + b_n;
            bs[0] = bv0.x; bs[132] = bv0.y; bs[2 * 132] = bv0.z; bs[3 * 132] = bv0.w;
            bs[4 * 132] = bv1.x; bs[5 * 132] = bv1.y; bs[6 * 132] = bv1.z; bs[7 * 132] = bv1.w;
        }
        __syncthreads();
        if (kt + 1 < NT) {
            av  = *reinterpret_cast<const float4*>(Aptr + (kt + 1) * 16);
            bv0 = *reinterpret_cast<const float4*>(Bptr + (kt + 1) * 16);
            bv1 = *reinterpret_cast<const float4*>(Bptr + (kt + 1) * 16 + 4);
        }
#pragma unroll
        for (int k = 0; k < 16; k++) {
            float4 a4  = *reinterpret_cast<const float4*>(As + k * 68 + tg * 4);
            float4 b40 = *reinterpret_cast<const float4*>(Bs + k * 132 + ng * 8);
            float4 b41 = *reinterpret_cast<const float4*>(Bs + k * 132 + ng * 8 + 4);
            float aval[4] = {a4.x, a4.y, a4.z, a4.w};
            float2 bp[4] = {make_float2(b40.x, b40.y), make_float2(b40.z, b40.w),
                            make_float2(b41.x, b41.y), make_float2(b41.z, b41.w)};
#pragma unroll
            for (int i = 0; i < 4; i++) {
                float2 aa = make_float2(aval[i], aval[i]);
#pragma unroll
                for (int j = 0; j < 4; j++) acc[i][j] = ffma2(aa, bp[j], acc[i][j]);
            }
        }
        __syncthreads();
    }
#pragma unroll
    for (int i = 0; i < 4; i++) {
        int token = tok0 + tg * 4 + i;
        float* op = g_zp + (size_t)token * 384 + g * 128 + ng * 8;
#pragma unroll
        for (int j = 0; j < 4; j++)
            *reinterpret_cast<float2*>(op + 2 * j) = acc[i][j];
    }
}

// ---------------- K3: u = sigmoid(h @ ch_gate_w1^T + b1) * x ----------------
// grid (BL/64, D/128), block 256. K=128 (BK=16, 8 iters).
__global__ __launch_bounds__(256) void ugemm_kernel(
    const float* __restrict__ x,
    const float* __restrict__ w1,   // (D, R) row-major
    const float* __restrict__ b1) {
    const int tok0 = blockIdx.x * 64;
    const int d0   = blockIdx.y * 128;

    __shared__ float As[16 * 68];
    __shared__ float Bs[16 * 132];

    const int tid = threadIdx.x;
    const int tg = tid >> 4, ng = tid & 15;
    const int a_tok = tok0 + (tid >> 2);
    const int a_k   = (tid & 3) * 4;
    const int b_n   = tid >> 1;
    const int b_k   = (tid & 1) * 8;

    float2 acc[4][4];
#pragma unroll
    for (int i = 0; i < 4; i++)
#pragma unroll
        for (int j = 0; j < 4; j++) acc[i][j] = make_float2(0.f, 0.f);

    const float* Aptr = g_zp + (size_t)a_tok * 384 + 256 + a_k;
    const float* Bptr = w1 + (size_t)(d0 + b_n) * Rr + b_k;

    float4 av  = *reinterpret_cast<const float4*>(Aptr);
    float4 bv0 = *reinterpret_cast<const float4*>(Bptr);
    float4 bv1 = *reinterpret_cast<const float4*>(Bptr + 4);

    const int NT = Rr / 16;  // 8
    for (int kt = 0; kt < NT; ++kt) {
        {
            float* as = As + a_k * 68 + (tid >> 2);
            as[0] = av.x; as[68] = av.y; as[2 * 68] = av.z; as[3 * 68] = av.w;
            float* bs = Bs + b_k * 132 + b_n;
            bs[0] = bv0.x; bs[132] = bv0.y; bs[2 * 132] = bv0.z; bs[3 * 132] = bv0.w;
            bs[4 * 132] = bv1.x; bs[5 * 132] = bv1.y; bs[6 * 132] = bv1.z; bs[7 * 132] = bv1.w;
        }
        __syncthreads();
        if (kt + 1 < NT) {
            av  = *reinterpret_cast<const float4*>(Aptr + (kt + 1) * 16);
            bv0 = *reinterpret_cast<const float4*>(Bptr + (kt + 1) * 16);
            bv1 = *reinterpret_cast<const float4*>(Bptr + (kt + 1) * 16 + 4);
        }
#pragma unroll
        for (int k = 0; k < 16; k++) {
            float4 a4  = *reinterpret_cast<const float4*>(As + k * 68 + tg * 4);
            float4 b40 = *reinterpret_cast<const float4*>(Bs + k * 132 + ng * 8);
            float4 b41 = *reinterpret_cast<const float4*>(Bs + k * 132 + ng * 8 + 4);
            float aval[4] = {a4.x, a4.y, a4.z, a4.w};
            float2 bp[4] = {make_float2(b40.x, b40.y), make_float2(b40.z, b40.w),
                            make_float2(b41.x, b41.y), make_float2(b41.z, b41.w)};
#pragma unroll
            for (int i = 0; i < 4; i++) {
                float2 aa = make_float2(aval[i], aval[i]);
#pragma unroll
                for (int j = 0; j < 4; j++) acc[i][j] = ffma2(aa, bp[j], acc[i][j]);
            }
        }
        __syncthreads();
    }
    // epilogue: sigmoid(z + b1[d]) * x
#pragma unroll
    for (int i = 0; i < 4; i++) {
        int token = tok0 + tg * 4 + i;
#pragma unroll
        for (int j = 0; j < 4; j++) {
            int dc = d0 + ng * 8 + 2 * j;
            float z0 = acc[i][j].x + b1[dc];
            float z1 = acc[i][j].y + b1[dc + 1];
            float u0 = sigmoidf_(z0) * x[(size_t)token * Dd + dc];
            float u1 = sigmoidf_(z1) * x[(size_t)token * Dd + dc + 1];
            float2 uv = make_float2(u0, u1);
            *reinterpret_cast<float2*>(g_u + (size_t)token * Dd + dc) = uv;
        }
    }
}

// ---------------- K4: gate math per token -----------------------------------
// grid (BL/4), block 128 (one warp per token; lane handles m and m+32)
__global__ void gates_kernel(const float* __restrict__ mb) {
    int warp = threadIdx.x >> 5;
    int lane = threadIdx.x & 31;
    int token = blockIdx.x * 4 + warp;
    const float* zp = g_zp + (size_t)token * 384;

    float r_a = zp[lane],        r_b = zp[32 + lane];
    float k_a = zp[64 + lane],   k_b = zp[96 + lane];
    float m1a = zp[128 + lane] + mb[lane];
    float m1b = zp[160 + lane] + mb[32 + lane];
    float m2a = zp[192 + lane] + mb[64 + lane];
    float m2b = zp[224 + lane] + mb[96 + lane];

    float sela = softplusf_(m1a), selb = softplusf_(m1b);
    float taua = sigmoidf_(m2a),  taub = sigmoidf_(m2b);
    float ita = expf(taua * logf(sela));
    float itb = expf(taub * logf(selb));
    float ega = expf(-sela * taua);
    float egb = expf(-selb * taub);

    float ss = k_a * k_a + k_b * k_b;
#pragma unroll
    for (int o = 16; o > 0; o >>= 1) ss += __shfl_xor_sync(0xffffffffu, ss, o);
    float inv = 1.f / fmaxf(sqrtf(ss), 1e-12f);

    float* go = g_gates + (size_t)token * 192;
    go[lane]       = r_a;            go[32 + lane]  = r_b;
    go[64 + lane]  = k_a * inv * ita; go[96 + lane]  = k_b * inv * itb;
    go[128 + lane] = ega;            go[160 + lane] = egb;
}

// ---------------- K5: sequential scan + residual epilogue -------------------
// grid (D/64, B), block 64. One thread per (b,d) column; M=64 state in regs
// as 32 float2. Gates broadcast via smem double buffer (48 float4 per step).
__global__ __launch_bounds__(64) void scan_kernel(const float* __restrict__ rw,
                                                  float* __restrict__ out) {
    int tid = threadIdx.x;
    int d = blockIdx.x * 64 + tid;
    int b = blockIdx.y;
    __shared__ float sg[2][192];
    const float* gb = g_gates + (size_t)b * Ll * 192;
    if (tid < 48)
        *reinterpret_cast<float4*>(&sg[0][tid * 4]) =
            *reinterpret_cast<const float4*>(gb + tid * 4);
    __syncthreads();

    float2 S[32];
#pragma unroll
    for (int p = 0; p < 32; p++) S[p] = make_float2(0.f, 0.f);

    const float* ub = g_u + ((size_t)b * Ll) * Dd + d;
    const float* sb = g_shift + ((size_t)b * Ll) * Dd + d;
    float* ob = out + ((size_t)b * Ll) * Dd + d;
    float rwd = rw[d];
    float ucur = ub[0], scur = sb[0];

    for (int t = 0; t < Ll; t++) {
        int cur = t & 1;
        float4 nx = make_float4(0.f, 0.f, 0.f, 0.f);
        float un = 0.f, sn = 0.f;
        if (t + 1 < Ll) {
            if (tid < 48)
                nx = *reinterpret_cast<const float4*>(gb + (size_t)(t + 1) * 192 + tid * 4);
            un = ub[(size_t)(t + 1) * Dd];
            sn = sb[(size_t)(t + 1) * Dd];
        }
        float2 uu = make_float2(ucur, ucur);
        float2 a0 = make_float2(0.f, 0.f), a1 = a0, a2 = a0, a3 = a0;
#pragma unroll
        for (int q = 0; q < 16; q++) {
            float4 r4 = *reinterpret_cast<const float4*>(&sg[cur][q * 4]);
            float4 k4 = *reinterpret_cast<const float4*>(&sg[cur][64 + q * 4]);
            float4 e4 = *reinterpret_cast<const float4*>(&sg[cur][128 + q * 4]);
            float2 kv0 = fmul2(make_float2(k4.x, k4.y), uu);
            S[2 * q] = ffma2(make_float2(e4.x, e4.y), S[2 * q], kv0);
            float2 kv1 = fmul2(make_float2(k4.z, k4.w), uu);
            S[2 * q + 1] = ffma2(make_float2(e4.z, e4.w), S[2 * q + 1], kv1);
            if (q & 1) {
                a0 = ffma2(make_float2(r4.x, r4.y), S[2 * q], a0);
                a1 = ffma2(make_float2(r4.z, r4.w), S[2 * q + 1], a1);
            } else {
                a2 = ffma2(make_float2(r4.x, r4.y), S[2 * q], a2);
                a3 = ffma2(make_float2(r4.z, r4.w), S[2 * q + 1], a3);
            }
        }
        float sx = (a0.x + a1.x) + (a2.x + a3.x);
        float sy = (a0.y + a1.y) + (a2.y + a3.y);
        float o = OSCALE * (sx + sy) + scur * rwd;
        ob[(size_t)t * Dd] = o;
        if (t + 1 < Ll && tid < 48)
            *reinterpret_cast<float4*>(&sg[cur ^ 1][tid * 4]) = nx;
        __syncthreads();
        ucur = un; scur = sn;
    }
}

// ---------------- launch -----------------------------------------------------
extern "C" void kernel_launch(void* const* d_in, const int* in_sizes, int n_in,
                              void* d_out, int out_size) {
    const float* x        = (const float*)d_in[0];  // (B,L,D)
    const float* conv_w   = (const float*)d_in[1];  // (D,4)
    const float* conv_b   = (const float*)d_in[2];  // (D,)
    const float* in_proj  = (const float*)d_in[3];  // (128,D)
    const float* ch_w0    = (const float*)d_in[4];  // (128,D)
    const float* ch_w1    = (const float*)d_in[5];  // (D,128)
    const float* ch_b1    = (const float*)d_in[6];  // (D,)
    const float* mem_w    = (const float*)d_in[7];  // (128,D)
    const float* mem_b    = (const float*)d_in[8];  // (128,)
    const float* res_w    = (const float*)d_in[9];  // (D,)
    float* out = (float*)d_out;

    conv_silu_kernel<<<dim3(Dd / 256, Ll / 8, Bb), 256>>>(x, conv_w, conv_b);
    proj_gemm_kernel<<<dim3(BL / 64, 3), 256>>>(x, in_proj, mem_w, ch_w0);
    ugemm_kernel<<<dim3(BL / 64, Dd / 128), 256>>>(x, ch_w1, ch_b1);
    gates_kernel<<<dim3(BL / 4), 128>>>(mem_b);
    scan_kernel<<<dim3(Dd / 64, Bb), 64>>>(res_w, out);
}

// round 3
// speedup vs baseline: 1.8014x; 1.8014x over previous
#include <cuda_runtime.h>
#include <math.h>

// Problem constants
#define Bb 4
#define Ll 2048
#define Dd 2048
#define Mm 64
#define Rr 128
#define BL (Bb*Ll)
#define OSCALE 0.125f   // 1/sqrt(64)
#define PF 4            // scan gates prefetch stages (power of 2)

// ---------------- scratch (device globals; no allocation allowed) ----------
__device__ float g_shift[BL*Dd];     // silu(conv(x))  (also the residual)
__device__ float g_u[BL*Dd];         // ch * x
__device__ float g_zp[BL*384];       // [token][0..127]=rk, [128..255]=mg(pre-bias), [256..383]=h
__device__ float g_gates[BL*192];    // [token][0..63]=r, [64..127]=k_hat, [128..191]=exp(g)

// ---------------- f32x2 packed math helpers --------------------------------
__device__ __forceinline__ float2 ffma2(float2 a, float2 b, float2 c) {
    unsigned long long au = *reinterpret_cast<unsigned long long*>(&a);
    unsigned long long bu = *reinterpret_cast<unsigned long long*>(&b);
    unsigned long long cu = *reinterpret_cast<unsigned long long*>(&c);
    unsigned long long du;
    asm("fma.rn.f32x2 %0, %1, %2, %3;" : "=l"(du) : "l"(au), "l"(bu), "l"(cu));
    return *reinterpret_cast<float2*>(&du);
}
__device__ __forceinline__ float2 fmul2(float2 a, float2 b) {
    unsigned long long au = *reinterpret_cast<unsigned long long*>(&a);
    unsigned long long bu = *reinterpret_cast<unsigned long long*>(&b);
    unsigned long long du;
    asm("mul.rn.f32x2 %0, %1, %2;" : "=l"(du) : "l"(au), "l"(bu));
    return *reinterpret_cast<float2*>(&du);
}

__device__ __forceinline__ float sigmoidf_(float x) { return 1.f / (1.f + expf(-x)); }
__device__ __forceinline__ float softplusf_(float x) {
    return fmaxf(x, 0.f) + log1pf(expf(-fabsf(x)));
}

// ---------------- K1: causal depthwise conv (W=4) + SiLU -------------------
__global__ void conv_silu_kernel(const float* __restrict__ x,
                                 const float* __restrict__ cw,
                                 const float* __restrict__ cb) {
    int d  = blockIdx.x * 256 + threadIdx.x;
    int t0 = blockIdx.y * 8;
    int b  = blockIdx.z;
    float4 w = *reinterpret_cast<const float4*>(cw + d * 4);
    float bias = cb[d];
    const float* xb = x + ((size_t)b * Ll) * Dd + d;
    float* sp = g_shift + ((size_t)b * Ll) * Dd + d;
    float xm3 = (t0 - 3 >= 0) ? xb[(size_t)(t0 - 3) * Dd] : 0.f;
    float xm2 = (t0 - 2 >= 0) ? xb[(size_t)(t0 - 2) * Dd] : 0.f;
    float xm1 = (t0 - 1 >= 0) ? xb[(size_t)(t0 - 1) * Dd] : 0.f;
#pragma unroll
    for (int i = 0; i < 8; i++) {
        int t = t0 + i;
        float xt = xb[(size_t)t * Dd];
        float y = xm3 * w.x + xm2 * w.y + xm1 * w.z + xt * w.w + bias;
        sp[(size_t)t * Dd] = y * sigmoidf_(y);
        xm3 = xm2; xm2 = xm1; xm1 = xt;
    }
}

// ---------------- K2: projections GEMM (double-buffer, 1 sync/tile) --------
// grid (BL/64, 3), block 256. Tile: 64 tokens x 128 outputs, K=2048 (BK=16).
__global__ __launch_bounds__(256) void proj_gemm_kernel(
    const float* __restrict__ x,
    const float* __restrict__ w_inproj,
    const float* __restrict__ w_memgate,
    const float* __restrict__ w_ch0) {
    const int g = blockIdx.y;
    const float* A  = (g == 2) ? x : g_shift;
    const float* Wp = (g == 0) ? w_inproj : (g == 1) ? w_memgate : w_ch0;
    const int tok0 = blockIdx.x * 64;

    __shared__ float As[2][16 * 68];
    __shared__ float Bs[2][16 * 132];

    const int tid = threadIdx.x;
    const int tg = tid >> 4, ng = tid & 15;
    const int a_k   = (tid & 3) * 4;
    const int b_n   = tid >> 1;
    const int b_k   = (tid & 1) * 8;

    float2 acc[4][4];
#pragma unroll
    for (int i = 0; i < 4; i++)
#pragma unroll
        for (int j = 0; j < 4; j++) acc[i][j] = make_float2(0.f, 0.f);

    const float* Aptr = A + (size_t)(tok0 + (tid >> 2)) * Dd + a_k;
    const float* Bptr = Wp + (size_t)b_n * Dd + b_k;

    float4 av  = *reinterpret_cast<const float4*>(Aptr);
    float4 bv0 = *reinterpret_cast<const float4*>(Bptr);
    float4 bv1 = *reinterpret_cast<const float4*>(Bptr + 4);

    const int NT = Dd / 16;
    for (int kt = 0; kt < NT; ++kt) {
        const int p = kt & 1;
        {   // stage to smem (A transposed [k][tok], B transposed [k][n])
            float* as = As[p] + a_k * 68 + (tid >> 2);
            as[0] = av.x; as[68] = av.y; as[2 * 68] = av.z; as[3 * 68] = av.w;
            float* bs = Bs[p] + b_k * 132 + b_n;
            bs[0] = bv0.x; bs[132] = bv0.y; bs[2 * 132] = bv0.z; bs[3 * 132] = bv0.w;
            bs[4 * 132] = bv1.x; bs[5 * 132] = bv1.y; bs[6 * 132] = bv1.z; bs[7 * 132] = bv1.w;
        }
        __syncthreads();
        if (kt + 1 < NT) {
            av  = *reinterpret_cast<const float4*>(Aptr + (kt + 1) * 16);
            bv0 = *reinterpret_cast<const float4*>(Bptr + (kt + 1) * 16);
            bv1 = *reinterpret_cast<const float4*>(Bptr + (kt + 1) * 16 + 4);
        }
#pragma unroll
        for (int k = 0; k < 16; k++) {
            float4 a4  = *reinterpret_cast<const float4*>(As[p] + k * 68 + tg * 4);
            float4 b40 = *reinterpret_cast<const float4*>(Bs[p] + k * 132 + ng * 8);
            float4 b41 = *reinterpret_cast<const float4*>(Bs[p] + k * 132 + ng * 8 + 4);
            float aval[4] = {a4.x, a4.y, a4.z, a4.w};
            float2 bp[4] = {make_float2(b40.x, b40.y), make_float2(b40.z, b40.w),
                            make_float2(b41.x, b41.y), make_float2(b41.z, b41.w)};
#pragma unroll
            for (int i = 0; i < 4; i++) {
                float2 aa = make_float2(aval[i], aval[i]);
#pragma unroll
                for (int j = 0; j < 4; j++) acc[i][j] = ffma2(aa, bp[j], acc[i][j]);
            }
        }
    }
#pragma unroll
    for (int i = 0; i < 4; i++) {
        int token = tok0 + tg * 4 + i;
        float* op = g_zp + (size_t)token * 384 + g * 128 + ng * 8;
#pragma unroll
        for (int j = 0; j < 4; j++)
            *reinterpret_cast<float2*>(op + 2 * j) = acc[i][j];
    }
}

// ---------------- K3: u = sigmoid(h @ ch_gate_w1^T + b1) * x ----------------
__global__ __launch_bounds__(256) void ugemm_kernel(
    const float* __restrict__ x,
    const float* __restrict__ w1,   // (D, R) row-major
    const float* __restrict__ b1) {
    const int tok0 = blockIdx.x * 64;
    const int d0   = blockIdx.y * 128;

    __shared__ float As[2][16 * 68];
    __shared__ float Bs[2][16 * 132];

    const int tid = threadIdx.x;
    const int tg = tid >> 4, ng = tid & 15;
    const int a_k   = (tid & 3) * 4;
    const int b_n   = tid >> 1;
    const int b_k   = (tid & 1) * 8;

    float2 acc[4][4];
#pragma unroll
    for (int i = 0; i < 4; i++)
#pragma unroll
        for (int j = 0; j < 4; j++) acc[i][j] = make_float2(0.f, 0.f);

    const float* Aptr = g_zp + (size_t)(tok0 + (tid >> 2)) * 384 + 256 + a_k;
    const float* Bptr = w1 + (size_t)(d0 + b_n) * Rr + b_k;

    float4 av  = *reinterpret_cast<const float4*>(Aptr);
    float4 bv0 = *reinterpret_cast<const float4*>(Bptr);
    float4 bv1 = *reinterpret_cast<const float4*>(Bptr + 4);

    const int NT = Rr / 16;  // 8
    for (int kt = 0; kt < NT; ++kt) {
        const int p = kt & 1;
        {
            float* as = As[p] + a_k * 68 + (tid >> 2);
            as[0] = av.x; as[68] = av.y; as[2 * 68] = av.z; as[3 * 68] = av.w;
            float* bs = Bs[p] + b_k * 132 + b_n;
            bs[0] = bv0.x; bs[132] = bv0.y; bs[2 * 132] = bv0.z; bs[3 * 132] = bv0.w;
            bs[4 * 132] = bv1.x; bs[5 * 132] = bv1.y; bs[6 * 132] = bv1.z; bs[7 * 132] = bv1.w;
        }
        __syncthreads();
        if (kt + 1 < NT) {
            av  = *reinterpret_cast<const float4*>(Aptr + (kt + 1) * 16);
            bv0 = *reinterpret_cast<const float4*>(Bptr + (kt + 1) * 16);
            bv1 = *reinterpret_cast<const float4*>(Bptr + (kt + 1) * 16 + 4);
        }
#pragma unroll
        for (int k = 0; k < 16; k++) {
            float4 a4  = *reinterpret_cast<const float4*>(As[p] + k * 68 + tg * 4);
            float4 b40 = *reinterpret_cast<const float4*>(Bs[p] + k * 132 + ng * 8);
            float4 b41 = *reinterpret_cast<const float4*>(Bs[p] + k * 132 + ng * 8 + 4);
            float aval[4] = {a4.x, a4.y, a4.z, a4.w};
            float2 bp[4] = {make_float2(b40.x, b40.y), make_float2(b40.z, b40.w),
                            make_float2(b41.x, b41.y), make_float2(b41.z, b41.w)};
#pragma unroll
            for (int i = 0; i < 4; i++) {
                float2 aa = make_float2(aval[i], aval[i]);
#pragma unroll
                for (int j = 0; j < 4; j++) acc[i][j] = ffma2(aa, bp[j], acc[i][j]);
            }
        }
    }
#pragma unroll
    for (int i = 0; i < 4; i++) {
        int token = tok0 + tg * 4 + i;
#pragma unroll
        for (int j = 0; j < 4; j++) {
            int dc = d0 + ng * 8 + 2 * j;
            float z0 = acc[i][j].x + b1[dc];
            float z1 = acc[i][j].y + b1[dc + 1];
            float u0 = sigmoidf_(z0) * x[(size_t)token * Dd + dc];
            float u1 = sigmoidf_(z1) * x[(size_t)token * Dd + dc + 1];
            float2 uv = make_float2(u0, u1);
            *reinterpret_cast<float2*>(g_u + (size_t)token * Dd + dc) = uv;
        }
    }
}

// ---------------- K4: gate math per token -----------------------------------
__global__ void gates_kernel(const float* __restrict__ mb) {
    int warp = threadIdx.x >> 5;
    int lane = threadIdx.x & 31;
    int token = blockIdx.x * 4 + warp;
    const float* zp = g_zp + (size_t)token * 384;

    float r_a = zp[lane],        r_b = zp[32 + lane];
    float k_a = zp[64 + lane],   k_b = zp[96 + lane];
    float m1a = zp[128 + lane] + mb[lane];
    float m1b = zp[160 + lane] + mb[32 + lane];
    float m2a = zp[192 + lane] + mb[64 + lane];
    float m2b = zp[224 + lane] + mb[96 + lane];

    float sela = softplusf_(m1a), selb = softplusf_(m1b);
    float taua = sigmoidf_(m2a),  taub = sigmoidf_(m2b);
    float ita = expf(taua * logf(sela));
    float itb = expf(taub * logf(selb));
    float ega = expf(-sela * taua);
    float egb = expf(-selb * taub);

    float ss = k_a * k_a + k_b * k_b;
#pragma unroll
    for (int o = 16; o > 0; o >>= 1) ss += __shfl_xor_sync(0xffffffffu, ss, o);
    float inv = 1.f / fmaxf(sqrtf(ss), 1e-12f);

    float* go = g_gates + (size_t)token * 192;
    go[lane]       = r_a;             go[32 + lane]  = r_b;
    go[64 + lane]  = k_a * inv * ita; go[96 + lane]  = k_b * inv * itb;
    go[128 + lane] = ega;             go[160 + lane] = egb;
}

// ---------------- K5: sequential scan (m-split, deep prefetch) --------------
// grid (D/64, B, 2). Block 64 threads (2 warps). Each block owns 32 of the 64
// m-states for 64 d-columns; both halves atomicAdd into the zeroed output
// (2 commutative fp32 adds -> bit-deterministic). Gates arrive via a 4-stage
// per-warp cp.async ring; u/shift via an 8-deep register FIFO (~1000 cyc slack
// vs 577-cyc DRAM latency). No __syncthreads in the time loop.
__global__ __launch_bounds__(64) void scan_kernel(const float* __restrict__ rw,
                                                  float* __restrict__ out) {
    const int tid = threadIdx.x;
    const int w = tid >> 5, lane = tid & 31;
    const int d = blockIdx.x * 64 + tid;
    const int b = blockIdx.y;
    const int h = blockIdx.z;            // m half: states m = h*32 .. h*32+31

    __shared__ __align__(16) float sg[2][PF][96];   // per-warp gate stages: r(32) k(32) e(32)

    const float* gb = g_gates + (size_t)b * Ll * 192;
    const int ch  = lane >> 3;           // 0..3 (0..2 active)
    const int off = (lane & 7) * 4;
    const int gsrc_off = (ch == 0 ? h * 32 : ch == 1 ? 64 + h * 32 : 128 + h * 32) + off;
    const bool active = lane < 24;
    const unsigned sbase =
        (unsigned)__cvta_generic_to_shared(&sg[w][0][ch * 32 + off]);

    // prologue: issue stages 0..PF-2
#pragma unroll
    for (int s = 0; s < PF - 1; s++) {
        if (active) {
            const float* src = gb + (size_t)s * 192 + gsrc_off;
            unsigned dst = sbase + s * 96 * 4;
            asm volatile("cp.async.ca.shared.global [%0], [%1], 16;"
                         :: "r"(dst), "l"(src));
        }
        asm volatile("cp.async.commit_group;" ::: "memory");
    }

    float2 S[16];
#pragma unroll
    for (int p = 0; p < 16; p++) S[p] = make_float2(0.f, 0.f);

    const float* ub = g_u + ((size_t)b * Ll) * Dd + d;
    const float* sb = g_shift + ((size_t)b * Ll) * Dd + d;
    float* ob = out + ((size_t)b * Ll) * Dd + d;
    const float rwd = (h == 0) ? rw[d] : 0.f;

    float upf[8], spf[8];
#pragma unroll
    for (int i = 0; i < 8; i++) {
        upf[i] = __ldcg(ub + (size_t)i * Dd);
        spf[i] = (h == 0) ? __ldcg(sb + (size_t)i * Dd) : 0.f;
    }

    for (int tb = 0; tb < Ll; tb += 8) {
#pragma unroll
        for (int j = 0; j < 8; j++) {
            const int t = tb + j;
            asm volatile("cp.async.wait_group 2;" ::: "memory");
            __syncwarp();
            const float* g0 = &sg[w][t & (PF - 1)][0];

            float2 uu = make_float2(upf[j], upf[j]);
            float2 a0 = make_float2(0.f, 0.f), a1 = a0;
#pragma unroll
            for (int q = 0; q < 8; q++) {
                float4 r4 = *reinterpret_cast<const float4*>(g0 + q * 4);
                float4 k4 = *reinterpret_cast<const float4*>(g0 + 32 + q * 4);
                float4 e4 = *reinterpret_cast<const float4*>(g0 + 64 + q * 4);
                S[2 * q]     = ffma2(make_float2(e4.x, e4.y), S[2 * q],
                                     fmul2(make_float2(k4.x, k4.y), uu));
                S[2 * q + 1] = ffma2(make_float2(e4.z, e4.w), S[2 * q + 1],
                                     fmul2(make_float2(k4.z, k4.w), uu));
                a0 = ffma2(make_float2(r4.x, r4.y), S[2 * q],     a0);
                a1 = ffma2(make_float2(r4.z, r4.w), S[2 * q + 1], a1);
            }
            float o = OSCALE * ((a0.x + a0.y) + (a1.x + a1.y)) + spf[j] * rwd;
            atomicAdd(ob + (size_t)t * Dd, o);

            // issue gates stage for t+PF-1 (always commit to keep group count)
            const int tn = t + PF - 1;
            if (tn < Ll && active) {
                const float* src = gb + (size_t)tn * 192 + gsrc_off;
                unsigned dst = sbase + (tn & (PF - 1)) * 96 * 4;
                asm volatile("cp.async.ca.shared.global [%0], [%1], 16;"
                             :: "r"(dst), "l"(src));
            }
            asm volatile("cp.async.commit_group;" ::: "memory");

            // refill u/s FIFO for t+8
            if (t + 8 < Ll) {
                upf[j] = __ldcg(ub + (size_t)(t + 8) * Dd);
                spf[j] = (h == 0) ? __ldcg(sb + (size_t)(t + 8) * Dd) : 0.f;
            }
        }
    }
}

// ---------------- launch -----------------------------------------------------
extern "C" void kernel_launch(void* const* d_in, const int* in_sizes, int n_in,
                              void* d_out, int out_size) {
    const float* x        = (const float*)d_in[0];  // (B,L,D)
    const float* conv_w   = (const float*)d_in[1];  // (D,4)
    const float* conv_b   = (const float*)d_in[2];  // (D,)
    const float* in_proj  = (const float*)d_in[3];  // (128,D)
    const float* ch_w0    = (const float*)d_in[4];  // (128,D)
    const float* ch_w1    = (const float*)d_in[5];  // (D,128)
    const float* ch_b1    = (const float*)d_in[6];  // (D,)
    const float* mem_w    = (const float*)d_in[7];  // (128,D)
    const float* mem_b    = (const float*)d_in[8];  // (128,)
    const float* res_w    = (const float*)d_in[9];  // (D,)
    float* out = (float*)d_out;

    conv_silu_kernel<<<dim3(Dd / 256, Ll / 8, Bb), 256>>>(x, conv_w, conv_b);
    proj_gemm_kernel<<<dim3(BL / 64, 3), 256>>>(x, in_proj, mem_w, ch_w0);
    ugemm_kernel<<<dim3(BL / 64, Dd / 128), 256>>>(x, ch_w1, ch_b1);
    gates_kernel<<<dim3(BL / 4), 128>>>(mem_b);
    cudaMemsetAsync(out, 0, (size_t)out_size * sizeof(float), 0);
    scan_kernel<<<dim3(Dd / 64, Bb, 2), 64>>>(res_w, out);
}

// round 5
// speedup vs baseline: 2.3962x; 1.3302x over previous
#include <cuda_runtime.h>
#include <cuda_bf16.h>
#include <math.h>

// Problem constants
#define Bb 4
#define Ll 2048
#define Dd 2048
#define Mm 64
#define Rr 128
#define BL (Bb*Ll)
#define OSCALE 0.125f   // 1/sqrt(64)
#define PF 4            // scan gates prefetch stages (power of 2)

// ---------------- scratch (device globals; no allocation allowed) ----------
__device__ float g_shift[BL*Dd];     // silu(conv(x))  (residual, scan input)
__device__ float g_u[BL*Dd];         // ch * x
__device__ float g_zp[BL*384];       // [token][0..127]=rk, [128..255]=mg(pre-bias), [256..383]=h
__device__ float g_gates[BL*192];    // [token][0..63]=r, [64..127]=k_hat, [128..191]=exp(g)

// bf16 splits for tensor-core 3xBF16 GEMM
__device__ __nv_bfloat16 g_sh_hi[BL*Dd], g_sh_lo[BL*Dd];
__device__ __nv_bfloat16 g_x_hi[BL*Dd],  g_x_lo[BL*Dd];
__device__ __nv_bfloat16 g_b01_hi[256*Dd], g_b01_lo[256*Dd];  // [in_proj;mem_gate]
__device__ __nv_bfloat16 g_b2_hi[128*Dd],  g_b2_lo[128*Dd];   // ch_gate_w0

// ---------------- f32x2 packed math helpers --------------------------------
__device__ __forceinline__ float2 ffma2(float2 a, float2 b, float2 c) {
    unsigned long long au = *reinterpret_cast<unsigned long long*>(&a);
    unsigned long long bu = *reinterpret_cast<unsigned long long*>(&b);
    unsigned long long cu = *reinterpret_cast<unsigned long long*>(&c);
    unsigned long long du;
    asm("fma.rn.f32x2 %0, %1, %2, %3;" : "=l"(du) : "l"(au), "l"(bu), "l"(cu));
    return *reinterpret_cast<float2*>(&du);
}
__device__ __forceinline__ float2 fmul2(float2 a, float2 b) {
    unsigned long long au = *reinterpret_cast<unsigned long long*>(&a);
    unsigned long long bu = *reinterpret_cast<unsigned long long*>(&b);
    unsigned long long du;
    asm("mul.rn.f32x2 %0, %1, %2;" : "=l"(du) : "l"(au), "l"(bu));
    return *reinterpret_cast<float2*>(&du);
}
__device__ __forceinline__ float sigmoidf_(float x) { return 1.f / (1.f + expf(-x)); }
__device__ __forceinline__ float softplusf_(float x) {
    return fmaxf(x, 0.f) + log1pf(expf(-fabsf(x)));
}
__device__ __forceinline__ void split_bf16(float v, __nv_bfloat16* hi, __nv_bfloat16* lo) {
    __nv_bfloat16 h = __float2bfloat16_rn(v);
    *hi = h;
    *lo = __float2bfloat16_rn(v - __bfloat162float(h));
}

// ---------------- warp-MMA helpers (sm_80+ PTX; works on bare sm_103) ------
__device__ __forceinline__ void ldsm4(unsigned& r0, unsigned& r1, unsigned& r2,
                                      unsigned& r3, unsigned addr) {
    asm volatile("ldmatrix.sync.aligned.m8n8.x4.shared.b16 {%0,%1,%2,%3}, [%4];"
                 : "=r"(r0), "=r"(r1), "=r"(r2), "=r"(r3) : "r"(addr));
}
__device__ __forceinline__ void mma16816(float* c, const unsigned* a,
                                         unsigned b0, unsigned b1) {
    asm volatile(
        "mma.sync.aligned.m16n8k16.row.col.f32.bf16.bf16.f32 "
        "{%0,%1,%2,%3}, {%4,%5,%6,%7}, {%8,%9}, {%0,%1,%2,%3};"
        : "+f"(c[0]), "+f"(c[1]), "+f"(c[2]), "+f"(c[3])
        : "r"(a[0]), "r"(a[1]), "r"(a[2]), "r"(a[3]), "r"(b0), "r"(b1));
}
#define CP16(dst, src) asm volatile("cp.async.cg.shared.global [%0], [%1], 16;" :: "r"(dst), "l"(src))

// ---------------- K1: causal depthwise conv (W=4) + SiLU + bf16 splits -----
__global__ void conv_silu_kernel(const float* __restrict__ x,
                                 const float* __restrict__ cw,
                                 const float* __restrict__ cb) {
    int d  = blockIdx.x * 256 + threadIdx.x;
    int t0 = blockIdx.y * 8;
    int b  = blockIdx.z;
    float4 w = *reinterpret_cast<const float4*>(cw + d * 4);
    float bias = cb[d];
    size_t base = ((size_t)b * Ll) * Dd + d;
    const float* xb = x + base;
    float* sp = g_shift + base;
    float xm3 = (t0 - 3 >= 0) ? xb[(size_t)(t0 - 3) * Dd] : 0.f;
    float xm2 = (t0 - 2 >= 0) ? xb[(size_t)(t0 - 2) * Dd] : 0.f;
    float xm1 = (t0 - 1 >= 0) ? xb[(size_t)(t0 - 1) * Dd] : 0.f;
#pragma unroll
    for (int i = 0; i < 8; i++) {
        int t = t0 + i;
        size_t o = base + (size_t)t * Dd;
        float xt = xb[(size_t)t * Dd];
        float y = xm3 * w.x + xm2 * w.y + xm1 * w.z + xt * w.w + bias;
        float s = y * sigmoidf_(y);
        sp[(size_t)t * Dd] = s;
        split_bf16(s,  &g_sh_hi[o], &g_sh_lo[o]);
        split_bf16(xt, &g_x_hi[o],  &g_x_lo[o]);
        xm3 = xm2; xm2 = xm1; xm1 = xt;
    }
}

// ---------------- K1b: weight splits ----------------------------------------
__global__ void wsplit_kernel(const float* __restrict__ w_in,
                              const float* __restrict__ w_mg,
                              const float* __restrict__ w_ch) {
    int i = blockIdx.x * 256 + threadIdx.x;   // i < 256*2048
    float v = (i < 128 * Dd) ? w_in[i] : w_mg[i - 128 * Dd];
    split_bf16(v, &g_b01_hi[i], &g_b01_lo[i]);
    if (i < 128 * Dd) split_bf16(w_ch[i], &g_b2_hi[i], &g_b2_lo[i]);
}

// ---------------- K2: tensor-core projections via mma.sync (3xBF16) --------
// grid (64, 3), block 256 (8 warps).  y=0: rk cols 0..127 (A=shift, B=b01 rows 0..127)
//                                     y=1: mg cols 128..255 (A=shift, B=b01 rows 128..255)
//                                     y=2: h  cols 256..383 (A=x,     B=b2)
// CTA tile 128 tok x 128 n, K staged 32 at a time, 3-buffer cp.async ring.
// Warp tile 32 tok x 64 n (warps 4(M) x 2(N)).
#define SA 40                          // padded row stride (bf16 elems)
#define STG_E (4*128*SA)               // elems per stage (Ah,Al,Bh,Bl)
#define OFF_AL (128*SA)
#define OFF_BH (2*128*SA)
#define OFF_BL (3*128*SA)

__global__ __launch_bounds__(256, 1) void mma_proj_kernel() {
    extern __shared__ __align__(128) __nv_bfloat16 sm[];
    const int tid = threadIdx.x;
    const int lane = tid & 31, wid = tid >> 5;
    const int wm = wid & 3, wn = wid >> 2;
    const int y = blockIdx.y;
    const int tok0 = blockIdx.x * 128;

    const __nv_bfloat16* Ah = (y == 2) ? g_x_hi : g_sh_hi;
    const __nv_bfloat16* Al = (y == 2) ? g_x_lo : g_sh_lo;
    const __nv_bfloat16* Bh = (y == 2) ? g_b2_hi : g_b01_hi + (size_t)y * 128 * Dd;
    const __nv_bfloat16* Bl = (y == 2) ? g_b2_lo : g_b01_lo + (size_t)y * 128 * Dd;
    const int zoff = (y == 2) ? 256 : y * 128;

    const unsigned sbase = (unsigned)__cvta_generic_to_shared(sm);

    // loader: stage s -> ring slot s%3. 2048 16B-chunks / 256 threads = 8 each.
    auto load_stage = [&](int s) {
        const int kb = s * 32;
        const unsigned st = sbase + (s % 3) * (STG_E * 2);
#pragma unroll
        for (int j = 0; j < 8; j++) {
            int i = tid + j * 256;
            int arr = i >> 9;            // 0..3
            int rem = i & 511;
            int row = rem >> 2, c = rem & 3;
            unsigned dst = st + arr * (128 * SA * 2) + (row * SA + c * 8) * 2;
            const __nv_bfloat16* src =
                (arr == 0 ? Ah + (size_t)(tok0 + row) * Dd :
                 arr == 1 ? Al + (size_t)(tok0 + row) * Dd :
                 arr == 2 ? Bh + (size_t)row * Dd :
                            Bl + (size_t)row * Dd) + kb + c * 8;
            CP16(dst, src);
        }
    };

    load_stage(0);
    asm volatile("cp.async.commit_group;" ::: "memory");
    load_stage(1);
    asm volatile("cp.async.commit_group;" ::: "memory");

    float acc[2][8][4];
#pragma unroll
    for (int mt = 0; mt < 2; mt++)
#pragma unroll
        for (int nt = 0; nt < 8; nt++)
#pragma unroll
            for (int q = 0; q < 4; q++) acc[mt][nt][q] = 0.f;

    const int lr = lane & 15, lc = lane >> 4;   // ldmatrix lane addressing

    for (int s = 0; s < 64; s++) {
        asm volatile("cp.async.wait_group 1;" ::: "memory");
        __syncthreads();
        if (s + 2 < 64) load_stage(s + 2);
        asm volatile("cp.async.commit_group;" ::: "memory");

        const unsigned st = sbase + (s % 3) * (STG_E * 2);
#pragma unroll
        for (int kk = 0; kk < 2; kk++) {
            const unsigned kofs = (kk * 16 + lc * 8) * 2;
            unsigned ah[2][4], al[2][4];
#pragma unroll
            for (int mt = 0; mt < 2; mt++) {
                int row = wm * 32 + mt * 16 + lr;
                ldsm4(ah[mt][0], ah[mt][1], ah[mt][2], ah[mt][3],
                      st + row * (SA * 2) + kofs);
                ldsm4(al[mt][0], al[mt][1], al[mt][2], al[mt][3],
                      st + OFF_AL * 2 + row * (SA * 2) + kofs);
            }
#pragma unroll
            for (int nt16 = 0; nt16 < 4; nt16++) {
                int nrow = wn * 64 + nt16 * 16 + lr;
                unsigned bh[4], bl[4];
                ldsm4(bh[0], bh[1], bh[2], bh[3],
                      st + OFF_BH * 2 + nrow * (SA * 2) + kofs);
                ldsm4(bl[0], bl[1], bl[2], bl[3],
                      st + OFF_BL * 2 + nrow * (SA * 2) + kofs);
#pragma unroll
                for (int half = 0; half < 2; half++) {
                    unsigned bh0 = half ? bh[1] : bh[0], bh1 = half ? bh[3] : bh[2];
                    unsigned bl0 = half ? bl[1] : bl[0], bl1 = half ? bl[3] : bl[2];
                    int nt = nt16 * 2 + half;
#pragma unroll
                    for (int mt = 0; mt < 2; mt++) {
                        mma16816(acc[mt][nt], ah[mt], bh0, bh1);
                        mma16816(acc[mt][nt], ah[mt], bl0, bl1);
                        mma16816(acc[mt][nt], al[mt], bh0, bh1);
                    }
                }
            }
        }
    }

    // epilogue: c0,c1 -> (row g, col 2*tig), c2,c3 -> (row g+8)
    const int g = lane >> 2, tig = lane & 3;
#pragma unroll
    for (int mt = 0; mt < 2; mt++) {
        int token = tok0 + wm * 32 + mt * 16 + g;
#pragma unroll
        for (int nt = 0; nt < 8; nt++) {
            int col = zoff + wn * 64 + nt * 8 + tig * 2;
            *reinterpret_cast<float2*>(g_zp + (size_t)token * 384 + col) =
                make_float2(acc[mt][nt][0], acc[mt][nt][1]);
            *reinterpret_cast<float2*>(g_zp + (size_t)(token + 8) * 384 + col) =
                make_float2(acc[mt][nt][2], acc[mt][nt][3]);
        }
    }
}

// ---------------- K3: u = sigmoid(h @ ch_gate_w1^T + b1) * x ----------------
__global__ __launch_bounds__(256) void ugemm_kernel(
    const float* __restrict__ x,
    const float* __restrict__ w1,   // (D, R) row-major
    const float* __restrict__ b1) {
    const int tok0 = blockIdx.x * 64;
    const int d0   = blockIdx.y * 128;

    __shared__ float As[2][16 * 68];
    __shared__ float Bs[2][16 * 132];

    const int tid = threadIdx.x;
    const int tg = tid >> 4, ng = tid & 15;
    const int a_k   = (tid & 3) * 4;
    const int b_n   = tid >> 1;
    const int b_k   = (tid & 1) * 8;

    float2 acc[4][4];
#pragma unroll
    for (int i = 0; i < 4; i++)
#pragma unroll
        for (int j = 0; j < 4; j++) acc[i][j] = make_float2(0.f, 0.f);

    const float* Aptr = g_zp + (size_t)(tok0 + (tid >> 2)) * 384 + 256 + a_k;
    const float* Bptr = w1 + (size_t)(d0 + b_n) * Rr + b_k;

    float4 av  = *reinterpret_cast<const float4*>(Aptr);
    float4 bv0 = *reinterpret_cast<const float4*>(Bptr);
    float4 bv1 = *reinterpret_cast<const float4*>(Bptr + 4);

    const int NT = Rr / 16;  // 8
    for (int kt = 0; kt < NT; ++kt) {
        const int p = kt & 1;
        {
            float* as = As[p] + a_k * 68 + (tid >> 2);
            as[0] = av.x; as[68] = av.y; as[2 * 68] = av.z; as[3 * 68] = av.w;
            float* bs = Bs[p] + b_k * 132 + b_n;
            bs[0] = bv0.x; bs[132] = bv0.y; bs[2 * 132] = bv0.z; bs[3 * 132] = bv0.w;
            bs[4 * 132] = bv1.x; bs[5 * 132] = bv1.y; bs[6 * 132] = bv1.z; bs[7 * 132] = bv1.w;
        }
        __syncthreads();
        if (kt + 1 < NT) {
            av  = *reinterpret_cast<const float4*>(Aptr + (kt + 1) * 16);
            bv0 = *reinterpret_cast<const float4*>(Bptr + (kt + 1) * 16);
            bv1 = *reinterpret_cast<const float4*>(Bptr + (kt + 1) * 16 + 4);
        }
#pragma unroll
        for (int k = 0; k < 16; k++) {
            float4 a4  = *reinterpret_cast<const float4*>(As[p] + k * 68 + tg * 4);
            float4 b40 = *reinterpret_cast<const float4*>(Bs[p] + k * 132 + ng * 8);
            float4 b41 = *reinterpret_cast<const float4*>(Bs[p] + k * 132 + ng * 8 + 4);
            float aval[4] = {a4.x, a4.y, a4.z, a4.w};
            float2 bp[4] = {make_float2(b40.x, b40.y), make_float2(b40.z, b40.w),
                            make_float2(b41.x, b41.y), make_float2(b41.z, b41.w)};
#pragma unroll
            for (int i = 0; i < 4; i++) {
                float2 aa = make_float2(aval[i], aval[i]);
#pragma unroll
                for (int j = 0; j < 4; j++) acc[i][j] = ffma2(aa, bp[j], acc[i][j]);
            }
        }
    }
#pragma unroll
    for (int i = 0; i < 4; i++) {
        int token = tok0 + tg * 4 + i;
#pragma unroll
        for (int j = 0; j < 4; j++) {
            int dc = d0 + ng * 8 + 2 * j;
            float z0 = acc[i][j].x + b1[dc];
            float z1 = acc[i][j].y + b1[dc + 1];
            float u0 = sigmoidf_(z0) * x[(size_t)token * Dd + dc];
            float u1 = sigmoidf_(z1) * x[(size_t)token * Dd + dc + 1];
            float2 uv = make_float2(u0, u1);
            *reinterpret_cast<float2*>(g_u + (size_t)token * Dd + dc) = uv;
        }
    }
}

// ---------------- K4: gate math per token -----------------------------------
__global__ void gates_kernel(const float* __restrict__ mb) {
    int warp = threadIdx.x >> 5;
    int lane = threadIdx.x & 31;
    int token = blockIdx.x * 4 + warp;
    const float* zp = g_zp + (size_t)token * 384;

    float r_a = zp[lane],        r_b = zp[32 + lane];
    float k_a = zp[64 + lane],   k_b = zp[96 + lane];
    float m1a = zp[128 + lane] + mb[lane];
    float m1b = zp[160 + lane] + mb[32 + lane];
    float m2a = zp[192 + lane] + mb[64 + lane];
    float m2b = zp[224 + lane] + mb[96 + lane];

    float sela = softplusf_(m1a), selb = softplusf_(m1b);
    float taua = sigmoidf_(m2a),  taub = sigmoidf_(m2b);
    float ita = expf(taua * logf(sela));
    float itb = expf(taub * logf(selb));
    float ega = expf(-sela * taua);
    float egb = expf(-selb * taub);

    float ss = k_a * k_a + k_b * k_b;
#pragma unroll
    for (int o = 16; o > 0; o >>= 1) ss += __shfl_xor_sync(0xffffffffu, ss, o);
    float inv = 1.f / fmaxf(sqrtf(ss), 1e-12f);

    float* go = g_gates + (size_t)token * 192;
    go[lane]       = r_a;             go[32 + lane]  = r_b;
    go[64 + lane]  = k_a * inv * ita; go[96 + lane]  = k_b * inv * itb;
    go[128 + lane] = ega;             go[160 + lane] = egb;
}

// ---------------- K5: sequential scan (m-split, deep prefetch) --------------
__global__ __launch_bounds__(64) void scan_kernel(const float* __restrict__ rw,
                                                  float* __restrict__ out) {
    const int tid = threadIdx.x;
    const int w = tid >> 5, lane = tid & 31;
    const int d = blockIdx.x * 64 + tid;
    const int b = blockIdx.y;
    const int h = blockIdx.z;            // m half: states m = h*32 .. h*32+31

    __shared__ __align__(16) float sg[2][PF][96];   // per-warp gate stages: r(32) k(32) e(32)

    const float* gb = g_gates + (size_t)b * Ll * 192;
    const int ch  = lane >> 3;           // 0..3 (0..2 active)
    const int off = (lane & 7) * 4;
    const int gsrc_off = (ch == 0 ? h * 32 : ch == 1 ? 64 + h * 32 : 128 + h * 32) + off;
    const bool active = lane < 24;
    const unsigned sbase =
        (unsigned)__cvta_generic_to_shared(&sg[w][0][ch * 32 + off]);

#pragma unroll
    for (int s = 0; s < PF - 1; s++) {
        if (active) {
            const float* src = gb + (size_t)s * 192 + gsrc_off;
            unsigned dst = sbase + s * 96 * 4;
            asm volatile("cp.async.ca.shared.global [%0], [%1], 16;"
                         :: "r"(dst), "l"(src));
        }
        asm volatile("cp.async.commit_group;" ::: "memory");
    }

    float2 S[16];
#pragma unroll
    for (int p = 0; p < 16; p++) S[p] = make_float2(0.f, 0.f);

    const float* ub = g_u + ((size_t)b * Ll) * Dd + d;
    const float* sb = g_shift + ((size_t)b * Ll) * Dd + d;
    float* ob = out + ((size_t)b * Ll) * Dd + d;
    const float rwd = (h == 0) ? rw[d] : 0.f;

    float upf[8], spf[8];
#pragma unroll
    for (int i = 0; i < 8; i++) {
        upf[i] = __ldcg(ub + (size_t)i * Dd);
        spf[i] = (h == 0) ? __ldcg(sb + (size_t)i * Dd) : 0.f;
    }

    for (int tb = 0; tb < Ll; tb += 8) {
#pragma unroll
        for (int j = 0; j < 8; j++) {
            const int t = tb + j;
            asm volatile("cp.async.wait_group 2;" ::: "memory");
            __syncwarp();
            const float* g0 = &sg[w][t & (PF - 1)][0];

            float2 uu = make_float2(upf[j], upf[j]);
            float2 a0 = make_float2(0.f, 0.f), a1 = a0;
#pragma unroll
            for (int q = 0; q < 8; q++) {
                float4 r4 = *reinterpret_cast<const float4*>(g0 + q * 4);
                float4 k4 = *reinterpret_cast<const float4*>(g0 + 32 + q * 4);
                float4 e4 = *reinterpret_cast<const float4*>(g0 + 64 + q * 4);
                S[2 * q]     = ffma2(make_float2(e4.x, e4.y), S[2 * q],
                                     fmul2(make_float2(k4.x, k4.y), uu));
                S[2 * q + 1] = ffma2(make_float2(e4.z, e4.w), S[2 * q + 1],
                                     fmul2(make_float2(k4.z, k4.w), uu));
                a0 = ffma2(make_float2(r4.x, r4.y), S[2 * q],     a0);
                a1 = ffma2(make_float2(r4.z, r4.w), S[2 * q + 1], a1);
            }
            float o = OSCALE * ((a0.x + a0.y) + (a1.x + a1.y)) + spf[j] * rwd;
            atomicAdd(ob + (size_t)t * Dd, o);

            const int tn = t + PF - 1;
            if (tn < Ll && active) {
                const float* src = gb + (size_t)tn * 192 + gsrc_off;
                unsigned dst = sbase + (tn & (PF - 1)) * 96 * 4;
                asm volatile("cp.async.ca.shared.global [%0], [%1], 16;"
                             :: "r"(dst), "l"(src));
            }
            asm volatile("cp.async.commit_group;" ::: "memory");

            if (t + 8 < Ll) {
                upf[j] = __ldcg(ub + (size_t)(t + 8) * Dd);
                spf[j] = (h == 0) ? __ldcg(sb + (size_t)(t + 8) * Dd) : 0.f;
            }
        }
    }
}

// ---------------- launch -----------------------------------------------------
extern "C" void kernel_launch(void* const* d_in, const int* in_sizes, int n_in,
                              void* d_out, int out_size) {
    const float* x        = (const float*)d_in[0];  // (B,L,D)
    const float* conv_w   = (const float*)d_in[1];  // (D,4)
    const float* conv_b   = (const float*)d_in[2];  // (D,)
    const float* in_proj  = (const float*)d_in[3];  // (128,D)
    const float* ch_w0    = (const float*)d_in[4];  // (128,D)
    const float* ch_w1    = (const float*)d_in[5];  // (D,128)
    const float* ch_b1    = (const float*)d_in[6];  // (D,)
    const float* mem_w    = (const float*)d_in[7];  // (128,D)
    const float* mem_b    = (const float*)d_in[8];  // (128,)
    const float* res_w    = (const float*)d_in[9];  // (D,)
    float* out = (float*)d_out;

    static bool attr_set = false;
    if (!attr_set) {
        cudaFuncSetAttribute(mma_proj_kernel,
                             cudaFuncAttributeMaxDynamicSharedMemorySize,
                             3 * STG_E * 2);
        attr_set = true;
    }

    conv_silu_kernel<<<dim3(Dd / 256, Ll / 8, Bb), 256>>>(x, conv_w, conv_b);
    wsplit_kernel<<<dim3(256 * Dd / 256), 256>>>(in_proj, mem_w, ch_w0);
    mma_proj_kernel<<<dim3(BL / 128, 3), 256, 3 * STG_E * 2>>>();
    ugemm_kernel<<<dim3(BL / 64, Dd / 128), 256>>>(x, ch_w1, ch_b1);
    gates_kernel<<<dim3(BL / 4), 128>>>(mem_b);
    cudaMemsetAsync(out, 0, (size_t)out_size * sizeof(float), 0);
    scan_kernel<<<dim3(Dd / 64, Bb, 2), 64>>>(res_w, out);
}

// round 7
// speedup vs baseline: 2.7358x; 1.1417x over previous
#include <cuda_runtime.h>
#include <cuda_bf16.h>
#include <math.h>

// Problem constants
#define Bb 4
#define Ll 2048
#define Dd 2048
#define Mm 64
#define Rr 128
#define BL (Bb*Ll)
#define OSCALE 0.125f   // 1/sqrt(64)
#define PF 4            // scan gates prefetch stages (power of 2)
#define NC 8            // scan time chunks
#define CL 256          // chunk length

// ---------------- scratch (device globals; no allocation allowed) ----------
__device__ float g_shift[BL*Dd];     // silu(conv(x))  (residual, scan input)
__device__ float g_u[BL*Dd];         // ch * x
__device__ float g_zp[BL*384];       // [token][0..127]=rk, [128..255]=mg(pre-bias)
__device__ float g_gates[BL*192];    // [token][0..63]=r, [64..127]=k_hat, [128..191]=exp(g)

// bf16 splits for tensor-core 3xBF16 GEMMs
__device__ __nv_bfloat16 g_sh_hi[BL*Dd], g_sh_lo[BL*Dd];
__device__ __nv_bfloat16 g_x_hi[BL*Dd],  g_x_lo[BL*Dd];
__device__ __nv_bfloat16 g_b01_hi[256*Dd], g_b01_lo[256*Dd];  // [in_proj;mem_gate]
__device__ __nv_bfloat16 g_b2_hi[128*Dd],  g_b2_lo[128*Dd];   // ch_gate_w0
__device__ __nv_bfloat16 g_w1_hi[Dd*Rr],   g_w1_lo[Dd*Rr];    // ch_gate_w1
__device__ __nv_bfloat16 g_h_hi[BL*Rr],    g_h_lo[BL*Rr];     // h = x @ w0^T

// chunked-scan scratch
__device__ float g_Send[Bb*NC*Mm*Dd];   // local end-state per chunk
__device__ float g_Sin[Bb*NC*Mm*Dd];    // incoming state per chunk (c>=1)
__device__ float g_rtil[BL*Mm];         // r_t * cumdecay_within_chunk
__device__ float g_Pc[Bb*NC*Mm];        // full-chunk decay products

// ---------------- f32x2 packed math helpers --------------------------------
__device__ __forceinline__ float2 ffma2(float2 a, float2 b, float2 c) {
    unsigned long long au = *reinterpret_cast<unsigned long long*>(&a);
    unsigned long long bu = *reinterpret_cast<unsigned long long*>(&b);
    unsigned long long cu = *reinterpret_cast<unsigned long long*>(&c);
    unsigned long long du;
    asm("fma.rn.f32x2 %0, %1, %2, %3;" : "=l"(du) : "l"(au), "l"(bu), "l"(cu));
    return *reinterpret_cast<float2*>(&du);
}
__device__ __forceinline__ float2 fmul2(float2 a, float2 b) {
    unsigned long long au = *reinterpret_cast<unsigned long long*>(&a);
    unsigned long long bu = *reinterpret_cast<unsigned long long*>(&b);
    unsigned long long du;
    asm("mul.rn.f32x2 %0, %1, %2;" : "=l"(du) : "l"(au), "l"(bu));
    return *reinterpret_cast<float2*>(&du);
}
__device__ __forceinline__ float sigmoidf_(float x) { return 1.f / (1.f + expf(-x)); }
__device__ __forceinline__ float softplusf_(float x) {
    return fmaxf(x, 0.f) + log1pf(expf(-fabsf(x)));
}
__device__ __forceinline__ void split_bf16(float v, __nv_bfloat16* hi, __nv_bfloat16* lo) {
    __nv_bfloat16 h = __float2bfloat16_rn(v);
    *hi = h;
    *lo = __float2bfloat16_rn(v - __bfloat162float(h));
}

// ---------------- warp-MMA helpers ------------------------------------------
__device__ __forceinline__ void ldsm4(unsigned& r0, unsigned& r1, unsigned& r2,
                                      unsigned& r3, unsigned addr) {
    asm volatile("ldmatrix.sync.aligned.m8n8.x4.shared.b16 {%0,%1,%2,%3}, [%4];"
                 : "=r"(r0), "=r"(r1), "=r"(r2), "=r"(r3) : "r"(addr));
}
__device__ __forceinline__ void mma16816(float* c, const unsigned* a,
                                         unsigned b0, unsigned b1) {
    asm volatile(
        "mma.sync.aligned.m16n8k16.row.col.f32.bf16.bf16.f32 "
        "{%0,%1,%2,%3}, {%4,%5,%6,%7}, {%8,%9}, {%0,%1,%2,%3};"
        : "+f"(c[0]), "+f"(c[1]), "+f"(c[2]), "+f"(c[3])
        : "r"(a[0]), "r"(a[1]), "r"(a[2]), "r"(a[3]), "r"(b0), "r"(b1));
}
#define CP16(dst, src) asm volatile("cp.async.cg.shared.global [%0], [%1], 16;" :: "r"(dst), "l"(src))

// ---------------- K1: causal depthwise conv (W=4) + SiLU + bf16 splits -----
__global__ void conv_silu_kernel(const float* __restrict__ x,
                                 const float* __restrict__ cw,
                                 const float* __restrict__ cb) {
    int d  = blockIdx.x * 256 + threadIdx.x;
    int t0 = blockIdx.y * 8;
    int b  = blockIdx.z;
    float4 w = *reinterpret_cast<const float4*>(cw + d * 4);
    float bias = cb[d];
    size_t base = ((size_t)b * Ll) * Dd + d;
    const float* xb = x + base;
    float* sp = g_shift + base;
    float xm3 = (t0 - 3 >= 0) ? xb[(size_t)(t0 - 3) * Dd] : 0.f;
    float xm2 = (t0 - 2 >= 0) ? xb[(size_t)(t0 - 2) * Dd] : 0.f;
    float xm1 = (t0 - 1 >= 0) ? xb[(size_t)(t0 - 1) * Dd] : 0.f;
#pragma unroll
    for (int i = 0; i < 8; i++) {
        int t = t0 + i;
        size_t o = base + (size_t)t * Dd;
        float xt = xb[(size_t)t * Dd];
        float y = xm3 * w.x + xm2 * w.y + xm1 * w.z + xt * w.w + bias;
        float s = y * sigmoidf_(y);
        sp[(size_t)t * Dd] = s;
        split_bf16(s,  &g_sh_hi[o], &g_sh_lo[o]);
        split_bf16(xt, &g_x_hi[o],  &g_x_lo[o]);
        xm3 = xm2; xm2 = xm1; xm1 = xt;
    }
}

// ---------------- K1b: weight splits ----------------------------------------
// w1 has exactly 128*Dd elements (D rows x R cols) — single-branch split only.
__global__ void wsplit_kernel(const float* __restrict__ w_in,
                              const float* __restrict__ w_mg,
                              const float* __restrict__ w_ch,
                              const float* __restrict__ w1) {
    int i = blockIdx.x * 256 + threadIdx.x;   // i < 256*2048
    float v = (i < 128 * Dd) ? w_in[i] : w_mg[i - 128 * Dd];
    split_bf16(v, &g_b01_hi[i], &g_b01_lo[i]);
    if (i < 128 * Dd) {
        split_bf16(w_ch[i], &g_b2_hi[i], &g_b2_lo[i]);
        split_bf16(w1[i],   &g_w1_hi[i], &g_w1_lo[i]);
    }
}

// ---------------- K2: tensor-core projections via mma.sync (3xBF16) --------
#define SA 40                          // padded row stride (bf16 elems)
#define STG_E (4*128*SA)               // elems per stage (Ah,Al,Bh,Bl)
#define OFF_AL (128*SA)
#define OFF_BH (2*128*SA)
#define OFF_BL (3*128*SA)

__global__ __launch_bounds__(256, 1) void mma_proj_kernel() {
    extern __shared__ __align__(128) __nv_bfloat16 sm[];
    const int tid = threadIdx.x;
    const int lane = tid & 31, wid = tid >> 5;
    const int wm = wid & 3, wn = wid >> 2;
    const int y = blockIdx.y;
    const int tok0 = blockIdx.x * 128;

    const __nv_bfloat16* Ah = (y == 2) ? g_x_hi : g_sh_hi;
    const __nv_bfloat16* Al = (y == 2) ? g_x_lo : g_sh_lo;
    const __nv_bfloat16* Bh = (y == 2) ? g_b2_hi : g_b01_hi + (size_t)y * 128 * Dd;
    const __nv_bfloat16* Bl = (y == 2) ? g_b2_lo : g_b01_lo + (size_t)y * 128 * Dd;

    const unsigned sbase = (unsigned)__cvta_generic_to_shared(sm);

    auto load_stage = [&](int s) {
        const int kb = s * 32;
        const unsigned st = sbase + (s % 3) * (STG_E * 2);
#pragma unroll
        for (int j = 0; j < 8; j++) {
            int i = tid + j * 256;
            int arr = i >> 9;
            int rem = i & 511;
            int row = rem >> 2, c = rem & 3;
            unsigned dst = st + arr * (128 * SA * 2) + (row * SA + c * 8) * 2;
            const __nv_bfloat16* src =
                (arr == 0 ? Ah + (size_t)(tok0 + row) * Dd :
                 arr == 1 ? Al + (size_t)(tok0 + row) * Dd :
                 arr == 2 ? Bh + (size_t)row * Dd :
                            Bl + (size_t)row * Dd) + kb + c * 8;
            CP16(dst, src);
        }
    };

    load_stage(0);
    asm volatile("cp.async.commit_group;" ::: "memory");
    load_stage(1);
    asm volatile("cp.async.commit_group;" ::: "memory");

    float acc[2][8][4];
#pragma unroll
    for (int mt = 0; mt < 2; mt++)
#pragma unroll
        for (int nt = 0; nt < 8; nt++)
#pragma unroll
            for (int q = 0; q < 4; q++) acc[mt][nt][q] = 0.f;

    const int lr = lane & 15, lc = lane >> 4;

    for (int s = 0; s < 64; s++) {
        asm volatile("cp.async.wait_group 1;" ::: "memory");
        __syncthreads();
        if (s + 2 < 64) load_stage(s + 2);
        asm volatile("cp.async.commit_group;" ::: "memory");

        const unsigned st = sbase + (s % 3) * (STG_E * 2);
#pragma unroll
        for (int kk = 0; kk < 2; kk++) {
            const unsigned kofs = (kk * 16 + lc * 8) * 2;
            unsigned ah[2][4], al[2][4];
#pragma unroll
            for (int mt = 0; mt < 2; mt++) {
                int row = wm * 32 + mt * 16 + lr;
                ldsm4(ah[mt][0], ah[mt][1], ah[mt][2], ah[mt][3],
                      st + row * (SA * 2) + kofs);
                ldsm4(al[mt][0], al[mt][1], al[mt][2], al[mt][3],
                      st + OFF_AL * 2 + row * (SA * 2) + kofs);
            }
#pragma unroll
            for (int nt16 = 0; nt16 < 4; nt16++) {
                int nrow = wn * 64 + nt16 * 16 + lr;
                unsigned bh[4], bl[4];
                ldsm4(bh[0], bh[1], bh[2], bh[3],
                      st + OFF_BH * 2 + nrow * (SA * 2) + kofs);
                ldsm4(bl[0], bl[1], bl[2], bl[3],
                      st + OFF_BL * 2 + nrow * (SA * 2) + kofs);
#pragma unroll
                for (int half = 0; half < 2; half++) {
                    unsigned bh0 = half ? bh[1] : bh[0], bh1 = half ? bh[3] : bh[2];
                    unsigned bl0 = half ? bl[1] : bl[0], bl1 = half ? bl[3] : bl[2];
                    int nt = nt16 * 2 + half;
#pragma unroll
                    for (int mt = 0; mt < 2; mt++) {
                        mma16816(acc[mt][nt], ah[mt], bh0, bh1);
                        mma16816(acc[mt][nt], ah[mt], bl0, bl1);
                        mma16816(acc[mt][nt], al[mt], bh0, bh1);
                    }
                }
            }
        }
    }

    const int g = lane >> 2, tig = lane & 3;
    if (y < 2) {
        const int zoff = y * 128;
#pragma unroll
        for (int mt = 0; mt < 2; mt++) {
            int token = tok0 + wm * 32 + mt * 16 + g;
#pragma unroll
            for (int nt = 0; nt < 8; nt++) {
                int col = zoff + wn * 64 + nt * 8 + tig * 2;
                *reinterpret_cast<float2*>(g_zp + (size_t)token * 384 + col) =
                    make_float2(acc[mt][nt][0], acc[mt][nt][1]);
                *reinterpret_cast<float2*>(g_zp + (size_t)(token + 8) * 384 + col) =
                    make_float2(acc[mt][nt][2], acc[mt][nt][3]);
            }
        }
    } else {
        // h output: write bf16 splits for the downstream tensor-core ugemm
#pragma unroll
        for (int mt = 0; mt < 2; mt++) {
            int token = tok0 + wm * 32 + mt * 16 + g;
#pragma unroll
            for (int nt = 0; nt < 8; nt++) {
                int col = wn * 64 + nt * 8 + tig * 2;
                size_t o0 = (size_t)token * Rr + col;
                size_t o1 = (size_t)(token + 8) * Rr + col;
                split_bf16(acc[mt][nt][0], &g_h_hi[o0],     &g_h_lo[o0]);
                split_bf16(acc[mt][nt][1], &g_h_hi[o0 + 1], &g_h_lo[o0 + 1]);
                split_bf16(acc[mt][nt][2], &g_h_hi[o1],     &g_h_lo[o1]);
                split_bf16(acc[mt][nt][3], &g_h_hi[o1 + 1], &g_h_lo[o1 + 1]);
            }
        }
    }
}

// ---------------- K3: u = sigmoid(h @ w1^T + b1) * x  (tensor core) --------
__global__ __launch_bounds__(256, 1) void ugemm_mma_kernel(
    const float* __restrict__ x, const float* __restrict__ b1) {
    extern __shared__ __align__(128) __nv_bfloat16 sm[];
    const int tid = threadIdx.x;
    const int lane = tid & 31, wid = tid >> 5;
    const int wm = wid & 3, wn = wid >> 2;
    const int tok0 = blockIdx.x * 128;
    const int d0   = blockIdx.y * 128;

    const unsigned sbase = (unsigned)__cvta_generic_to_shared(sm);

    auto load_stage = [&](int s) {
        const int kb = s * 32;
        const unsigned st = sbase + (s % 3) * (STG_E * 2);
#pragma unroll
        for (int j = 0; j < 8; j++) {
            int i = tid + j * 256;
            int arr = i >> 9;
            int rem = i & 511;
            int row = rem >> 2, c = rem & 3;
            unsigned dst = st + arr * (128 * SA * 2) + (row * SA + c * 8) * 2;
            const __nv_bfloat16* src =
                (arr == 0 ? g_h_hi + (size_t)(tok0 + row) * Rr :
                 arr == 1 ? g_h_lo + (size_t)(tok0 + row) * Rr :
                 arr == 2 ? g_w1_hi + (size_t)(d0 + row) * Rr :
                            g_w1_lo + (size_t)(d0 + row) * Rr) + kb + c * 8;
            CP16(dst, src);
        }
    };

    load_stage(0);
    asm volatile("cp.async.commit_group;" ::: "memory");
    load_stage(1);
    asm volatile("cp.async.commit_group;" ::: "memory");

    float acc[2][8][4];
#pragma unroll
    for (int mt = 0; mt < 2; mt++)
#pragma unroll
        for (int nt = 0; nt < 8; nt++)
#pragma unroll
            for (int q = 0; q < 4; q++) acc[mt][nt][q] = 0.f;

    const int lr = lane & 15, lc = lane >> 4;

    for (int s = 0; s < 4; s++) {
        asm volatile("cp.async.wait_group 1;" ::: "memory");
        __syncthreads();
        if (s + 2 < 4) load_stage(s + 2);
        asm volatile("cp.async.commit_group;" ::: "memory");

        const unsigned st = sbase + (s % 3) * (STG_E * 2);
#pragma unroll
        for (int kk = 0; kk < 2; kk++) {
            const unsigned kofs = (kk * 16 + lc * 8) * 2;
            unsigned ah[2][4], al[2][4];
#pragma unroll
            for (int mt = 0; mt < 2; mt++) {
                int row = wm * 32 + mt * 16 + lr;
                ldsm4(ah[mt][0], ah[mt][1], ah[mt][2], ah[mt][3],
                      st + row * (SA * 2) + kofs);
                ldsm4(al[mt][0], al[mt][1], al[mt][2], al[mt][3],
                      st + OFF_AL * 2 + row * (SA * 2) + kofs);
            }
#pragma unroll
            for (int nt16 = 0; nt16 < 4; nt16++) {
                int nrow = wn * 64 + nt16 * 16 + lr;
                unsigned bh[4], bl[4];
                ldsm4(bh[0], bh[1], bh[2], bh[3],
                      st + OFF_BH * 2 + nrow * (SA * 2) + kofs);
                ldsm4(bl[0], bl[1], bl[2], bl[3],
                      st + OFF_BL * 2 + nrow * (SA * 2) + kofs);
#pragma unroll
                for (int half = 0; half < 2; half++) {
                    unsigned bh0 = half ? bh[1] : bh[0], bh1 = half ? bh[3] : bh[2];
                    unsigned bl0 = half ? bl[1] : bl[0], bl1 = half ? bl[3] : bl[2];
                    int nt = nt16 * 2 + half;
#pragma unroll
                    for (int mt = 0; mt < 2; mt++) {
                        mma16816(acc[mt][nt], ah[mt], bh0, bh1);
                        mma16816(acc[mt][nt], ah[mt], bl0, bl1);
                        mma16816(acc[mt][nt], al[mt], bh0, bh1);
                    }
                }
            }
        }
    }

    const int g = lane >> 2, tig = lane & 3;
#pragma unroll
    for (int mt = 0; mt < 2; mt++) {
        int token = tok0 + wm * 32 + mt * 16 + g;
#pragma unroll
        for (int nt = 0; nt < 8; nt++) {
            int col = d0 + wn * 64 + nt * 8 + tig * 2;
            float2 bb = *reinterpret_cast<const float2*>(b1 + col);
#pragma unroll
            for (int rr = 0; rr < 2; rr++) {
                int tk = token + rr * 8;
                float z0 = acc[mt][nt][rr * 2]     + bb.x;
                float z1 = acc[mt][nt][rr * 2 + 1] + bb.y;
                float2 xv = *reinterpret_cast<const float2*>(x + (size_t)tk * Dd + col);
                float2 uv = make_float2(sigmoidf_(z0) * xv.x, sigmoidf_(z1) * xv.y);
                *reinterpret_cast<float2*>(g_u + (size_t)tk * Dd + col) = uv;
            }
        }
    }
}

// ---------------- K4: gate math per token -----------------------------------
__global__ void gates_kernel(const float* __restrict__ mb) {
    int warp = threadIdx.x >> 5;
    int lane = threadIdx.x & 31;
    int token = blockIdx.x * 4 + warp;
    const float* zp = g_zp + (size_t)token * 384;

    float r_a = zp[lane],        r_b = zp[32 + lane];
    float k_a = zp[64 + lane],   k_b = zp[96 + lane];
    float m1a = zp[128 + lane] + mb[lane];
    float m1b = zp[160 + lane] + mb[32 + lane];
    float m2a = zp[192 + lane] + mb[64 + lane];
    float m2b = zp[224 + lane] + mb[96 + lane];

    float sela = softplusf_(m1a), selb = softplusf_(m1b);
    float taua = sigmoidf_(m2a),  taub = sigmoidf_(m2b);
    float ita = expf(taua * logf(sela));
    float itb = expf(taub * logf(selb));
    float ega = expf(-sela * taua);
    float egb = expf(-selb * taub);

    float ss = k_a * k_a + k_b * k_b;
#pragma unroll
    for (int o = 16; o > 0; o >>= 1) ss += __shfl_xor_sync(0xffffffffu, ss, o);
    float inv = 1.f / fmaxf(sqrtf(ss), 1e-12f);

    float* go = g_gates + (size_t)token * 192;
    go[lane]       = r_a;             go[32 + lane]  = r_b;
    go[64 + lane]  = k_a * inv * ita; go[96 + lane]  = k_b * inv * itb;
    go[128 + lane] = ega;             go[160 + lane] = egb;
}

// ---------------- K4b: r~ = r * cumdecay (per chunk) + chunk products -------
__global__ __launch_bounds__(128) void rtil_kernel() {
    int w = blockIdx.x * 4 + (threadIdx.x >> 5);
    int lane = threadIdx.x & 31;
    int c = w & 7;
    int bh = w >> 3;
    int b = bh >> 1, h = bh & 1;
    int m = h * 32 + lane;

    const float* gbase = g_gates + ((size_t)(b * Ll + c * CL)) * 192;
    float* rout = g_rtil + ((size_t)(b * Ll + c * CL)) * Mm + m;

    float P = 1.f;
    float ef[8], rf[8];
#pragma unroll
    for (int i = 0; i < 8; i++) {
        ef[i] = gbase[(size_t)i * 192 + 128 + m];
        rf[i] = gbase[(size_t)i * 192 + m];
    }
    for (int t = 0; t < CL; t++) {
        int j = t & 7;
        P *= ef[j];
        rout[(size_t)t * Mm] = rf[j] * P;
        if (t + 8 < CL) {
            ef[j] = gbase[(size_t)(t + 8) * 192 + 128 + m];
            rf[j] = gbase[(size_t)(t + 8) * 192 + m];
        }
    }
    g_Pc[(b * NC + c) * Mm + m] = P;
}

// ---------------- K5a: chunk-local scans ------------------------------------
__global__ __launch_bounds__(64) void scanA_kernel(const float* __restrict__ rw,
                                                   float* __restrict__ out) {
    const int tid = threadIdx.x;
    const int w = tid >> 5, lane = tid & 31;
    const int d = blockIdx.x * 64 + tid;
    const int b = blockIdx.y;
    const int h = blockIdx.z / NC;
    const int c = blockIdx.z % NC;
    const int t0base = c * CL;

    __shared__ __align__(16) float sg[2][PF][96];

    const float* gb = g_gates + (size_t)b * Ll * 192;
    const int ch  = lane >> 3;
    const int off = (lane & 7) * 4;
    const int gsrc_off = (ch == 0 ? h * 32 : ch == 1 ? 64 + h * 32 : 128 + h * 32) + off;
    const bool active = lane < 24;
    const unsigned sbase =
        (unsigned)__cvta_generic_to_shared(&sg[w][0][ch * 32 + off]);

#pragma unroll
    for (int s = 0; s < PF - 1; s++) {
        if (active) {
            const float* src = gb + (size_t)(t0base + s) * 192 + gsrc_off;
            unsigned dst = sbase + ((t0base + s) & (PF - 1)) * 96 * 4;
            asm volatile("cp.async.ca.shared.global [%0], [%1], 16;"
                         :: "r"(dst), "l"(src));
        }
        asm volatile("cp.async.commit_group;" ::: "memory");
    }

    float2 S[16];
#pragma unroll
    for (int p = 0; p < 16; p++) S[p] = make_float2(0.f, 0.f);

    const float* ub = g_u + ((size_t)b * Ll) * Dd + d;
    const float* sb = g_shift + ((size_t)b * Ll) * Dd + d;
    float* ob = out + ((size_t)b * Ll) * Dd + d;
    const float rwd = (h == 0) ? rw[d] : 0.f;

    float upf[8], spf[8];
#pragma unroll
    for (int i = 0; i < 8; i++) {
        upf[i] = __ldcg(ub + (size_t)(t0base + i) * Dd);
        spf[i] = (h == 0) ? __ldcg(sb + (size_t)(t0base + i) * Dd) : 0.f;
    }

    for (int tb = 0; tb < CL; tb += 8) {
#pragma unroll
        for (int j = 0; j < 8; j++) {
            const int t = t0base + tb + j;
            asm volatile("cp.async.wait_group 2;" ::: "memory");
            __syncwarp();
            const float* g0 = &sg[w][t & (PF - 1)][0];

            float2 uu = make_float2(upf[j], upf[j]);
            float2 a0 = make_float2(0.f, 0.f), a1 = a0;
#pragma unroll
            for (int q = 0; q < 8; q++) {
                float4 r4 = *reinterpret_cast<const float4*>(g0 + q * 4);
                float4 k4 = *reinterpret_cast<const float4*>(g0 + 32 + q * 4);
                float4 e4 = *reinterpret_cast<const float4*>(g0 + 64 + q * 4);
                S[2 * q]     = ffma2(make_float2(e4.x, e4.y), S[2 * q],
                                     fmul2(make_float2(k4.x, k4.y), uu));
                S[2 * q + 1] = ffma2(make_float2(e4.z, e4.w), S[2 * q + 1],
                                     fmul2(make_float2(k4.z, k4.w), uu));
                a0 = ffma2(make_float2(r4.x, r4.y), S[2 * q],     a0);
                a1 = ffma2(make_float2(r4.z, r4.w), S[2 * q + 1], a1);
            }
            float o = OSCALE * ((a0.x + a0.y) + (a1.x + a1.y)) + spf[j] * rwd;
            atomicAdd(ob + (size_t)t * Dd, o);

            const int tn = t + PF - 1;
            if (tn < t0base + CL && active) {
                const float* src = gb + (size_t)tn * 192 + gsrc_off;
                unsigned dst = sbase + (tn & (PF - 1)) * 96 * 4;
                asm volatile("cp.async.ca.shared.global [%0], [%1], 16;"
                             :: "r"(dst), "l"(src));
            }
            asm volatile("cp.async.commit_group;" ::: "memory");

            if (tb + j + 8 < CL) {
                upf[j] = __ldcg(ub + (size_t)(t + 8) * Dd);
                spf[j] = (h == 0) ? __ldcg(sb + (size_t)(t + 8) * Dd) : 0.f;
            }
        }
    }

    if (c < NC - 1) {
        float* se = g_Send + ((size_t)(b * NC + c) * Mm + h * 32) * Dd + d;
#pragma unroll
        for (int p = 0; p < 16; p++) {
            se[(size_t)(2 * p) * Dd]     = S[p].x;
            se[(size_t)(2 * p + 1) * Dd] = S[p].y;
        }
    }
}

// ---------------- K5b: cross-chunk state propagation ------------------------
__global__ __launch_bounds__(64) void phaseB_kernel() {
    const int d = blockIdx.x * 64 + threadIdx.x;
    const int b = blockIdx.y;
    const int h = blockIdx.z;

    float Sin[32];
#pragma unroll
    for (int j = 0; j < 32; j++) Sin[j] = 0.f;

    for (int c = 0; c < NC - 1; c++) {
        const float* se = g_Send + ((size_t)(b * NC + c) * Mm + h * 32) * Dd + d;
        const float* pc = g_Pc + (b * NC + c) * Mm + h * 32;
        float* so = g_Sin + ((size_t)(b * NC + c + 1) * Mm + h * 32) * Dd + d;
#pragma unroll
        for (int j = 0; j < 32; j++) {
            Sin[j] = pc[j] * Sin[j] + se[(size_t)j * Dd];
            so[(size_t)j * Dd] = Sin[j];
        }
    }
}

// ---------------- K5c: correction GEMM out += OSCALE * rtil @ Sin -----------
__global__ __launch_bounds__(256) void phaseC_kernel(float* __restrict__ out) {
    const int idx = blockIdx.y;
    const int b = idx / (NC - 1);
    const int c = 1 + idx % (NC - 1);
    const int tt = blockIdx.x & 3, dt = blockIdx.x >> 2;
    const int t0 = c * CL + tt * 64;
    const int d0 = dt * 128;

    const float* A  = g_rtil + ((size_t)b * Ll + t0) * Mm;        // [64 t][64 k]
    const float* Bm = g_Sin + ((size_t)(b * NC + c) * Mm) * Dd + d0; // [64 k][Dd]

    __shared__ float As[2][16 * 68];
    __shared__ float Bs[2][16 * 132];

    const int tid = threadIdx.x;
    const int tg = tid >> 4, ng = tid & 15;
    const int a_t = tid >> 2, a_k = (tid & 3) * 4;
    const int b_kr = tid >> 4, b_nb = (tid & 15) * 8;

    float2 acc[4][4];
#pragma unroll
    for (int i = 0; i < 4; i++)
#pragma unroll
        for (int j = 0; j < 4; j++) acc[i][j] = make_float2(0.f, 0.f);

    const float* Aptr = A + (size_t)a_t * Mm + a_k;
    const float* Bptr = Bm + (size_t)b_kr * Dd + b_nb;

    float4 av  = *reinterpret_cast<const float4*>(Aptr);
    float4 bv0 = *reinterpret_cast<const float4*>(Bptr);
    float4 bv1 = *reinterpret_cast<const float4*>(Bptr + 4);

    const int NT = 4;   // K=64, BK=16
    for (int kt = 0; kt < NT; ++kt) {
        const int p = kt & 1;
        {
            float* as = As[p] + a_k * 68 + a_t;
            as[0] = av.x; as[68] = av.y; as[2 * 68] = av.z; as[3 * 68] = av.w;
            float* bs = Bs[p] + b_kr * 132 + b_nb;
            bs[0] = bv0.x; bs[1] = bv0.y; bs[2] = bv0.z; bs[3] = bv0.w;
            bs[4] = bv1.x; bs[5] = bv1.y; bs[6] = bv1.z; bs[7] = bv1.w;
        }
        __syncthreads();
        if (kt + 1 < NT) {
            av  = *reinterpret_cast<const float4*>(Aptr + (kt + 1) * 16);
            bv0 = *reinterpret_cast<const float4*>(Bptr + (size_t)(kt + 1) * 16 * Dd);
            bv1 = *reinterpret_cast<const float4*>(Bptr + (size_t)(kt + 1) * 16 * Dd + 4);
        }
#pragma unroll
        for (int k = 0; k < 16; k++) {
            float4 a4  = *reinterpret_cast<const float4*>(As[p] + k * 68 + tg * 4);
            float4 b40 = *reinterpret_cast<const float4*>(Bs[p] + k * 132 + ng * 8);
            float4 b41 = *reinterpret_cast<const float4*>(Bs[p] + k * 132 + ng * 8 + 4);
            float aval[4] = {a4.x, a4.y, a4.z, a4.w};
            float2 bp[4] = {make_float2(b40.x, b40.y), make_float2(b40.z, b40.w),
                            make_float2(b41.x, b41.y), make_float2(b41.z, b41.w)};
#pragma unroll
            for (int i = 0; i < 4; i++) {
                float2 aa = make_float2(aval[i], aval[i]);
#pragma unroll
                for (int j = 0; j < 4; j++) acc[i][j] = ffma2(aa, bp[j], acc[i][j]);
            }
        }
    }
#pragma unroll
    for (int i = 0; i < 4; i++) {
        int token = t0 + tg * 4 + i;
        float* op = out + ((size_t)b * Ll + token) * Dd + d0 + ng * 8;
#pragma unroll
        for (int j = 0; j < 4; j++) {
            float2 cur = *reinterpret_cast<float2*>(op + 2 * j);
            cur.x += OSCALE * acc[i][j].x;
            cur.y += OSCALE * acc[i][j].y;
            *reinterpret_cast<float2*>(op + 2 * j) = cur;
        }
    }
}

// ---------------- launch -----------------------------------------------------
extern "C" void kernel_launch(void* const* d_in, const int* in_sizes, int n_in,
                              void* d_out, int out_size) {
    const float* x        = (const float*)d_in[0];  // (B,L,D)
    const float* conv_w   = (const float*)d_in[1];  // (D,4)
    const float* conv_b   = (const float*)d_in[2];  // (D,)
    const float* in_proj  = (const float*)d_in[3];  // (128,D)
    const float* ch_w0    = (const float*)d_in[4];  // (128,D)
    const float* ch_w1    = (const float*)d_in[5];  // (D,128)
    const float* ch_b1    = (const float*)d_in[6];  // (D,)
    const float* mem_w    = (const float*)d_in[7];  // (128,D)
    const float* mem_b    = (const float*)d_in[8];  // (128,)
    const float* res_w    = (const float*)d_in[9];  // (D,)
    float* out = (float*)d_out;

    static bool attr_set = false;
    if (!attr_set) {
        cudaFuncSetAttribute(mma_proj_kernel,
                             cudaFuncAttributeMaxDynamicSharedMemorySize, 3 * STG_E * 2);
        cudaFuncSetAttribute(ugemm_mma_kernel,
                             cudaFuncAttributeMaxDynamicSharedMemorySize, 3 * STG_E * 2);
        attr_set = true;
    }

    conv_silu_kernel<<<dim3(Dd / 256, Ll / 8, Bb), 256>>>(x, conv_w, conv_b);
    wsplit_kernel<<<dim3(256 * Dd / 256), 256>>>(in_proj, mem_w, ch_w0, ch_w1);
    mma_proj_kernel<<<dim3(BL / 128, 3), 256, 3 * STG_E * 2>>>();
    ugemm_mma_kernel<<<dim3(BL / 128, Dd / 128), 256, 3 * STG_E * 2>>>(x, ch_b1);
    gates_kernel<<<dim3(BL / 4), 128>>>(mem_b);
    rtil_kernel<<<dim3(16), 128>>>();
    cudaMemsetAsync(out, 0, (size_t)out_size * sizeof(float), 0);
    scanA_kernel<<<dim3(Dd / 64, Bb, 2 * NC), 64>>>(res_w, out);
    phaseB_kernel<<<dim3(Dd / 64, Bb, 2), 64>>>();
    phaseC_kernel<<<dim3(64, Bb * (NC - 1)), 256>>>(out);
}

// round 8
// speedup vs baseline: 3.0194x; 1.1037x over previous
#include <cuda_runtime.h>
#include <cuda_bf16.h>
#include <math.h>

// Problem constants
#define Bb 4
#define Ll 2048
#define Dd 2048
#define Mm 64
#define Rr 128
#define BL (Bb*Ll)
#define OSCALE 0.125f   // 1/sqrt(64)
#define PF 4            // scan gates prefetch stages (power of 2)
#define NC 8            // scan time chunks
#define CL 256          // chunk length

// ---------------- scratch (device globals; no allocation allowed) ----------
__device__ float g_shift[BL*Dd];     // silu(conv(x))  (residual, scan input)
__device__ float g_u[BL*Dd];         // ch * x
__device__ float g_zp[BL*384];       // [token][0..127]=rk, [128..255]=mg(pre-bias)
__device__ float g_gates[BL*192];    // [token][0..63]=r, [64..127]=k_hat, [128..191]=exp(g)

// bf16 splits for tensor-core 3xBF16 GEMMs
__device__ __nv_bfloat16 g_sh_hi[BL*Dd], g_sh_lo[BL*Dd];
__device__ __nv_bfloat16 g_x_hi[BL*Dd],  g_x_lo[BL*Dd];
__device__ __nv_bfloat16 g_b01_hi[256*Dd], g_b01_lo[256*Dd];  // [in_proj;mem_gate]
__device__ __nv_bfloat16 g_b2_hi[128*Dd],  g_b2_lo[128*Dd];   // ch_gate_w0
__device__ __nv_bfloat16 g_w1_hi[Dd*Rr],   g_w1_lo[Dd*Rr];    // ch_gate_w1
__device__ __nv_bfloat16 g_h_hi[BL*Rr],    g_h_lo[BL*Rr];     // h = x @ w0^T

// chunked-scan scratch
__device__ float g_Send[Bb*NC*Mm*Dd];   // local end-state per chunk
__device__ float g_Sin[Bb*NC*Mm*Dd];    // incoming state per chunk (c>=1)
__device__ float g_rtil[BL*Mm];         // r_t * cumdecay_within_chunk
__device__ float g_Pc[Bb*NC*Mm];        // full-chunk decay products

// ---------------- f32x2 packed math helpers --------------------------------
__device__ __forceinline__ float2 ffma2(float2 a, float2 b, float2 c) {
    unsigned long long au = *reinterpret_cast<unsigned long long*>(&a);
    unsigned long long bu = *reinterpret_cast<unsigned long long*>(&b);
    unsigned long long cu = *reinterpret_cast<unsigned long long*>(&c);
    unsigned long long du;
    asm("fma.rn.f32x2 %0, %1, %2, %3;" : "=l"(du) : "l"(au), "l"(bu), "l"(cu));
    return *reinterpret_cast<float2*>(&du);
}
__device__ __forceinline__ float2 fmul2(float2 a, float2 b) {
    unsigned long long au = *reinterpret_cast<unsigned long long*>(&a);
    unsigned long long bu = *reinterpret_cast<unsigned long long*>(&b);
    unsigned long long du;
    asm("mul.rn.f32x2 %0, %1, %2;" : "=l"(du) : "l"(au), "l"(bu));
    return *reinterpret_cast<float2*>(&du);
}
__device__ __forceinline__ float sigmoidf_(float x) { return 1.f / (1.f + expf(-x)); }
__device__ __forceinline__ float softplusf_(float x) {
    return fmaxf(x, 0.f) + log1pf(expf(-fabsf(x)));
}
__device__ __forceinline__ void split_bf16(float v, __nv_bfloat16* hi, __nv_bfloat16* lo) {
    __nv_bfloat16 h = __float2bfloat16_rn(v);
    *hi = h;
    *lo = __float2bfloat16_rn(v - __bfloat162float(h));
}

// ---------------- warp-MMA helpers ------------------------------------------
__device__ __forceinline__ void ldsm4(unsigned& r0, unsigned& r1, unsigned& r2,
                                      unsigned& r3, unsigned addr) {
    asm volatile("ldmatrix.sync.aligned.m8n8.x4.shared.b16 {%0,%1,%2,%3}, [%4];"
                 : "=r"(r0), "=r"(r1), "=r"(r2), "=r"(r3) : "r"(addr));
}
__device__ __forceinline__ void mma16816(float* c, const unsigned* a,
                                         unsigned b0, unsigned b1) {
    asm volatile(
        "mma.sync.aligned.m16n8k16.row.col.f32.bf16.bf16.f32 "
        "{%0,%1,%2,%3}, {%4,%5,%6,%7}, {%8,%9}, {%0,%1,%2,%3};"
        : "+f"(c[0]), "+f"(c[1]), "+f"(c[2]), "+f"(c[3])
        : "r"(a[0]), "r"(a[1]), "r"(a[2]), "r"(a[3]), "r"(b0), "r"(b1));
}
#define CP16(dst, src) asm volatile("cp.async.cg.shared.global [%0], [%1], 16;" :: "r"(dst), "l"(src))

// ---------------- K1: causal depthwise conv (W=4) + SiLU + bf16 splits -----
__global__ void conv_silu_kernel(const float* __restrict__ x,
                                 const float* __restrict__ cw,
                                 const float* __restrict__ cb) {
    int d  = blockIdx.x * 256 + threadIdx.x;
    int t0 = blockIdx.y * 8;
    int b  = blockIdx.z;
    float4 w = *reinterpret_cast<const float4*>(cw + d * 4);
    float bias = cb[d];
    size_t base = ((size_t)b * Ll) * Dd + d;
    const float* xb = x + base;
    float* sp = g_shift + base;
    float xm3 = (t0 - 3 >= 0) ? xb[(size_t)(t0 - 3) * Dd] : 0.f;
    float xm2 = (t0 - 2 >= 0) ? xb[(size_t)(t0 - 2) * Dd] : 0.f;
    float xm1 = (t0 - 1 >= 0) ? xb[(size_t)(t0 - 1) * Dd] : 0.f;
#pragma unroll
    for (int i = 0; i < 8; i++) {
        int t = t0 + i;
        size_t o = base + (size_t)t * Dd;
        float xt = xb[(size_t)t * Dd];
        float y = xm3 * w.x + xm2 * w.y + xm1 * w.z + xt * w.w + bias;
        float s = y * sigmoidf_(y);
        sp[(size_t)t * Dd] = s;
        split_bf16(s,  &g_sh_hi[o], &g_sh_lo[o]);
        split_bf16(xt, &g_x_hi[o],  &g_x_lo[o]);
        xm3 = xm2; xm2 = xm1; xm1 = xt;
    }
}

// ---------------- K1b: weight splits ----------------------------------------
__global__ void wsplit_kernel(const float* __restrict__ w_in,
                              const float* __restrict__ w_mg,
                              const float* __restrict__ w_ch,
                              const float* __restrict__ w1) {
    int i = blockIdx.x * 256 + threadIdx.x;   // i < 256*2048
    float v = (i < 128 * Dd) ? w_in[i] : w_mg[i - 128 * Dd];
    split_bf16(v, &g_b01_hi[i], &g_b01_lo[i]);
    if (i < 128 * Dd) {
        split_bf16(w_ch[i], &g_b2_hi[i], &g_b2_lo[i]);
        split_bf16(w1[i],   &g_w1_hi[i], &g_w1_lo[i]);
    }
}

// ---------------- K2: tensor-core projections via mma.sync (3xBF16) --------
// 2-stage smem ring (80KB) -> 2 CTAs/SM co-resident for latency hiding.
#define SA 40                          // padded row stride (bf16 elems)
#define STG_E (4*128*SA)               // elems per stage (Ah,Al,Bh,Bl)
#define OFF_AL (128*SA)
#define OFF_BH (2*128*SA)
#define OFF_BL (3*128*SA)
#define SMEM_2STG (2*STG_E*2)

__global__ __launch_bounds__(256, 2) void mma_proj_kernel() {
    extern __shared__ __align__(128) __nv_bfloat16 sm[];
    const int tid = threadIdx.x;
    const int lane = tid & 31, wid = tid >> 5;
    const int wm = wid & 3, wn = wid >> 2;
    const int y = blockIdx.y;
    const int tok0 = blockIdx.x * 128;

    const __nv_bfloat16* Ah = (y == 2) ? g_x_hi : g_sh_hi;
    const __nv_bfloat16* Al = (y == 2) ? g_x_lo : g_sh_lo;
    const __nv_bfloat16* Bh = (y == 2) ? g_b2_hi : g_b01_hi + (size_t)y * 128 * Dd;
    const __nv_bfloat16* Bl = (y == 2) ? g_b2_lo : g_b01_lo + (size_t)y * 128 * Dd;

    const unsigned sbase = (unsigned)__cvta_generic_to_shared(sm);

    auto load_stage = [&](int s) {
        const int kb = s * 32;
        const unsigned st = sbase + (s & 1) * (STG_E * 2);
#pragma unroll
        for (int j = 0; j < 8; j++) {
            int i = tid + j * 256;
            int arr = i >> 9;
            int rem = i & 511;
            int row = rem >> 2, c = rem & 3;
            unsigned dst = st + arr * (128 * SA * 2) + (row * SA + c * 8) * 2;
            const __nv_bfloat16* src =
                (arr == 0 ? Ah + (size_t)(tok0 + row) * Dd :
                 arr == 1 ? Al + (size_t)(tok0 + row) * Dd :
                 arr == 2 ? Bh + (size_t)row * Dd :
                            Bl + (size_t)row * Dd) + kb + c * 8;
            CP16(dst, src);
        }
    };

    load_stage(0);
    asm volatile("cp.async.commit_group;" ::: "memory");
    load_stage(1);
    asm volatile("cp.async.commit_group;" ::: "memory");

    float acc[2][8][4];
#pragma unroll
    for (int mt = 0; mt < 2; mt++)
#pragma unroll
        for (int nt = 0; nt < 8; nt++)
#pragma unroll
            for (int q = 0; q < 4; q++) acc[mt][nt][q] = 0.f;

    const int lr = lane & 15, lc = lane >> 4;

    for (int s = 0; s < 64; s++) {
        asm volatile("cp.async.wait_group 1;" ::: "memory");
        __syncthreads();

        const unsigned st = sbase + (s & 1) * (STG_E * 2);
#pragma unroll
        for (int kk = 0; kk < 2; kk++) {
            const unsigned kofs = (kk * 16 + lc * 8) * 2;
            unsigned ah[2][4], al[2][4];
#pragma unroll
            for (int mt = 0; mt < 2; mt++) {
                int row = wm * 32 + mt * 16 + lr;
                ldsm4(ah[mt][0], ah[mt][1], ah[mt][2], ah[mt][3],
                      st + row * (SA * 2) + kofs);
                ldsm4(al[mt][0], al[mt][1], al[mt][2], al[mt][3],
                      st + OFF_AL * 2 + row * (SA * 2) + kofs);
            }
#pragma unroll
            for (int nt16 = 0; nt16 < 4; nt16++) {
                int nrow = wn * 64 + nt16 * 16 + lr;
                unsigned bh[4], bl[4];
                ldsm4(bh[0], bh[1], bh[2], bh[3],
                      st + OFF_BH * 2 + nrow * (SA * 2) + kofs);
                ldsm4(bl[0], bl[1], bl[2], bl[3],
                      st + OFF_BL * 2 + nrow * (SA * 2) + kofs);
#pragma unroll
                for (int half = 0; half < 2; half++) {
                    unsigned bh0 = half ? bh[1] : bh[0], bh1 = half ? bh[3] : bh[2];
                    unsigned bl0 = half ? bl[1] : bl[0], bl1 = half ? bl[3] : bl[2];
                    int nt = nt16 * 2 + half;
#pragma unroll
                    for (int mt = 0; mt < 2; mt++) {
                        mma16816(acc[mt][nt], ah[mt], bh0, bh1);
                        mma16816(acc[mt][nt], ah[mt], bl0, bl1);
                        mma16816(acc[mt][nt], al[mt], bh0, bh1);
                    }
                }
            }
        }
        // 2-stage ring: slot (s+2)&1 == slot s&1 — must finish compute first
        __syncthreads();
        if (s + 2 < 64) load_stage(s + 2);
        asm volatile("cp.async.commit_group;" ::: "memory");
    }

    const int g = lane >> 2, tig = lane & 3;
    if (y < 2) {
        const int zoff = y * 128;
#pragma unroll
        for (int mt = 0; mt < 2; mt++) {
            int token = tok0 + wm * 32 + mt * 16 + g;
#pragma unroll
            for (int nt = 0; nt < 8; nt++) {
                int col = zoff + wn * 64 + nt * 8 + tig * 2;
                *reinterpret_cast<float2*>(g_zp + (size_t)token * 384 + col) =
                    make_float2(acc[mt][nt][0], acc[mt][nt][1]);
                *reinterpret_cast<float2*>(g_zp + (size_t)(token + 8) * 384 + col) =
                    make_float2(acc[mt][nt][2], acc[mt][nt][3]);
            }
        }
    } else {
#pragma unroll
        for (int mt = 0; mt < 2; mt++) {
            int token = tok0 + wm * 32 + mt * 16 + g;
#pragma unroll
            for (int nt = 0; nt < 8; nt++) {
                int col = wn * 64 + nt * 8 + tig * 2;
                size_t o0 = (size_t)token * Rr + col;
                size_t o1 = (size_t)(token + 8) * Rr + col;
                split_bf16(acc[mt][nt][0], &g_h_hi[o0],     &g_h_lo[o0]);
                split_bf16(acc[mt][nt][1], &g_h_hi[o0 + 1], &g_h_lo[o0 + 1]);
                split_bf16(acc[mt][nt][2], &g_h_hi[o1],     &g_h_lo[o1]);
                split_bf16(acc[mt][nt][3], &g_h_hi[o1 + 1], &g_h_lo[o1 + 1]);
            }
        }
    }
}

// ---------------- K3: u = sigmoid(h @ w1^T + b1) * x  (tensor core) --------
__global__ __launch_bounds__(256, 2) void ugemm_mma_kernel(
    const float* __restrict__ x, const float* __restrict__ b1) {
    extern __shared__ __align__(128) __nv_bfloat16 sm[];
    const int tid = threadIdx.x;
    const int lane = tid & 31, wid = tid >> 5;
    const int wm = wid & 3, wn = wid >> 2;
    const int tok0 = blockIdx.x * 128;
    const int d0   = blockIdx.y * 128;

    const unsigned sbase = (unsigned)__cvta_generic_to_shared(sm);

    auto load_stage = [&](int s) {
        const int kb = s * 32;
        const unsigned st = sbase + (s & 1) * (STG_E * 2);
#pragma unroll
        for (int j = 0; j < 8; j++) {
            int i = tid + j * 256;
            int arr = i >> 9;
            int rem = i & 511;
            int row = rem >> 2, c = rem & 3;
            unsigned dst = st + arr * (128 * SA * 2) + (row * SA + c * 8) * 2;
            const __nv_bfloat16* src =
                (arr == 0 ? g_h_hi + (size_t)(tok0 + row) * Rr :
                 arr == 1 ? g_h_lo + (size_t)(tok0 + row) * Rr :
                 arr == 2 ? g_w1_hi + (size_t)(d0 + row) * Rr :
                            g_w1_lo + (size_t)(d0 + row) * Rr) + kb + c * 8;
            CP16(dst, src);
        }
    };

    load_stage(0);
    asm volatile("cp.async.commit_group;" ::: "memory");
    load_stage(1);
    asm volatile("cp.async.commit_group;" ::: "memory");

    float acc[2][8][4];
#pragma unroll
    for (int mt = 0; mt < 2; mt++)
#pragma unroll
        for (int nt = 0; nt < 8; nt++)
#pragma unroll
            for (int q = 0; q < 4; q++) acc[mt][nt][q] = 0.f;

    const int lr = lane & 15, lc = lane >> 4;

    for (int s = 0; s < 4; s++) {
        asm volatile("cp.async.wait_group 1;" ::: "memory");
        __syncthreads();

        const unsigned st = sbase + (s & 1) * (STG_E * 2);
#pragma unroll
        for (int kk = 0; kk < 2; kk++) {
            const unsigned kofs = (kk * 16 + lc * 8) * 2;
            unsigned ah[2][4], al[2][4];
#pragma unroll
            for (int mt = 0; mt < 2; mt++) {
                int row = wm * 32 + mt * 16 + lr;
                ldsm4(ah[mt][0], ah[mt][1], ah[mt][2], ah[mt][3],
                      st + row * (SA * 2) + kofs);
                ldsm4(al[mt][0], al[mt][1], al[mt][2], al[mt][3],
                      st + OFF_AL * 2 + row * (SA * 2) + kofs);
            }
#pragma unroll
            for (int nt16 = 0; nt16 < 4; nt16++) {
                int nrow = wn * 64 + nt16 * 16 + lr;
                unsigned bh[4], bl[4];
                ldsm4(bh[0], bh[1], bh[2], bh[3],
                      st + OFF_BH * 2 + nrow * (SA * 2) + kofs);
                ldsm4(bl[0], bl[1], bl[2], bl[3],
                      st + OFF_BL * 2 + nrow * (SA * 2) + kofs);
#pragma unroll
                for (int half = 0; half < 2; half++) {
                    unsigned bh0 = half ? bh[1] : bh[0], bh1 = half ? bh[3] : bh[2];
                    unsigned bl0 = half ? bl[1] : bl[0], bl1 = half ? bl[3] : bl[2];
                    int nt = nt16 * 2 + half;
#pragma unroll
                    for (int mt = 0; mt < 2; mt++) {
                        mma16816(acc[mt][nt], ah[mt], bh0, bh1);
                        mma16816(acc[mt][nt], ah[mt], bl0, bl1);
                        mma16816(acc[mt][nt], al[mt], bh0, bh1);
                    }
                }
            }
        }
        __syncthreads();
        if (s + 2 < 4) load_stage(s + 2);
        asm volatile("cp.async.commit_group;" ::: "memory");
    }

    const int g = lane >> 2, tig = lane & 3;
#pragma unroll
    for (int mt = 0; mt < 2; mt++) {
        int token = tok0 + wm * 32 + mt * 16 + g;
#pragma unroll
        for (int nt = 0; nt < 8; nt++) {
            int col = d0 + wn * 64 + nt * 8 + tig * 2;
            float2 bb = *reinterpret_cast<const float2*>(b1 + col);
#pragma unroll
            for (int rr = 0; rr < 2; rr++) {
                int tk = token + rr * 8;
                float z0 = acc[mt][nt][rr * 2]     + bb.x;
                float z1 = acc[mt][nt][rr * 2 + 1] + bb.y;
                float2 xv = *reinterpret_cast<const float2*>(x + (size_t)tk * Dd + col);
                float2 uv = make_float2(sigmoidf_(z0) * xv.x, sigmoidf_(z1) * xv.y);
                *reinterpret_cast<float2*>(g_u + (size_t)tk * Dd + col) = uv;
            }
        }
    }
}

// ---------------- K4: gate math per token -----------------------------------
__global__ void gates_kernel(const float* __restrict__ mb) {
    int warp = threadIdx.x >> 5;
    int lane = threadIdx.x & 31;
    int token = blockIdx.x * 4 + warp;
    const float* zp = g_zp + (size_t)token * 384;

    float r_a = zp[lane],        r_b = zp[32 + lane];
    float k_a = zp[64 + lane],   k_b = zp[96 + lane];
    float m1a = zp[128 + lane] + mb[lane];
    float m1b = zp[160 + lane] + mb[32 + lane];
    float m2a = zp[192 + lane] + mb[64 + lane];
    float m2b = zp[224 + lane] + mb[96 + lane];

    float sela = softplusf_(m1a), selb = softplusf_(m1b);
    float taua = sigmoidf_(m2a),  taub = sigmoidf_(m2b);
    float ita = expf(taua * logf(sela));
    float itb = expf(taub * logf(selb));
    float ega = expf(-sela * taua);
    float egb = expf(-selb * taub);

    float ss = k_a * k_a + k_b * k_b;
#pragma unroll
    for (int o = 16; o > 0; o >>= 1) ss += __shfl_xor_sync(0xffffffffu, ss, o);
    float inv = 1.f / fmaxf(sqrtf(ss), 1e-12f);

    float* go = g_gates + (size_t)token * 192;
    go[lane]       = r_a;             go[32 + lane]  = r_b;
    go[64 + lane]  = k_a * inv * ita; go[96 + lane]  = k_b * inv * itb;
    go[128 + lane] = ega;             go[160 + lane] = egb;
}

// ---------------- K4b: r~ = r * cumdecay (per chunk) + chunk products -------
__global__ __launch_bounds__(128) void rtil_kernel() {
    int w = blockIdx.x * 4 + (threadIdx.x >> 5);
    int lane = threadIdx.x & 31;
    int c = w & 7;
    int bh = w >> 3;
    int b = bh >> 1, h = bh & 1;
    int m = h * 32 + lane;

    const float* gbase = g_gates + ((size_t)(b * Ll + c * CL)) * 192;
    float* rout = g_rtil + ((size_t)(b * Ll + c * CL)) * Mm + m;

    float P = 1.f;
    float ef[8], rf[8];
#pragma unroll
    for (int i = 0; i < 8; i++) {
        ef[i] = gbase[(size_t)i * 192 + 128 + m];
        rf[i] = gbase[(size_t)i * 192 + m];
    }
    for (int t = 0; t < CL; t++) {
        int j = t & 7;
        P *= ef[j];
        rout[(size_t)t * Mm] = rf[j] * P;
        if (t + 8 < CL) {
            ef[j] = gbase[(size_t)(t + 8) * 192 + 128 + m];
            rf[j] = gbase[(size_t)(t + 8) * 192 + m];
        }
    }
    g_Pc[(b * NC + c) * Mm + m] = P;
}

// ---------------- K5a: chunk-local scans ------------------------------------
__global__ __launch_bounds__(64) void scanA_kernel(const float* __restrict__ rw,
                                                   float* __restrict__ out) {
    const int tid = threadIdx.x;
    const int w = tid >> 5, lane = tid & 31;
    const int d = blockIdx.x * 64 + tid;
    const int b = blockIdx.y;
    const int h = blockIdx.z / NC;
    const int c = blockIdx.z % NC;
    const int t0base = c * CL;

    __shared__ __align__(16) float sg[2][PF][96];

    const float* gb = g_gates + (size_t)b * Ll * 192;
    const int ch  = lane >> 3;
    const int off = (lane & 7) * 4;
    const int gsrc_off = (ch == 0 ? h * 32 : ch == 1 ? 64 + h * 32 : 128 + h * 32) + off;
    const bool active = lane < 24;
    const unsigned sbase =
        (unsigned)__cvta_generic_to_shared(&sg[w][0][ch * 32 + off]);

#pragma unroll
    for (int s = 0; s < PF - 1; s++) {
        if (active) {
            const float* src = gb + (size_t)(t0base + s) * 192 + gsrc_off;
            unsigned dst = sbase + ((t0base + s) & (PF - 1)) * 96 * 4;
            asm volatile("cp.async.ca.shared.global [%0], [%1], 16;"
                         :: "r"(dst), "l"(src));
        }
        asm volatile("cp.async.commit_group;" ::: "memory");
    }

    float2 S[16];
#pragma unroll
    for (int p = 0; p < 16; p++) S[p] = make_float2(0.f, 0.f);

    const float* ub = g_u + ((size_t)b * Ll) * Dd + d;
    const float* sb = g_shift + ((size_t)b * Ll) * Dd + d;
    float* ob = out + ((size_t)b * Ll) * Dd + d;
    const float rwd = (h == 0) ? rw[d] : 0.f;

    float upf[8], spf[8];
#pragma unroll
    for (int i = 0; i < 8; i++) {
        upf[i] = __ldcg(ub + (size_t)(t0base + i) * Dd);
        spf[i] = (h == 0) ? __ldcg(sb + (size_t)(t0base + i) * Dd) : 0.f;
    }

    for (int tb = 0; tb < CL; tb += 8) {
#pragma unroll
        for (int j = 0; j < 8; j++) {
            const int t = t0base + tb + j;
            asm volatile("cp.async.wait_group 2;" ::: "memory");
            __syncwarp();
            const float* g0 = &sg[w][t & (PF - 1)][0];

            float2 uu = make_float2(upf[j], upf[j]);
            float2 a0 = make_float2(0.f, 0.f), a1 = a0;
#pragma unroll
            for (int q = 0; q < 8; q++) {
                float4 r4 = *reinterpret_cast<const float4*>(g0 + q * 4);
                float4 k4 = *reinterpret_cast<const float4*>(g0 + 32 + q * 4);
                float4 e4 = *reinterpret_cast<const float4*>(g0 + 64 + q * 4);
                S[2 * q]     = ffma2(make_float2(e4.x, e4.y), S[2 * q],
                                     fmul2(make_float2(k4.x, k4.y), uu));
                S[2 * q + 1] = ffma2(make_float2(e4.z, e4.w), S[2 * q + 1],
                                     fmul2(make_float2(k4.z, k4.w), uu));
                a0 = ffma2(make_float2(r4.x, r4.y), S[2 * q],     a0);
                a1 = ffma2(make_float2(r4.z, r4.w), S[2 * q + 1], a1);
            }
            float o = OSCALE * ((a0.x + a0.y) + (a1.x + a1.y)) + spf[j] * rwd;
            atomicAdd(ob + (size_t)t * Dd, o);

            const int tn = t + PF - 1;
            if (tn < t0base + CL && active) {
                const float* src = gb + (size_t)tn * 192 + gsrc_off;
                unsigned dst = sbase + (tn & (PF - 1)) * 96 * 4;
                asm volatile("cp.async.ca.shared.global [%0], [%1], 16;"
                             :: "r"(dst), "l"(src));
            }
            asm volatile("cp.async.commit_group;" ::: "memory");

            if (tb + j + 8 < CL) {
                upf[j] = __ldcg(ub + (size_t)(t + 8) * Dd);
                spf[j] = (h == 0) ? __ldcg(sb + (size_t)(t + 8) * Dd) : 0.f;
            }
        }
    }

    if (c < NC - 1) {
        float* se = g_Send + ((size_t)(b * NC + c) * Mm + h * 32) * Dd + d;
#pragma unroll
        for (int p = 0; p < 16; p++) {
            se[(size_t)(2 * p) * Dd]     = S[p].x;
            se[(size_t)(2 * p + 1) * Dd] = S[p].y;
        }
    }
}

// ---------------- K5b: cross-chunk state propagation ------------------------
__global__ __launch_bounds__(64) void phaseB_kernel() {
    const int d = blockIdx.x * 64 + threadIdx.x;
    const int b = blockIdx.y;
    const int h = blockIdx.z;

    float Sin[32];
#pragma unroll
    for (int j = 0; j < 32; j++) Sin[j] = 0.f;

    for (int c = 0; c < NC - 1; c++) {
        const float* se = g_Send + ((size_t)(b * NC + c) * Mm + h * 32) * Dd + d;
        const float* pc = g_Pc + (b * NC + c) * Mm + h * 32;
        float* so = g_Sin + ((size_t)(b * NC + c + 1) * Mm + h * 32) * Dd + d;
#pragma unroll
        for (int j = 0; j < 32; j++) {
            Sin[j] = pc[j] * Sin[j] + se[(size_t)j * Dd];
            so[(size_t)j * Dd] = Sin[j];
        }
    }
}

// ---------------- K5c: correction GEMM out += OSCALE * rtil @ Sin -----------
__global__ __launch_bounds__(256) void phaseC_kernel(float* __restrict__ out) {
    const int idx = blockIdx.y;
    const int b = idx / (NC - 1);
    const int c = 1 + idx % (NC - 1);
    const int tt = blockIdx.x & 3, dt = blockIdx.x >> 2;
    const int t0 = c * CL + tt * 64;
    const int d0 = dt * 128;

    const float* A  = g_rtil + ((size_t)b * Ll + t0) * Mm;        // [64 t][64 k]
    const float* Bm = g_Sin + ((size_t)(b * NC + c) * Mm) * Dd + d0; // [64 k][Dd]

    __shared__ float As[2][16 * 68];
    __shared__ float Bs[2][16 * 132];

    const int tid = threadIdx.x;
    const int tg = tid >> 4, ng = tid & 15;
    const int a_t = tid >> 2, a_k = (tid & 3) * 4;
    const int b_kr = tid >> 4, b_nb = (tid & 15) * 8;

    float2 acc[4][4];
#pragma unroll
    for (int i = 0; i < 4; i++)
#pragma unroll
        for (int j = 0; j < 4; j++) acc[i][j] = make_float2(0.f, 0.f);

    const float* Aptr = A + (size_t)a_t * Mm + a_k;
    const float* Bptr = Bm + (size_t)b_kr * Dd + b_nb;

    float4 av  = *reinterpret_cast<const float4*>(Aptr);
    float4 bv0 = *reinterpret_cast<const float4*>(Bptr);
    float4 bv1 = *reinterpret_cast<const float4*>(Bptr + 4);

    const int NT = 4;   // K=64, BK=16
    for (int kt = 0; kt < NT; ++kt) {
        const int p = kt & 1;
        {
            float* as = As[p] + a_k * 68 + a_t;
            as[0] = av.x; as[68] = av.y; as[2 * 68] = av.z; as[3 * 68] = av.w;
            float* bs = Bs[p] + b_kr * 132 + b_nb;
            bs[0] = bv0.x; bs[1] = bv0.y; bs[2] = bv0.z; bs[3] = bv0.w;
            bs[4] = bv1.x; bs[5] = bv1.y; bs[6] = bv1.z; bs[7] = bv1.w;
        }
        __syncthreads();
        if (kt + 1 < NT) {
            av  = *reinterpret_cast<const float4*>(Aptr + (kt + 1) * 16);
            bv0 = *reinterpret_cast<const float4*>(Bptr + (size_t)(kt + 1) * 16 * Dd);
            bv1 = *reinterpret_cast<const float4*>(Bptr + (size_t)(kt + 1) * 16 * Dd + 4);
        }
#pragma unroll
        for (int k = 0; k < 16; k++) {
            float4 a4  = *reinterpret_cast<const float4*>(As[p] + k * 68 + tg * 4);
            float4 b40 = *reinterpret_cast<const float4*>(Bs[p] + k * 132 + ng * 8);
            float4 b41 = *reinterpret_cast<const float4*>(Bs[p] + k * 132 + ng * 8 + 4);
            float aval[4] = {a4.x, a4.y, a4.z, a4.w};
            float2 bp[4] = {make_float2(b40.x, b40.y), make_float2(b40.z, b40.w),
                            make_float2(b41.x, b41.y), make_float2(b41.z, b41.w)};
#pragma unroll
            for (int i = 0; i < 4; i++) {
                float2 aa = make_float2(aval[i], aval[i]);
#pragma unroll
                for (int j = 0; j < 4; j++) acc[i][j] = ffma2(aa, bp[j], acc[i][j]);
            }
        }
    }
#pragma unroll
    for (int i = 0; i < 4; i++) {
        int token = t0 + tg * 4 + i;
        float* op = out + ((size_t)b * Ll + token) * Dd + d0 + ng * 8;
#pragma unroll
        for (int j = 0; j < 4; j++) {
            float2 cur = *reinterpret_cast<float2*>(op + 2 * j);
            cur.x += OSCALE * acc[i][j].x;
            cur.y += OSCALE * acc[i][j].y;
            *reinterpret_cast<float2*>(op + 2 * j) = cur;
        }
    }
}

// ---------------- launch -----------------------------------------------------
extern "C" void kernel_launch(void* const* d_in, const int* in_sizes, int n_in,
                              void* d_out, int out_size) {
    const float* x        = (const float*)d_in[0];  // (B,L,D)
    const float* conv_w   = (const float*)d_in[1];  // (D,4)
    const float* conv_b   = (const float*)d_in[2];  // (D,)
    const float* in_proj  = (const float*)d_in[3];  // (128,D)
    const float* ch_w0    = (const float*)d_in[4];  // (128,D)
    const float* ch_w1    = (const float*)d_in[5];  // (D,128)
    const float* ch_b1    = (const float*)d_in[6];  // (D,)
    const float* mem_w    = (const float*)d_in[7];  // (128,D)
    const float* mem_b    = (const float*)d_in[8];  // (128,)
    const float* res_w    = (const float*)d_in[9];  // (D,)
    float* out = (float*)d_out;

    static bool attr_set = false;
    if (!attr_set) {
        cudaFuncSetAttribute(mma_proj_kernel,
                             cudaFuncAttributeMaxDynamicSharedMemorySize, SMEM_2STG);
        cudaFuncSetAttribute(ugemm_mma_kernel,
                             cudaFuncAttributeMaxDynamicSharedMemorySize, SMEM_2STG);
        attr_set = true;
    }

    conv_silu_kernel<<<dim3(Dd / 256, Ll / 8, Bb), 256>>>(x, conv_w, conv_b);
    wsplit_kernel<<<dim3(256 * Dd / 256), 256>>>(in_proj, mem_w, ch_w0, ch_w1);
    mma_proj_kernel<<<dim3(BL / 128, 3), 256, SMEM_2STG>>>();
    ugemm_mma_kernel<<<dim3(BL / 128, Dd / 128), 256, SMEM_2STG>>>(x, ch_b1);
    gates_kernel<<<dim3(BL / 4), 128>>>(mem_b);
    rtil_kernel<<<dim3(16), 128>>>();
    cudaMemsetAsync(out, 0, (size_t)out_size * sizeof(float), 0);
    scanA_kernel<<<dim3(Dd / 64, Bb, 2 * NC), 64>>>(res_w, out);
    phaseB_kernel<<<dim3(Dd / 64, Bb, 2), 64>>>();
    phaseC_kernel<<<dim3(64, Bb * (NC - 1)), 256>>>(out);
}

// round 9
// speedup vs baseline: 3.2462x; 1.0751x over previous
#include <cuda_runtime.h>
#include <cuda_bf16.h>
#include <math.h>

// Problem constants
#define Bb 4
#define Ll 2048
#define Dd 2048
#define Mm 64
#define Rr 128
#define BL (Bb*Ll)
#define OSCALE 0.125f   // 1/sqrt(64)
#define PF 4            // scan gates prefetch stages (power of 2)
#define NC 8            // scan time chunks
#define CL 256          // chunk length

// ---------------- scratch (device globals; no allocation allowed) ----------
__device__ float g_shift[BL*Dd];     // silu(conv(x))  (residual, scan input)
__device__ float g_u[BL*Dd];         // ch * x
__device__ float g_zp[BL*384];       // [token][0..127]=rk, [128..255]=mg(pre-bias)
__device__ float g_gates[BL*192];    // [token][0..63]=r, [64..127]=k_hat, [128..191]=exp(g)

// bf16 splits for tensor-core 3xBF16 GEMMs
__device__ __nv_bfloat16 g_sh_hi[BL*Dd], g_sh_lo[BL*Dd];
__device__ __nv_bfloat16 g_x_hi[BL*Dd],  g_x_lo[BL*Dd];
__device__ __nv_bfloat16 g_b01_hi[256*Dd], g_b01_lo[256*Dd];  // [in_proj;mem_gate]
__device__ __nv_bfloat16 g_b2_hi[128*Dd],  g_b2_lo[128*Dd];   // ch_gate_w0
__device__ __nv_bfloat16 g_w1_hi[Dd*Rr],   g_w1_lo[Dd*Rr];    // ch_gate_w1
__device__ __nv_bfloat16 g_h_hi[BL*Rr],    g_h_lo[BL*Rr];     // h = x @ w0^T

// chunked-scan scratch
__device__ float g_Send[Bb*NC*Mm*Dd];   // local end-state per chunk
__device__ float g_Sin[Bb*NC*Mm*Dd];    // incoming state per chunk (c>=1)
__device__ float g_rtil[BL*Mm];         // r_t * cumdecay_within_chunk
__device__ float g_Pc[Bb*NC*Mm];        // full-chunk decay products

// ---------------- f32x2 packed math helpers --------------------------------
__device__ __forceinline__ float2 ffma2(float2 a, float2 b, float2 c) {
    unsigned long long au = *reinterpret_cast<unsigned long long*>(&a);
    unsigned long long bu = *reinterpret_cast<unsigned long long*>(&b);
    unsigned long long cu = *reinterpret_cast<unsigned long long*>(&c);
    unsigned long long du;
    asm("fma.rn.f32x2 %0, %1, %2, %3;" : "=l"(du) : "l"(au), "l"(bu), "l"(cu));
    return *reinterpret_cast<float2*>(&du);
}
__device__ __forceinline__ float2 fmul2(float2 a, float2 b) {
    unsigned long long au = *reinterpret_cast<unsigned long long*>(&a);
    unsigned long long bu = *reinterpret_cast<unsigned long long*>(&b);
    unsigned long long du;
    asm("mul.rn.f32x2 %0, %1, %2;" : "=l"(du) : "l"(au), "l"(bu));
    return *reinterpret_cast<float2*>(&du);
}
__device__ __forceinline__ float sigmoidf_(float x) { return 1.f / (1.f + expf(-x)); }
__device__ __forceinline__ float softplusf_(float x) {
    return fmaxf(x, 0.f) + log1pf(expf(-fabsf(x)));
}
__device__ __forceinline__ void split_bf16(float v, __nv_bfloat16* hi, __nv_bfloat16* lo) {
    __nv_bfloat16 h = __float2bfloat16_rn(v);
    *hi = h;
    *lo = __float2bfloat16_rn(v - __bfloat162float(h));
}

// ---------------- warp-MMA helpers ------------------------------------------
__device__ __forceinline__ void ldsm4(unsigned& r0, unsigned& r1, unsigned& r2,
                                      unsigned& r3, unsigned addr) {
    asm volatile("ldmatrix.sync.aligned.m8n8.x4.shared.b16 {%0,%1,%2,%3}, [%4];"
                 : "=r"(r0), "=r"(r1), "=r"(r2), "=r"(r3) : "r"(addr));
}
__device__ __forceinline__ void mma16816(float* c, const unsigned* a,
                                         unsigned b0, unsigned b1) {
    asm volatile(
        "mma.sync.aligned.m16n8k16.row.col.f32.bf16.bf16.f32 "
        "{%0,%1,%2,%3}, {%4,%5,%6,%7}, {%8,%9}, {%0,%1,%2,%3};"
        : "+f"(c[0]), "+f"(c[1]), "+f"(c[2]), "+f"(c[3])
        : "r"(a[0]), "r"(a[1]), "r"(a[2]), "r"(a[3]), "r"(b0), "r"(b1));
}
#define CP16(dst, src) asm volatile("cp.async.cg.shared.global [%0], [%1], 16;" :: "r"(dst), "l"(src))
#define CPA16(dst, src) asm volatile("cp.async.ca.shared.global [%0], [%1], 16;" :: "r"(dst), "l"(src))

// ---------------- K1: causal depthwise conv (W=4) + SiLU + bf16 splits -----
__global__ void conv_silu_kernel(const float* __restrict__ x,
                                 const float* __restrict__ cw,
                                 const float* __restrict__ cb) {
    int d  = blockIdx.x * 256 + threadIdx.x;
    int t0 = blockIdx.y * 8;
    int b  = blockIdx.z;
    float4 w = *reinterpret_cast<const float4*>(cw + d * 4);
    float bias = cb[d];
    size_t base = ((size_t)b * Ll) * Dd + d;
    const float* xb = x + base;
    float* sp = g_shift + base;
    float xm3 = (t0 - 3 >= 0) ? xb[(size_t)(t0 - 3) * Dd] : 0.f;
    float xm2 = (t0 - 2 >= 0) ? xb[(size_t)(t0 - 2) * Dd] : 0.f;
    float xm1 = (t0 - 1 >= 0) ? xb[(size_t)(t0 - 1) * Dd] : 0.f;
#pragma unroll
    for (int i = 0; i < 8; i++) {
        int t = t0 + i;
        size_t o = base + (size_t)t * Dd;
        float xt = xb[(size_t)t * Dd];
        float y = xm3 * w.x + xm2 * w.y + xm1 * w.z + xt * w.w + bias;
        float s = y * sigmoidf_(y);
        sp[(size_t)t * Dd] = s;
        split_bf16(s,  &g_sh_hi[o], &g_sh_lo[o]);
        split_bf16(xt, &g_x_hi[o],  &g_x_lo[o]);
        xm3 = xm2; xm2 = xm1; xm1 = xt;
    }
}

// ---------------- K1b: weight splits ----------------------------------------
__global__ void wsplit_kernel(const float* __restrict__ w_in,
                              const float* __restrict__ w_mg,
                              const float* __restrict__ w_ch,
                              const float* __restrict__ w1) {
    int i = blockIdx.x * 256 + threadIdx.x;   // i < 256*2048
    float v = (i < 128 * Dd) ? w_in[i] : w_mg[i - 128 * Dd];
    split_bf16(v, &g_b01_hi[i], &g_b01_lo[i]);
    if (i < 128 * Dd) {
        split_bf16(w_ch[i], &g_b2_hi[i], &g_b2_lo[i]);
        split_bf16(w1[i],   &g_w1_hi[i], &g_w1_lo[i]);
    }
}

// ---------------- K2: tensor-core projections via mma.sync (3xBF16) --------
// 2-stage smem ring (80KB) -> 2 CTAs/SM co-resident for latency hiding.
#define SA 40                          // padded row stride (bf16 elems)
#define STG_E (4*128*SA)               // elems per stage (Ah,Al,Bh,Bl)
#define OFF_AL (128*SA)
#define OFF_BH (2*128*SA)
#define OFF_BL (3*128*SA)
#define SMEM_2STG (2*STG_E*2)

__global__ __launch_bounds__(256, 2) void mma_proj_kernel() {
    extern __shared__ __align__(128) __nv_bfloat16 sm[];
    const int tid = threadIdx.x;
    const int lane = tid & 31, wid = tid >> 5;
    const int wm = wid & 3, wn = wid >> 2;
    const int y = blockIdx.y;
    const int tok0 = blockIdx.x * 128;

    const __nv_bfloat16* Ah = (y == 2) ? g_x_hi : g_sh_hi;
    const __nv_bfloat16* Al = (y == 2) ? g_x_lo : g_sh_lo;
    const __nv_bfloat16* Bh = (y == 2) ? g_b2_hi : g_b01_hi + (size_t)y * 128 * Dd;
    const __nv_bfloat16* Bl = (y == 2) ? g_b2_lo : g_b01_lo + (size_t)y * 128 * Dd;

    const unsigned sbase = (unsigned)__cvta_generic_to_shared(sm);

    auto load_stage = [&](int s) {
        const int kb = s * 32;
        const unsigned st = sbase + (s & 1) * (STG_E * 2);
#pragma unroll
        for (int j = 0; j < 8; j++) {
            int i = tid + j * 256;
            int arr = i >> 9;
            int rem = i & 511;
            int row = rem >> 2, c = rem & 3;
            unsigned dst = st + arr * (128 * SA * 2) + (row * SA + c * 8) * 2;
            const __nv_bfloat16* src =
                (arr == 0 ? Ah + (size_t)(tok0 + row) * Dd :
                 arr == 1 ? Al + (size_t)(tok0 + row) * Dd :
                 arr == 2 ? Bh + (size_t)row * Dd :
                            Bl + (size_t)row * Dd) + kb + c * 8;
            CP16(dst, src);
        }
    };

    load_stage(0);
    asm volatile("cp.async.commit_group;" ::: "memory");
    load_stage(1);
    asm volatile("cp.async.commit_group;" ::: "memory");

    float acc[2][8][4];
#pragma unroll
    for (int mt = 0; mt < 2; mt++)
#pragma unroll
        for (int nt = 0; nt < 8; nt++)
#pragma unroll
            for (int q = 0; q < 4; q++) acc[mt][nt][q] = 0.f;

    const int lr = lane & 15, lc = lane >> 4;

    for (int s = 0; s < 64; s++) {
        asm volatile("cp.async.wait_group 1;" ::: "memory");
        __syncthreads();

        const unsigned st = sbase + (s & 1) * (STG_E * 2);
#pragma unroll
        for (int kk = 0; kk < 2; kk++) {
            const unsigned kofs = (kk * 16 + lc * 8) * 2;
            unsigned ah[2][4], al[2][4];
#pragma unroll
            for (int mt = 0; mt < 2; mt++) {
                int row = wm * 32 + mt * 16 + lr;
                ldsm4(ah[mt][0], ah[mt][1], ah[mt][2], ah[mt][3],
                      st + row * (SA * 2) + kofs);
                ldsm4(al[mt][0], al[mt][1], al[mt][2], al[mt][3],
                      st + OFF_AL * 2 + row * (SA * 2) + kofs);
            }
#pragma unroll
            for (int nt16 = 0; nt16 < 4; nt16++) {
                int nrow = wn * 64 + nt16 * 16 + lr;
                unsigned bh[4], bl[4];
                ldsm4(bh[0], bh[1], bh[2], bh[3],
                      st + OFF_BH * 2 + nrow * (SA * 2) + kofs);
                ldsm4(bl[0], bl[1], bl[2], bl[3],
                      st + OFF_BL * 2 + nrow * (SA * 2) + kofs);
#pragma unroll
                for (int half = 0; half < 2; half++) {
                    unsigned bh0 = half ? bh[1] : bh[0], bh1 = half ? bh[3] : bh[2];
                    unsigned bl0 = half ? bl[1] : bl[0], bl1 = half ? bl[3] : bl[2];
                    int nt = nt16 * 2 + half;
#pragma unroll
                    for (int mt = 0; mt < 2; mt++) {
                        mma16816(acc[mt][nt], ah[mt], bh0, bh1);
                        mma16816(acc[mt][nt], ah[mt], bl0, bl1);
                        mma16816(acc[mt][nt], al[mt], bh0, bh1);
                    }
                }
            }
        }
        // 2-stage ring: slot (s+2)&1 == slot s&1 — must finish compute first
        __syncthreads();
        if (s + 2 < 64) load_stage(s + 2);
        asm volatile("cp.async.commit_group;" ::: "memory");
    }

    const int g = lane >> 2, tig = lane & 3;
    if (y < 2) {
        const int zoff = y * 128;
#pragma unroll
        for (int mt = 0; mt < 2; mt++) {
            int token = tok0 + wm * 32 + mt * 16 + g;
#pragma unroll
            for (int nt = 0; nt < 8; nt++) {
                int col = zoff + wn * 64 + nt * 8 + tig * 2;
                *reinterpret_cast<float2*>(g_zp + (size_t)token * 384 + col) =
                    make_float2(acc[mt][nt][0], acc[mt][nt][1]);
                *reinterpret_cast<float2*>(g_zp + (size_t)(token + 8) * 384 + col) =
                    make_float2(acc[mt][nt][2], acc[mt][nt][3]);
            }
        }
    } else {
#pragma unroll
        for (int mt = 0; mt < 2; mt++) {
            int token = tok0 + wm * 32 + mt * 16 + g;
#pragma unroll
            for (int nt = 0; nt < 8; nt++) {
                int col = wn * 64 + nt * 8 + tig * 2;
                size_t o0 = (size_t)token * Rr + col;
                size_t o1 = (size_t)(token + 8) * Rr + col;
                split_bf16(acc[mt][nt][0], &g_h_hi[o0],     &g_h_lo[o0]);
                split_bf16(acc[mt][nt][1], &g_h_hi[o0 + 1], &g_h_lo[o0 + 1]);
                split_bf16(acc[mt][nt][2], &g_h_hi[o1],     &g_h_lo[o1]);
                split_bf16(acc[mt][nt][3], &g_h_hi[o1 + 1], &g_h_lo[o1 + 1]);
            }
        }
    }
}

// ---------------- K3: u = sigmoid(h @ w1^T + b1) * x  (tensor core) --------
__global__ __launch_bounds__(256, 2) void ugemm_mma_kernel(
    const float* __restrict__ x, const float* __restrict__ b1) {
    extern __shared__ __align__(128) __nv_bfloat16 sm[];
    const int tid = threadIdx.x;
    const int lane = tid & 31, wid = tid >> 5;
    const int wm = wid & 3, wn = wid >> 2;
    const int tok0 = blockIdx.x * 128;
    const int d0   = blockIdx.y * 128;

    const unsigned sbase = (unsigned)__cvta_generic_to_shared(sm);

    auto load_stage = [&](int s) {
        const int kb = s * 32;
        const unsigned st = sbase + (s & 1) * (STG_E * 2);
#pragma unroll
        for (int j = 0; j < 8; j++) {
            int i = tid + j * 256;
            int arr = i >> 9;
            int rem = i & 511;
            int row = rem >> 2, c = rem & 3;
            unsigned dst = st + arr * (128 * SA * 2) + (row * SA + c * 8) * 2;
            const __nv_bfloat16* src =
                (arr == 0 ? g_h_hi + (size_t)(tok0 + row) * Rr :
                 arr == 1 ? g_h_lo + (size_t)(tok0 + row) * Rr :
                 arr == 2 ? g_w1_hi + (size_t)(d0 + row) * Rr :
                            g_w1_lo + (size_t)(d0 + row) * Rr) + kb + c * 8;
            CP16(dst, src);
        }
    };

    load_stage(0);
    asm volatile("cp.async.commit_group;" ::: "memory");
    load_stage(1);
    asm volatile("cp.async.commit_group;" ::: "memory");

    float acc[2][8][4];
#pragma unroll
    for (int mt = 0; mt < 2; mt++)
#pragma unroll
        for (int nt = 0; nt < 8; nt++)
#pragma unroll
            for (int q = 0; q < 4; q++) acc[mt][nt][q] = 0.f;

    const int lr = lane & 15, lc = lane >> 4;

    for (int s = 0; s < 4; s++) {
        asm volatile("cp.async.wait_group 1;" ::: "memory");
        __syncthreads();

        const unsigned st = sbase + (s & 1) * (STG_E * 2);
#pragma unroll
        for (int kk = 0; kk < 2; kk++) {
            const unsigned kofs = (kk * 16 + lc * 8) * 2;
            unsigned ah[2][4], al[2][4];
#pragma unroll
            for (int mt = 0; mt < 2; mt++) {
                int row = wm * 32 + mt * 16 + lr;
                ldsm4(ah[mt][0], ah[mt][1], ah[mt][2], ah[mt][3],
                      st + row * (SA * 2) + kofs);
                ldsm4(al[mt][0], al[mt][1], al[mt][2], al[mt][3],
                      st + OFF_AL * 2 + row * (SA * 2) + kofs);
            }
#pragma unroll
            for (int nt16 = 0; nt16 < 4; nt16++) {
                int nrow = wn * 64 + nt16 * 16 + lr;
                unsigned bh[4], bl[4];
                ldsm4(bh[0], bh[1], bh[2], bh[3],
                      st + OFF_BH * 2 + nrow * (SA * 2) + kofs);
                ldsm4(bl[0], bl[1], bl[2], bl[3],
                      st + OFF_BL * 2 + nrow * (SA * 2) + kofs);
#pragma unroll
                for (int half = 0; half < 2; half++) {
                    unsigned bh0 = half ? bh[1] : bh[0], bh1 = half ? bh[3] : bh[2];
                    unsigned bl0 = half ? bl[1] : bl[0], bl1 = half ? bl[3] : bl[2];
                    int nt = nt16 * 2 + half;
#pragma unroll
                    for (int mt = 0; mt < 2; mt++) {
                        mma16816(acc[mt][nt], ah[mt], bh0, bh1);
                        mma16816(acc[mt][nt], ah[mt], bl0, bl1);
                        mma16816(acc[mt][nt], al[mt], bh0, bh1);
                    }
                }
            }
        }
        __syncthreads();
        if (s + 2 < 4) load_stage(s + 2);
        asm volatile("cp.async.commit_group;" ::: "memory");
    }

    const int g = lane >> 2, tig = lane & 3;
#pragma unroll
    for (int mt = 0; mt < 2; mt++) {
        int token = tok0 + wm * 32 + mt * 16 + g;
#pragma unroll
        for (int nt = 0; nt < 8; nt++) {
            int col = d0 + wn * 64 + nt * 8 + tig * 2;
            float2 bb = *reinterpret_cast<const float2*>(b1 + col);
#pragma unroll
            for (int rr = 0; rr < 2; rr++) {
                int tk = token + rr * 8;
                float z0 = acc[mt][nt][rr * 2]     + bb.x;
                float z1 = acc[mt][nt][rr * 2 + 1] + bb.y;
                float2 xv = *reinterpret_cast<const float2*>(x + (size_t)tk * Dd + col);
                float2 uv = make_float2(sigmoidf_(z0) * xv.x, sigmoidf_(z1) * xv.y);
                *reinterpret_cast<float2*>(g_u + (size_t)tk * Dd + col) = uv;
            }
        }
    }
}

// ---------------- K4: gate math per token -----------------------------------
__global__ void gates_kernel(const float* __restrict__ mb) {
    int warp = threadIdx.x >> 5;
    int lane = threadIdx.x & 31;
    int token = blockIdx.x * 4 + warp;
    const float* zp = g_zp + (size_t)token * 384;

    float r_a = zp[lane],        r_b = zp[32 + lane];
    float k_a = zp[64 + lane],   k_b = zp[96 + lane];
    float m1a = zp[128 + lane] + mb[lane];
    float m1b = zp[160 + lane] + mb[32 + lane];
    float m2a = zp[192 + lane] + mb[64 + lane];
    float m2b = zp[224 + lane] + mb[96 + lane];

    float sela = softplusf_(m1a), selb = softplusf_(m1b);
    float taua = sigmoidf_(m2a),  taub = sigmoidf_(m2b);
    float ita = expf(taua * logf(sela));
    float itb = expf(taub * logf(selb));
    float ega = expf(-sela * taua);
    float egb = expf(-selb * taub);

    float ss = k_a * k_a + k_b * k_b;
#pragma unroll
    for (int o = 16; o > 0; o >>= 1) ss += __shfl_xor_sync(0xffffffffu, ss, o);
    float inv = 1.f / fmaxf(sqrtf(ss), 1e-12f);

    float* go = g_gates + (size_t)token * 192;
    go[lane]       = r_a;             go[32 + lane]  = r_b;
    go[64 + lane]  = k_a * inv * ita; go[96 + lane]  = k_b * inv * itb;
    go[128 + lane] = ega;             go[160 + lane] = egb;
}

// ---------------- K4b: r~ = r * cumdecay (per chunk) + chunk products -------
__global__ __launch_bounds__(128) void rtil_kernel() {
    int w = blockIdx.x * 4 + (threadIdx.x >> 5);
    int lane = threadIdx.x & 31;
    int c = w & 7;
    int bh = w >> 3;
    int b = bh >> 1, h = bh & 1;
    int m = h * 32 + lane;

    const float* gbase = g_gates + ((size_t)(b * Ll + c * CL)) * 192;
    float* rout = g_rtil + ((size_t)(b * Ll + c * CL)) * Mm + m;

    float P = 1.f;
    float ef[8], rf[8];
#pragma unroll
    for (int i = 0; i < 8; i++) {
        ef[i] = gbase[(size_t)i * 192 + 128 + m];
        rf[i] = gbase[(size_t)i * 192 + m];
    }
    for (int t = 0; t < CL; t++) {
        int j = t & 7;
        P *= ef[j];
        rout[(size_t)t * Mm] = rf[j] * P;
        if (t + 8 < CL) {
            ef[j] = gbase[(size_t)(t + 8) * 192 + 128 + m];
            rf[j] = gbase[(size_t)(t + 8) * 192 + m];
        }
    }
    g_Pc[(b * NC + c) * Mm + m] = P;
}

// ---------------- K5a: chunk-local scans (merged 64-m, no atomics) ----------
// grid (D/64, B, NC), block 64 (2 warps). One thread owns one d-column and
// ALL 64 m-states (32 float2). Output is a single plain store (out memset
// eliminated). Gates (192 floats/step) via per-warp PF-stage cp.async ring.
__global__ __launch_bounds__(64) void scanA_kernel(const float* __restrict__ rw,
                                                   float* __restrict__ out) {
    const int tid = threadIdx.x;
    const int w = tid >> 5, lane = tid & 31;
    const int d = blockIdx.x * 64 + tid;
    const int b = blockIdx.y;
    const int c = blockIdx.z;
    const int t0base = c * CL;

    __shared__ __align__(16) float sg[2][PF][192];

    const float* gb = g_gates + (size_t)b * Ll * 192;
    const unsigned sb0 = (unsigned)__cvta_generic_to_shared(&sg[w][0][lane * 4]);
    const unsigned sb1 = (unsigned)__cvta_generic_to_shared(&sg[w][0][(32 + lane) * 4]);

#pragma unroll
    for (int s = 0; s < PF - 1; s++) {
        const int t = t0base + s;
        const float* src = gb + (size_t)t * 192;
        unsigned o = (unsigned)(t & (PF - 1)) * 192 * 4;
        CPA16(sb0 + o, src + lane * 4);
        if (lane < 16) CPA16(sb1 + o, src + (32 + lane) * 4);
        asm volatile("cp.async.commit_group;" ::: "memory");
    }

    float2 S[32];
#pragma unroll
    for (int p = 0; p < 32; p++) S[p] = make_float2(0.f, 0.f);

    const float* ub = g_u + ((size_t)b * Ll) * Dd + d;
    const float* sb = g_shift + ((size_t)b * Ll) * Dd + d;
    float* ob = out + ((size_t)b * Ll) * Dd + d;
    const float rwd = rw[d];

    float upf[8], spf[8];
#pragma unroll
    for (int i = 0; i < 8; i++) {
        upf[i] = __ldcg(ub + (size_t)(t0base + i) * Dd);
        spf[i] = __ldcg(sb + (size_t)(t0base + i) * Dd);
    }

    for (int tb = 0; tb < CL; tb += 8) {
#pragma unroll
        for (int j = 0; j < 8; j++) {
            const int t = t0base + tb + j;
            asm volatile("cp.async.wait_group 2;" ::: "memory");
            __syncwarp();
            const float* g0 = &sg[w][t & (PF - 1)][0];

            float2 uu = make_float2(upf[j], upf[j]);
            float2 a0 = make_float2(0.f, 0.f), a1 = a0, a2 = a0, a3 = a0;
#pragma unroll
            for (int q = 0; q < 16; q++) {
                float4 r4 = *reinterpret_cast<const float4*>(g0 + q * 4);
                float4 k4 = *reinterpret_cast<const float4*>(g0 + 64 + q * 4);
                float4 e4 = *reinterpret_cast<const float4*>(g0 + 128 + q * 4);
                S[2 * q]     = ffma2(make_float2(e4.x, e4.y), S[2 * q],
                                     fmul2(make_float2(k4.x, k4.y), uu));
                S[2 * q + 1] = ffma2(make_float2(e4.z, e4.w), S[2 * q + 1],
                                     fmul2(make_float2(k4.z, k4.w), uu));
                if (q & 1) {
                    a0 = ffma2(make_float2(r4.x, r4.y), S[2 * q],     a0);
                    a1 = ffma2(make_float2(r4.z, r4.w), S[2 * q + 1], a1);
                } else {
                    a2 = ffma2(make_float2(r4.x, r4.y), S[2 * q],     a2);
                    a3 = ffma2(make_float2(r4.z, r4.w), S[2 * q + 1], a3);
                }
            }
            float sx = (a0.x + a1.x) + (a2.x + a3.x);
            float sy = (a0.y + a1.y) + (a2.y + a3.y);
            float o = OSCALE * (sx + sy) + spf[j] * rwd;
            ob[(size_t)t * Dd] = o;

            const int tn = t + PF - 1;
            if (tn < t0base + CL) {
                const float* src = gb + (size_t)tn * 192;
                unsigned oo = (unsigned)(tn & (PF - 1)) * 192 * 4;
                CPA16(sb0 + oo, src + lane * 4);
                if (lane < 16) CPA16(sb1 + oo, src + (32 + lane) * 4);
            }
            asm volatile("cp.async.commit_group;" ::: "memory");

            if (tb + j + 8 < CL) {
                upf[j] = __ldcg(ub + (size_t)(t + 8) * Dd);
                spf[j] = __ldcg(sb + (size_t)(t + 8) * Dd);
            }
        }
    }

    if (c < NC - 1) {
        float* se = g_Send + ((size_t)(b * NC + c) * Mm) * Dd + d;
#pragma unroll
        for (int p = 0; p < 32; p++) {
            se[(size_t)(2 * p) * Dd]     = S[p].x;
            se[(size_t)(2 * p + 1) * Dd] = S[p].y;
        }
    }
}

// ---------------- K5b: cross-chunk state propagation ------------------------
__global__ __launch_bounds__(64) void phaseB_kernel() {
    const int d = blockIdx.x * 64 + threadIdx.x;
    const int b = blockIdx.y;
    const int h = blockIdx.z;

    float Sin[32];
#pragma unroll
    for (int j = 0; j < 32; j++) Sin[j] = 0.f;

    for (int c = 0; c < NC - 1; c++) {
        const float* se = g_Send + ((size_t)(b * NC + c) * Mm + h * 32) * Dd + d;
        const float* pc = g_Pc + (b * NC + c) * Mm + h * 32;
        float* so = g_Sin + ((size_t)(b * NC + c + 1) * Mm + h * 32) * Dd + d;
#pragma unroll
        for (int j = 0; j < 32; j++) {
            Sin[j] = pc[j] * Sin[j] + se[(size_t)j * Dd];
            so[(size_t)j * Dd] = Sin[j];
        }
    }
}

// ---------------- K5c: correction GEMM out += OSCALE * rtil @ Sin -----------
__global__ __launch_bounds__(256) void phaseC_kernel(float* __restrict__ out) {
    const int idx = blockIdx.y;
    const int b = idx / (NC - 1);
    const int c = 1 + idx % (NC - 1);
    const int tt = blockIdx.x & 3, dt = blockIdx.x >> 2;
    const int t0 = c * CL + tt * 64;
    const int d0 = dt * 128;

    const float* A  = g_rtil + ((size_t)b * Ll + t0) * Mm;        // [64 t][64 k]
    const float* Bm = g_Sin + ((size_t)(b * NC + c) * Mm) * Dd + d0; // [64 k][Dd]

    __shared__ float As[2][16 * 68];
    __shared__ float Bs[2][16 * 132];

    const int tid = threadIdx.x;
    const int tg = tid >> 4, ng = tid & 15;
    const int a_t = tid >> 2, a_k = (tid & 3) * 4;
    const int b_kr = tid >> 4, b_nb = (tid & 15) * 8;

    float2 acc[4][4];
#pragma unroll
    for (int i = 0; i < 4; i++)
#pragma unroll
        for (int j = 0; j < 4; j++) acc[i][j] = make_float2(0.f, 0.f);

    const float* Aptr = A + (size_t)a_t * Mm + a_k;
    const float* Bptr = Bm + (size_t)b_kr * Dd + b_nb;

    float4 av  = *reinterpret_cast<const float4*>(Aptr);
    float4 bv0 = *reinterpret_cast<const float4*>(Bptr);
    float4 bv1 = *reinterpret_cast<const float4*>(Bptr + 4);

    const int NT = 4;   // K=64, BK=16
    for (int kt = 0; kt < NT; ++kt) {
        const int p = kt & 1;
        {
            float* as = As[p] + a_k * 68 + a_t;
            as[0] = av.x; as[68] = av.y; as[2 * 68] = av.z; as[3 * 68] = av.w;
            float* bs = Bs[p] + b_kr * 132 + b_nb;
            bs[0] = bv0.x; bs[1] = bv0.y; bs[2] = bv0.z; bs[3] = bv0.w;
            bs[4] = bv1.x; bs[5] = bv1.y; bs[6] = bv1.z; bs[7] = bv1.w;
        }
        __syncthreads();
        if (kt + 1 < NT) {
            av  = *reinterpret_cast<const float4*>(Aptr + (kt + 1) * 16);
            bv0 = *reinterpret_cast<const float4*>(Bptr + (size_t)(kt + 1) * 16 * Dd);
            bv1 = *reinterpret_cast<const float4*>(Bptr + (size_t)(kt + 1) * 16 * Dd + 4);
        }
#pragma unroll
        for (int k = 0; k < 16; k++) {
            float4 a4  = *reinterpret_cast<const float4*>(As[p] + k * 68 + tg * 4);
            float4 b40 = *reinterpret_cast<const float4*>(Bs[p] + k * 132 + ng * 8);
            float4 b41 = *reinterpret_cast<const float4*>(Bs[p] + k * 132 + ng * 8 + 4);
            float aval[4] = {a4.x, a4.y, a4.z, a4.w};
            float2 bp[4] = {make_float2(b40.x, b40.y), make_float2(b40.z, b40.w),
                            make_float2(b41.x, b41.y), make_float2(b41.z, b41.w)};
#pragma unroll
            for (int i = 0; i < 4; i++) {
                float2 aa = make_float2(aval[i], aval[i]);
#pragma unroll
                for (int j = 0; j < 4; j++) acc[i][j] = ffma2(aa, bp[j], acc[i][j]);
            }
        }
    }
#pragma unroll
    for (int i = 0; i < 4; i++) {
        int token = t0 + tg * 4 + i;
        float* op = out + ((size_t)b * Ll + token) * Dd + d0 + ng * 8;
#pragma unroll
        for (int j = 0; j < 4; j++) {
            float2 cur = *reinterpret_cast<float2*>(op + 2 * j);
            cur.x += OSCALE * acc[i][j].x;
            cur.y += OSCALE * acc[i][j].y;
            *reinterpret_cast<float2*>(op + 2 * j) = cur;
        }
    }
}

// ---------------- launch -----------------------------------------------------
extern "C" void kernel_launch(void* const* d_in, const int* in_sizes, int n_in,
                              void* d_out, int out_size) {
    const float* x        = (const float*)d_in[0];  // (B,L,D)
    const float* conv_w   = (const float*)d_in[1];  // (D,4)
    const float* conv_b   = (const float*)d_in[2];  // (D,)
    const float* in_proj  = (const float*)d_in[3];  // (128,D)
    const float* ch_w0    = (const float*)d_in[4];  // (128,D)
    const float* ch_w1    = (const float*)d_in[5];  // (D,128)
    const float* ch_b1    = (const float*)d_in[6];  // (D,)
    const float* mem_w    = (const float*)d_in[7];  // (128,D)
    const float* mem_b    = (const float*)d_in[8];  // (128,)
    const float* res_w    = (const float*)d_in[9];  // (D,)
    float* out = (float*)d_out;

    static bool attr_set = false;
    if (!attr_set) {
        cudaFuncSetAttribute(mma_proj_kernel,
                             cudaFuncAttributeMaxDynamicSharedMemorySize, SMEM_2STG);
        cudaFuncSetAttribute(ugemm_mma_kernel,
                             cudaFuncAttributeMaxDynamicSharedMemorySize, SMEM_2STG);
        attr_set = true;
    }

    conv_silu_kernel<<<dim3(Dd / 256, Ll / 8, Bb), 256>>>(x, conv_w, conv_b);
    wsplit_kernel<<<dim3(256 * Dd / 256), 256>>>(in_proj, mem_w, ch_w0, ch_w1);
    mma_proj_kernel<<<dim3(BL / 128, 3), 256, SMEM_2STG>>>();
    ugemm_mma_kernel<<<dim3(BL / 128, Dd / 128), 256, SMEM_2STG>>>(x, ch_b1);
    gates_kernel<<<dim3(BL / 4), 128>>>(mem_b);
    rtil_kernel<<<dim3(16), 128>>>();
    scanA_kernel<<<dim3(Dd / 64, Bb, NC), 64>>>(res_w, out);
    phaseB_kernel<<<dim3(Dd / 64, Bb, 2), 64>>>();
    phaseC_kernel<<<dim3(64, Bb * (NC - 1)), 256>>>(out);
}

// round 10
// speedup vs baseline: 3.4657x; 1.0676x over previous
#include <cuda_runtime.h>
#include <cuda_bf16.h>
#include <math.h>

// Problem constants
#define Bb 4
#define Ll 2048
#define Dd 2048
#define Mm 64
#define Rr 128
#define BL (Bb*Ll)
#define OSCALE 0.125f   // 1/sqrt(64)
#define PF 4            // scan gates prefetch stages (power of 2)
#define NC 8            // scan time chunks
#define CL 256          // chunk length

// ---------------- scratch (device globals; no allocation allowed) ----------
__device__ float g_shift[BL*Dd];     // silu(conv(x))  (residual, scan input)
__device__ float g_u[BL*Dd];         // ch * x
__device__ float g_zp[BL*384];       // [token][0..127]=rk, [128..255]=mg(pre-bias)
__device__ float g_gates[BL*192];    // [token][0..63]=r, [64..127]=k_hat, [128..191]=exp(g)

// bf16 splits for tensor-core 3xBF16 GEMMs
__device__ __nv_bfloat16 g_sh_hi[BL*Dd], g_sh_lo[BL*Dd];
__device__ __nv_bfloat16 g_x_hi[BL*Dd],  g_x_lo[BL*Dd];
__device__ __nv_bfloat16 g_b01_hi[256*Dd], g_b01_lo[256*Dd];  // [in_proj;mem_gate]
__device__ __nv_bfloat16 g_b2_hi[128*Dd],  g_b2_lo[128*Dd];   // ch_gate_w0
__device__ __nv_bfloat16 g_w1_hi[Dd*Rr],   g_w1_lo[Dd*Rr];    // ch_gate_w1
__device__ __nv_bfloat16 g_h_hi[BL*Rr],    g_h_lo[BL*Rr];     // h = x @ w0^T

// chunked-scan scratch
__device__ float g_Send[Bb*NC*Mm*Dd];   // local end-state per chunk
__device__ float g_Sin[Bb*NC*Mm*Dd];    // incoming state per chunk (c>=1)
__device__ float g_rtil[BL*Mm];         // r_t * cumdecay_within_chunk
__device__ float g_Pc[Bb*NC*Mm];        // full-chunk decay products

// ---------------- f32x2 packed math helpers --------------------------------
__device__ __forceinline__ float2 ffma2(float2 a, float2 b, float2 c) {
    unsigned long long au = *reinterpret_cast<unsigned long long*>(&a);
    unsigned long long bu = *reinterpret_cast<unsigned long long*>(&b);
    unsigned long long cu = *reinterpret_cast<unsigned long long*>(&c);
    unsigned long long du;
    asm("fma.rn.f32x2 %0, %1, %2, %3;" : "=l"(du) : "l"(au), "l"(bu), "l"(cu));
    return *reinterpret_cast<float2*>(&du);
}
__device__ __forceinline__ float2 fmul2(float2 a, float2 b) {
    unsigned long long au = *reinterpret_cast<unsigned long long*>(&a);
    unsigned long long bu = *reinterpret_cast<unsigned long long*>(&b);
    unsigned long long du;
    asm("mul.rn.f32x2 %0, %1, %2;" : "=l"(du) : "l"(au), "l"(bu));
    return *reinterpret_cast<float2*>(&du);
}
__device__ __forceinline__ float sigmoidf_(float x) { return 1.f / (1.f + expf(-x)); }
__device__ __forceinline__ float softplusf_(float x) {
    return fmaxf(x, 0.f) + log1pf(expf(-fabsf(x)));
}
__device__ __forceinline__ void split_bf16(float v, __nv_bfloat16* hi, __nv_bfloat16* lo) {
    __nv_bfloat16 h = __float2bfloat16_rn(v);
    *hi = h;
    *lo = __float2bfloat16_rn(v - __bfloat162float(h));
}

// ---------------- warp-MMA helpers ------------------------------------------
__device__ __forceinline__ void ldsm4(unsigned& r0, unsigned& r1, unsigned& r2,
                                      unsigned& r3, unsigned addr) {
    asm volatile("ldmatrix.sync.aligned.m8n8.x4.shared.b16 {%0,%1,%2,%3}, [%4];"
                 : "=r"(r0), "=r"(r1), "=r"(r2), "=r"(r3) : "r"(addr));
}
__device__ __forceinline__ void mma16816(float* c, const unsigned* a,
                                         unsigned b0, unsigned b1) {
    asm volatile(
        "mma.sync.aligned.m16n8k16.row.col.f32.bf16.bf16.f32 "
        "{%0,%1,%2,%3}, {%4,%5,%6,%7}, {%8,%9}, {%0,%1,%2,%3};"
        : "+f"(c[0]), "+f"(c[1]), "+f"(c[2]), "+f"(c[3])
        : "r"(a[0]), "r"(a[1]), "r"(a[2]), "r"(a[3]), "r"(b0), "r"(b1));
}
#define CP16(dst, src) asm volatile("cp.async.cg.shared.global [%0], [%1], 16;" :: "r"(dst), "l"(src))
#define CPA16(dst, src) asm volatile("cp.async.ca.shared.global [%0], [%1], 16;" :: "r"(dst), "l"(src))

// ---------------- K1: causal depthwise conv (W=4) + SiLU + bf16 splits -----
__global__ void conv_silu_kernel(const float* __restrict__ x,
                                 const float* __restrict__ cw,
                                 const float* __restrict__ cb) {
    int d  = blockIdx.x * 256 + threadIdx.x;
    int t0 = blockIdx.y * 8;
    int b  = blockIdx.z;
    float4 w = *reinterpret_cast<const float4*>(cw + d * 4);
    float bias = cb[d];
    size_t base = ((size_t)b * Ll) * Dd + d;
    const float* xb = x + base;
    float* sp = g_shift + base;
    float xm3 = (t0 - 3 >= 0) ? xb[(size_t)(t0 - 3) * Dd] : 0.f;
    float xm2 = (t0 - 2 >= 0) ? xb[(size_t)(t0 - 2) * Dd] : 0.f;
    float xm1 = (t0 - 1 >= 0) ? xb[(size_t)(t0 - 1) * Dd] : 0.f;
#pragma unroll
    for (int i = 0; i < 8; i++) {
        int t = t0 + i;
        size_t o = base + (size_t)t * Dd;
        float xt = xb[(size_t)t * Dd];
        float y = xm3 * w.x + xm2 * w.y + xm1 * w.z + xt * w.w + bias;
        float s = y * sigmoidf_(y);
        sp[(size_t)t * Dd] = s;
        split_bf16(s,  &g_sh_hi[o], &g_sh_lo[o]);
        split_bf16(xt, &g_x_hi[o],  &g_x_lo[o]);
        xm3 = xm2; xm2 = xm1; xm1 = xt;
    }
}

// ---------------- K1b: weight splits ----------------------------------------
__global__ void wsplit_kernel(const float* __restrict__ w_in,
                              const float* __restrict__ w_mg,
                              const float* __restrict__ w_ch,
                              const float* __restrict__ w1) {
    int i = blockIdx.x * 256 + threadIdx.x;   // i < 256*2048
    float v = (i < 128 * Dd) ? w_in[i] : w_mg[i - 128 * Dd];
    split_bf16(v, &g_b01_hi[i], &g_b01_lo[i]);
    if (i < 128 * Dd) {
        split_bf16(w_ch[i], &g_b2_hi[i], &g_b2_lo[i]);
        split_bf16(w1[i],   &g_w1_hi[i], &g_w1_lo[i]);
    }
}

// ---------------- K2: tensor-core projections via mma.sync (3xBF16) --------
// 64-token tiles: 384 CTAs so every SM holds 2 co-resident CTAs.
#define SA 40                          // padded row stride (bf16 elems)
#define PST (384*SA)                   // stage elems (Ah64,Al64,Bh128,Bl128)
#define POFF_AL (64*SA)
#define POFF_BH (128*SA)
#define POFF_BL (256*SA)
#define PSMEM (2*PST*2)                // 61440 B

__global__ __launch_bounds__(256, 2) void mma_proj_kernel() {
    extern __shared__ __align__(128) __nv_bfloat16 sm[];
    const int tid = threadIdx.x;
    const int lane = tid & 31, wid = tid >> 5;
    const int wm = wid & 1, wn = wid >> 1;     // warp tile 32 tok x 32 n
    const int y = blockIdx.y;
    const int tok0 = blockIdx.x * 64;

    const __nv_bfloat16* Ah = (y == 2) ? g_x_hi : g_sh_hi;
    const __nv_bfloat16* Al = (y == 2) ? g_x_lo : g_sh_lo;
    const __nv_bfloat16* Bh = (y == 2) ? g_b2_hi : g_b01_hi + (size_t)y * 128 * Dd;
    const __nv_bfloat16* Bl = (y == 2) ? g_b2_lo : g_b01_lo + (size_t)y * 128 * Dd;

    const unsigned sbase = (unsigned)__cvta_generic_to_shared(sm);

    auto load_stage = [&](int s) {
        const int kb = s * 32;
        const unsigned st = sbase + (s & 1) * (PST * 2);
#pragma unroll
        for (int j = 0; j < 6; j++) {
            int i = tid + j * 256;
            const __nv_bfloat16* src;
            unsigned dst;
            if (i < 512) {                       // A arrays: 2 x 64 rows x 4 chunks
                int arr = i >> 8, rem = i & 255;
                int row = rem >> 2, c = rem & 3;
                src = (arr ? Al : Ah) + (size_t)(tok0 + row) * Dd + kb + c * 8;
                dst = st + (arr ? POFF_AL * 2 : 0) + (row * SA + c * 8) * 2;
            } else {                             // B arrays: 2 x 128 rows x 4 chunks
                int i2 = i - 512;
                int arr = i2 >> 9, rem = i2 & 511;
                int row = rem >> 2, c = rem & 3;
                src = (arr ? Bl : Bh) + (size_t)row * Dd + kb + c * 8;
                dst = st + (arr ? POFF_BL * 2 : POFF_BH * 2) + (row * SA + c * 8) * 2;
            }
            CP16(dst, src);
        }
    };

    load_stage(0);
    asm volatile("cp.async.commit_group;" ::: "memory");
    load_stage(1);
    asm volatile("cp.async.commit_group;" ::: "memory");

    float acc[2][4][4];
#pragma unroll
    for (int mt = 0; mt < 2; mt++)
#pragma unroll
        for (int nt = 0; nt < 4; nt++)
#pragma unroll
            for (int q = 0; q < 4; q++) acc[mt][nt][q] = 0.f;

    const int lr = lane & 15, lc = lane >> 4;

    for (int s = 0; s < 64; s++) {
        asm volatile("cp.async.wait_group 1;" ::: "memory");
        __syncthreads();

        const unsigned st = sbase + (s & 1) * (PST * 2);
#pragma unroll
        for (int kk = 0; kk < 2; kk++) {
            const unsigned kofs = (kk * 16 + lc * 8) * 2;
            unsigned ah[2][4], al[2][4];
#pragma unroll
            for (int mt = 0; mt < 2; mt++) {
                int row = wm * 32 + mt * 16 + lr;
                ldsm4(ah[mt][0], ah[mt][1], ah[mt][2], ah[mt][3],
                      st + row * (SA * 2) + kofs);
                ldsm4(al[mt][0], al[mt][1], al[mt][2], al[mt][3],
                      st + POFF_AL * 2 + row * (SA * 2) + kofs);
            }
#pragma unroll
            for (int nt16 = 0; nt16 < 2; nt16++) {
                int nrow = wn * 32 + nt16 * 16 + lr;
                unsigned bh[4], bl[4];
                ldsm4(bh[0], bh[1], bh[2], bh[3],
                      st + POFF_BH * 2 + nrow * (SA * 2) + kofs);
                ldsm4(bl[0], bl[1], bl[2], bl[3],
                      st + POFF_BL * 2 + nrow * (SA * 2) + kofs);
#pragma unroll
                for (int half = 0; half < 2; half++) {
                    unsigned bh0 = half ? bh[1] : bh[0], bh1 = half ? bh[3] : bh[2];
                    unsigned bl0 = half ? bl[1] : bl[0], bl1 = half ? bl[3] : bl[2];
                    int nt = nt16 * 2 + half;
#pragma unroll
                    for (int mt = 0; mt < 2; mt++) {
                        mma16816(acc[mt][nt], ah[mt], bh0, bh1);
                        mma16816(acc[mt][nt], ah[mt], bl0, bl1);
                        mma16816(acc[mt][nt], al[mt], bh0, bh1);
                    }
                }
            }
        }
        __syncthreads();
        if (s + 2 < 64) load_stage(s + 2);
        asm volatile("cp.async.commit_group;" ::: "memory");
    }

    const int g = lane >> 2, tig = lane & 3;
    if (y < 2) {
        const int zoff = y * 128;
#pragma unroll
        for (int mt = 0; mt < 2; mt++) {
            int token = tok0 + wm * 32 + mt * 16 + g;
#pragma unroll
            for (int nt = 0; nt < 4; nt++) {
                int col = zoff + wn * 32 + nt * 8 + tig * 2;
                *reinterpret_cast<float2*>(g_zp + (size_t)token * 384 + col) =
                    make_float2(acc[mt][nt][0], acc[mt][nt][1]);
                *reinterpret_cast<float2*>(g_zp + (size_t)(token + 8) * 384 + col) =
                    make_float2(acc[mt][nt][2], acc[mt][nt][3]);
            }
        }
    } else {
#pragma unroll
        for (int mt = 0; mt < 2; mt++) {
            int token = tok0 + wm * 32 + mt * 16 + g;
#pragma unroll
            for (int nt = 0; nt < 4; nt++) {
                int col = wn * 32 + nt * 8 + tig * 2;
                size_t o0 = (size_t)token * Rr + col;
                size_t o1 = (size_t)(token + 8) * Rr + col;
                split_bf16(acc[mt][nt][0], &g_h_hi[o0],     &g_h_lo[o0]);
                split_bf16(acc[mt][nt][1], &g_h_hi[o0 + 1], &g_h_lo[o0 + 1]);
                split_bf16(acc[mt][nt][2], &g_h_hi[o1],     &g_h_lo[o1]);
                split_bf16(acc[mt][nt][3], &g_h_hi[o1 + 1], &g_h_lo[o1 + 1]);
            }
        }
    }
}

// ---------------- K3: u = sigmoid(h @ w1^T + b1) * x  (tensor core) --------
// Single-shot: full K=128 operands preloaded into smem (102KB), no pipeline.
// Tile 128 tok x 64 d; 2 CTAs/SM interleave load-wait with compute.
#define SA2 136                        // padded row stride for K=128 rows
#define UOFF_AL (128*SA2)
#define UOFF_BH (256*SA2)
#define UOFF_BL (320*SA2)
#define USMEM (384*SA2*2)              // 104448 B

__global__ __launch_bounds__(256, 2) void ugemm_mma_kernel(
    const float* __restrict__ x, const float* __restrict__ b1) {
    extern __shared__ __align__(128) __nv_bfloat16 sm[];
    const int tid = threadIdx.x;
    const int lane = tid & 31, wid = tid >> 5;
    const int wm = wid & 3, wn = wid >> 2;     // warp tile 32 tok x 32 d
    const int tok0 = blockIdx.x * 128;
    const int d0   = blockIdx.y * 64;

    const unsigned sbase = (unsigned)__cvta_generic_to_shared(sm);

    // one-shot load: A = h_hi/h_lo (128 rows x 16 chunks), B = w1_hi/lo (64 rows)
#pragma unroll
    for (int j = 0; j < 24; j++) {
        int i = tid + j * 256;
        const __nv_bfloat16* src;
        unsigned dst;
        if (i < 4096) {
            int arr = i >> 11, rem = i & 2047;
            int row = rem >> 4, c = rem & 15;
            src = (arr ? g_h_lo : g_h_hi) + (size_t)(tok0 + row) * Rr + c * 8;
            dst = sbase + (arr ? UOFF_AL * 2 : 0) + (row * SA2 + c * 8) * 2;
        } else {
            int i2 = i - 4096;
            int arr = i2 >> 10, rem = i2 & 1023;
            int row = rem >> 4, c = rem & 15;
            src = (arr ? g_w1_lo : g_w1_hi) + (size_t)(d0 + row) * Rr + c * 8;
            dst = sbase + (arr ? UOFF_BL * 2 : UOFF_BH * 2) + (row * SA2 + c * 8) * 2;
        }
        CP16(dst, src);
    }
    asm volatile("cp.async.commit_group;" ::: "memory");
    asm volatile("cp.async.wait_group 0;" ::: "memory");
    __syncthreads();

    float acc[2][4][4];
#pragma unroll
    for (int mt = 0; mt < 2; mt++)
#pragma unroll
        for (int nt = 0; nt < 4; nt++)
#pragma unroll
            for (int q = 0; q < 4; q++) acc[mt][nt][q] = 0.f;

    const int lr = lane & 15, lc = lane >> 4;

#pragma unroll
    for (int kk = 0; kk < 8; kk++) {
        const unsigned kofs = (kk * 16 + lc * 8) * 2;
        unsigned ah[2][4], al[2][4];
#pragma unroll
        for (int mt = 0; mt < 2; mt++) {
            int row = wm * 32 + mt * 16 + lr;
            ldsm4(ah[mt][0], ah[mt][1], ah[mt][2], ah[mt][3],
                  sbase + row * (SA2 * 2) + kofs);
            ldsm4(al[mt][0], al[mt][1], al[mt][2], al[mt][3],
                  sbase + UOFF_AL * 2 + row * (SA2 * 2) + kofs);
        }
#pragma unroll
        for (int nt16 = 0; nt16 < 2; nt16++) {
            int nrow = wn * 32 + nt16 * 16 + lr;
            unsigned bh[4], bl[4];
            ldsm4(bh[0], bh[1], bh[2], bh[3],
                  sbase + UOFF_BH * 2 + nrow * (SA2 * 2) + kofs);
            ldsm4(bl[0], bl[1], bl[2], bl[3],
                  sbase + UOFF_BL * 2 + nrow * (SA2 * 2) + kofs);
#pragma unroll
            for (int half = 0; half < 2; half++) {
                unsigned bh0 = half ? bh[1] : bh[0], bh1 = half ? bh[3] : bh[2];
                unsigned bl0 = half ? bl[1] : bl[0], bl1 = half ? bl[3] : bl[2];
                int nt = nt16 * 2 + half;
#pragma unroll
                for (int mt = 0; mt < 2; mt++) {
                    mma16816(acc[mt][nt], ah[mt], bh0, bh1);
                    mma16816(acc[mt][nt], ah[mt], bl0, bl1);
                    mma16816(acc[mt][nt], al[mt], bh0, bh1);
                }
            }
        }
    }

    const int g = lane >> 2, tig = lane & 3;
#pragma unroll
    for (int mt = 0; mt < 2; mt++) {
        int token = tok0 + wm * 32 + mt * 16 + g;
#pragma unroll
        for (int nt = 0; nt < 4; nt++) {
            int col = d0 + wn * 32 + nt * 8 + tig * 2;
            float2 bb = *reinterpret_cast<const float2*>(b1 + col);
#pragma unroll
            for (int rr = 0; rr < 2; rr++) {
                int tk = token + rr * 8;
                float z0 = acc[mt][nt][rr * 2]     + bb.x;
                float z1 = acc[mt][nt][rr * 2 + 1] + bb.y;
                float2 xv = *reinterpret_cast<const float2*>(x + (size_t)tk * Dd + col);
                float2 uv = make_float2(sigmoidf_(z0) * xv.x, sigmoidf_(z1) * xv.y);
                *reinterpret_cast<float2*>(g_u + (size_t)tk * Dd + col) = uv;
            }
        }
    }
}

// ---------------- K4: gate math per token -----------------------------------
__global__ void gates_kernel(const float* __restrict__ mb) {
    int warp = threadIdx.x >> 5;
    int lane = threadIdx.x & 31;
    int token = blockIdx.x * 4 + warp;
    const float* zp = g_zp + (size_t)token * 384;

    float r_a = zp[lane],        r_b = zp[32 + lane];
    float k_a = zp[64 + lane],   k_b = zp[96 + lane];
    float m1a = zp[128 + lane] + mb[lane];
    float m1b = zp[160 + lane] + mb[32 + lane];
    float m2a = zp[192 + lane] + mb[64 + lane];
    float m2b = zp[224 + lane] + mb[96 + lane];

    float sela = softplusf_(m1a), selb = softplusf_(m1b);
    float taua = sigmoidf_(m2a),  taub = sigmoidf_(m2b);
    float ita = expf(taua * logf(sela));
    float itb = expf(taub * logf(selb));
    float ega = expf(-sela * taua);
    float egb = expf(-selb * taub);

    float ss = k_a * k_a + k_b * k_b;
#pragma unroll
    for (int o = 16; o > 0; o >>= 1) ss += __shfl_xor_sync(0xffffffffu, ss, o);
    float inv = 1.f / fmaxf(sqrtf(ss), 1e-12f);

    float* go = g_gates + (size_t)token * 192;
    go[lane]       = r_a;             go[32 + lane]  = r_b;
    go[64 + lane]  = k_a * inv * ita; go[96 + lane]  = k_b * inv * itb;
    go[128 + lane] = ega;             go[160 + lane] = egb;
}

// ---------------- K4b: r~ = r * cumdecay (per chunk) + chunk products -------
__global__ __launch_bounds__(128) void rtil_kernel() {
    int w = blockIdx.x * 4 + (threadIdx.x >> 5);
    int lane = threadIdx.x & 31;
    int c = w & 7;
    int bh = w >> 3;
    int b = bh >> 1, h = bh & 1;
    int m = h * 32 + lane;

    const float* gbase = g_gates + ((size_t)(b * Ll + c * CL)) * 192;
    float* rout = g_rtil + ((size_t)(b * Ll + c * CL)) * Mm + m;

    float P = 1.f;
    float ef[8], rf[8];
#pragma unroll
    for (int i = 0; i < 8; i++) {
        ef[i] = gbase[(size_t)i * 192 + 128 + m];
        rf[i] = gbase[(size_t)i * 192 + m];
    }
    for (int t = 0; t < CL; t++) {
        int j = t & 7;
        P *= ef[j];
        rout[(size_t)t * Mm] = rf[j] * P;
        if (t + 8 < CL) {
            ef[j] = gbase[(size_t)(t + 8) * 192 + 128 + m];
            rf[j] = gbase[(size_t)(t + 8) * 192 + m];
        }
    }
    g_Pc[(b * NC + c) * Mm + m] = P;
}

// ---------------- K5a: chunk-local scans (merged 64-m, no atomics) ----------
__global__ __launch_bounds__(64) void scanA_kernel(const float* __restrict__ rw,
                                                   float* __restrict__ out) {
    const int tid = threadIdx.x;
    const int w = tid >> 5, lane = tid & 31;
    const int d = blockIdx.x * 64 + tid;
    const int b = blockIdx.y;
    const int c = blockIdx.z;
    const int t0base = c * CL;

    __shared__ __align__(16) float sg[2][PF][192];

    const float* gb = g_gates + (size_t)b * Ll * 192;
    const unsigned sb0 = (unsigned)__cvta_generic_to_shared(&sg[w][0][lane * 4]);
    const unsigned sb1 = (unsigned)__cvta_generic_to_shared(&sg[w][0][(32 + lane) * 4]);

#pragma unroll
    for (int s = 0; s < PF - 1; s++) {
        const int t = t0base + s;
        const float* src = gb + (size_t)t * 192;
        unsigned o = (unsigned)(t & (PF - 1)) * 192 * 4;
        CPA16(sb0 + o, src + lane * 4);
        if (lane < 16) CPA16(sb1 + o, src + (32 + lane) * 4);
        asm volatile("cp.async.commit_group;" ::: "memory");
    }

    float2 S[32];
#pragma unroll
    for (int p = 0; p < 32; p++) S[p] = make_float2(0.f, 0.f);

    const float* ub = g_u + ((size_t)b * Ll) * Dd + d;
    const float* sb = g_shift + ((size_t)b * Ll) * Dd + d;
    float* ob = out + ((size_t)b * Ll) * Dd + d;
    const float rwd = rw[d];

    float upf[8], spf[8];
#pragma unroll
    for (int i = 0; i < 8; i++) {
        upf[i] = __ldcg(ub + (size_t)(t0base + i) * Dd);
        spf[i] = __ldcg(sb + (size_t)(t0base + i) * Dd);
    }

    for (int tb = 0; tb < CL; tb += 8) {
#pragma unroll
        for (int j = 0; j < 8; j++) {
            const int t = t0base + tb + j;
            asm volatile("cp.async.wait_group 2;" ::: "memory");
            __syncwarp();
            const float* g0 = &sg[w][t & (PF - 1)][0];

            float2 uu = make_float2(upf[j], upf[j]);
            float2 a0 = make_float2(0.f, 0.f), a1 = a0, a2 = a0, a3 = a0;
#pragma unroll
            for (int q = 0; q < 16; q++) {
                float4 r4 = *reinterpret_cast<const float4*>(g0 + q * 4);
                float4 k4 = *reinterpret_cast<const float4*>(g0 + 64 + q * 4);
                float4 e4 = *reinterpret_cast<const float4*>(g0 + 128 + q * 4);
                S[2 * q]     = ffma2(make_float2(e4.x, e4.y), S[2 * q],
                                     fmul2(make_float2(k4.x, k4.y), uu));
                S[2 * q + 1] = ffma2(make_float2(e4.z, e4.w), S[2 * q + 1],
                                     fmul2(make_float2(k4.z, k4.w), uu));
                if (q & 1) {
                    a0 = ffma2(make_float2(r4.x, r4.y), S[2 * q],     a0);
                    a1 = ffma2(make_float2(r4.z, r4.w), S[2 * q + 1], a1);
                } else {
                    a2 = ffma2(make_float2(r4.x, r4.y), S[2 * q],     a2);
                    a3 = ffma2(make_float2(r4.z, r4.w), S[2 * q + 1], a3);
                }
            }
            float sx = (a0.x + a1.x) + (a2.x + a3.x);
            float sy = (a0.y + a1.y) + (a2.y + a3.y);
            float o = OSCALE * (sx + sy) + spf[j] * rwd;
            ob[(size_t)t * Dd] = o;

            const int tn = t + PF - 1;
            if (tn < t0base + CL) {
                const float* src = gb + (size_t)tn * 192;
                unsigned oo = (unsigned)(tn & (PF - 1)) * 192 * 4;
                CPA16(sb0 + oo, src + lane * 4);
                if (lane < 16) CPA16(sb1 + oo, src + (32 + lane) * 4);
            }
            asm volatile("cp.async.commit_group;" ::: "memory");

            if (tb + j + 8 < CL) {
                upf[j] = __ldcg(ub + (size_t)(t + 8) * Dd);
                spf[j] = __ldcg(sb + (size_t)(t + 8) * Dd);
            }
        }
    }

    if (c < NC - 1) {
        float* se = g_Send + ((size_t)(b * NC + c) * Mm) * Dd + d;
#pragma unroll
        for (int p = 0; p < 32; p++) {
            se[(size_t)(2 * p) * Dd]     = S[p].x;
            se[(size_t)(2 * p + 1) * Dd] = S[p].y;
        }
    }
}

// ---------------- K5b: cross-chunk state propagation ------------------------
__global__ __launch_bounds__(64) void phaseB_kernel() {
    const int d = blockIdx.x * 64 + threadIdx.x;
    const int b = blockIdx.y;
    const int h = blockIdx.z;

    float Sin[32];
#pragma unroll
    for (int j = 0; j < 32; j++) Sin[j] = 0.f;

    for (int c = 0; c < NC - 1; c++) {
        const float* se = g_Send + ((size_t)(b * NC + c) * Mm + h * 32) * Dd + d;
        const float* pc = g_Pc + (b * NC + c) * Mm + h * 32;
        float* so = g_Sin + ((size_t)(b * NC + c + 1) * Mm + h * 32) * Dd + d;
#pragma unroll
        for (int j = 0; j < 32; j++) {
            Sin[j] = pc[j] * Sin[j] + se[(size_t)j * Dd];
            so[(size_t)j * Dd] = Sin[j];
        }
    }
}

// ---------------- K5c: correction GEMM out += OSCALE * rtil @ Sin -----------
__global__ __launch_bounds__(256) void phaseC_kernel(float* __restrict__ out) {
    const int idx = blockIdx.y;
    const int b = idx / (NC - 1);
    const int c = 1 + idx % (NC - 1);
    const int tt = blockIdx.x & 3, dt = blockIdx.x >> 2;
    const int t0 = c * CL + tt * 64;
    const int d0 = dt * 128;

    const float* A  = g_rtil + ((size_t)b * Ll + t0) * Mm;        // [64 t][64 k]
    const float* Bm = g_Sin + ((size_t)(b * NC + c) * Mm) * Dd + d0; // [64 k][Dd]

    __shared__ float As[2][16 * 68];
    __shared__ float Bs[2][16 * 132];

    const int tid = threadIdx.x;
    const int tg = tid >> 4, ng = tid & 15;
    const int a_t = tid >> 2, a_k = (tid & 3) * 4;
    const int b_kr = tid >> 4, b_nb = (tid & 15) * 8;

    float2 acc[4][4];
#pragma unroll
    for (int i = 0; i < 4; i++)
#pragma unroll
        for (int j = 0; j < 4; j++) acc[i][j] = make_float2(0.f, 0.f);

    const float* Aptr = A + (size_t)a_t * Mm + a_k;
    const float* Bptr = Bm + (size_t)b_kr * Dd + b_nb;

    float4 av  = *reinterpret_cast<const float4*>(Aptr);
    float4 bv0 = *reinterpret_cast<const float4*>(Bptr);
    float4 bv1 = *reinterpret_cast<const float4*>(Bptr + 4);

    const int NT = 4;   // K=64, BK=16
    for (int kt = 0; kt < NT; ++kt) {
        const int p = kt & 1;
        {
            float* as = As[p] + a_k * 68 + a_t;
            as[0] = av.x; as[68] = av.y; as[2 * 68] = av.z; as[3 * 68] = av.w;
            float* bs = Bs[p] + b_kr * 132 + b_nb;
            bs[0] = bv0.x; bs[1] = bv0.y; bs[2] = bv0.z; bs[3] = bv0.w;
            bs[4] = bv1.x; bs[5] = bv1.y; bs[6] = bv1.z; bs[7] = bv1.w;
        }
        __syncthreads();
        if (kt + 1 < NT) {
            av  = *reinterpret_cast<const float4*>(Aptr + (kt + 1) * 16);
            bv0 = *reinterpret_cast<const float4*>(Bptr + (size_t)(kt + 1) * 16 * Dd);
            bv1 = *reinterpret_cast<const float4*>(Bptr + (size_t)(kt + 1) * 16 * Dd + 4);
        }
#pragma unroll
        for (int k = 0; k < 16; k++) {
            float4 a4  = *reinterpret_cast<const float4*>(As[p] + k * 68 + tg * 4);
            float4 b40 = *reinterpret_cast<const float4*>(Bs[p] + k * 132 + ng * 8);
            float4 b41 = *reinterpret_cast<const float4*>(Bs[p] + k * 132 + ng * 8 + 4);
            float aval[4] = {a4.x, a4.y, a4.z, a4.w};
            float2 bp[4] = {make_float2(b40.x, b40.y), make_float2(b40.z, b40.w),
                            make_float2(b41.x, b41.y), make_float2(b41.z, b41.w)};
#pragma unroll
            for (int i = 0; i < 4; i++) {
                float2 aa = make_float2(aval[i], aval[i]);
#pragma unroll
                for (int j = 0; j < 4; j++) acc[i][j] = ffma2(aa, bp[j], acc[i][j]);
            }
        }
    }
#pragma unroll
    for (int i = 0; i < 4; i++) {
        int token = t0 + tg * 4 + i;
        float* op = out + ((size_t)b * Ll + token) * Dd + d0 + ng * 8;
#pragma unroll
        for (int j = 0; j < 4; j++) {
            float2 cur = *reinterpret_cast<float2*>(op + 2 * j);
            cur.x += OSCALE * acc[i][j].x;
            cur.y += OSCALE * acc[i][j].y;
            *reinterpret_cast<float2*>(op + 2 * j) = cur;
        }
    }
}

// ---------------- launch -----------------------------------------------------
extern "C" void kernel_launch(void* const* d_in, const int* in_sizes, int n_in,
                              void* d_out, int out_size) {
    const float* x        = (const float*)d_in[0];  // (B,L,D)
    const float* conv_w   = (const float*)d_in[1];  // (D,4)
    const float* conv_b   = (const float*)d_in[2];  // (D,)
    const float* in_proj  = (const float*)d_in[3];  // (128,D)
    const float* ch_w0    = (const float*)d_in[4];  // (128,D)
    const float* ch_w1    = (const float*)d_in[5];  // (D,128)
    const float* ch_b1    = (const float*)d_in[6];  // (D,)
    const float* mem_w    = (const float*)d_in[7];  // (128,D)
    const float* mem_b    = (const float*)d_in[8];  // (128,)
    const float* res_w    = (const float*)d_in[9];  // (D,)
    float* out = (float*)d_out;

    static bool attr_set = false;
    if (!attr_set) {
        cudaFuncSetAttribute(mma_proj_kernel,
                             cudaFuncAttributeMaxDynamicSharedMemorySize, PSMEM);
        cudaFuncSetAttribute(ugemm_mma_kernel,
                             cudaFuncAttributeMaxDynamicSharedMemorySize, USMEM);
        attr_set = true;
    }

    conv_silu_kernel<<<dim3(Dd / 256, Ll / 8, Bb), 256>>>(x, conv_w, conv_b);
    wsplit_kernel<<<dim3(256 * Dd / 256), 256>>>(in_proj, mem_w, ch_w0, ch_w1);
    mma_proj_kernel<<<dim3(BL / 64, 3), 256, PSMEM>>>();
    ugemm_mma_kernel<<<dim3(BL / 128, Dd / 64), 256, USMEM>>>(x, ch_b1);
    gates_kernel<<<dim3(BL / 4), 128>>>(mem_b);
    rtil_kernel<<<dim3(16), 128>>>();
    scanA_kernel<<<dim3(Dd / 64, Bb, NC), 64>>>(res_w, out);
    phaseB_kernel<<<dim3(Dd / 64, Bb, 2), 64>>>();
    phaseC_kernel<<<dim3(64, Bb * (NC - 1)), 256>>>(out);
}

// round 11
// speedup vs baseline: 3.5767x; 1.0320x over previous
#include <cuda_runtime.h>
#include <cuda_bf16.h>
#include <math.h>

// Problem constants
#define Bb 4
#define Ll 2048
#define Dd 2048
#define Mm 64
#define Rr 128
#define BL (Bb*Ll)
#define OSCALE 0.125f   // 1/sqrt(64)
#define PF 4            // scan gates prefetch stages (power of 2)
#define NC 8            // scan time chunks
#define CL 256          // chunk length

// ---------------- scratch (device globals; no allocation allowed) ----------
__device__ float g_shift[BL*Dd];     // silu(conv(x))  (residual, scan input)
__device__ float g_u[BL*Dd];         // ch * x
__device__ float g_zp[BL*384];       // [token][0..127]=rk, [128..255]=mg(pre-bias)
__device__ float g_gates[BL*192];    // [token][0..63]=r, [64..127]=k_hat, [128..191]=exp(g)

// bf16 splits for tensor-core 3xBF16 GEMMs
__device__ __nv_bfloat16 g_sh_hi[BL*Dd], g_sh_lo[BL*Dd];
__device__ __nv_bfloat16 g_x_hi[BL*Dd],  g_x_lo[BL*Dd];
__device__ __nv_bfloat16 g_b01_hi[256*Dd], g_b01_lo[256*Dd];  // [in_proj;mem_gate]
__device__ __nv_bfloat16 g_b2_hi[128*Dd],  g_b2_lo[128*Dd];   // ch_gate_w0
__device__ __nv_bfloat16 g_w1_hi[Dd*Rr],   g_w1_lo[Dd*Rr];    // ch_gate_w1
__device__ __nv_bfloat16 g_h_hi[BL*Rr],    g_h_lo[BL*Rr];     // h = x @ w0^T

// chunked-scan scratch
__device__ float g_Send[Bb*NC*Mm*Dd];   // local end-state per chunk
__device__ float g_Sin[Bb*NC*Mm*Dd];    // incoming state per chunk (c>=1)
__device__ float g_rtil[BL*Mm];         // r_t * cumdecay_within_chunk
__device__ float g_Pc[Bb*NC*Mm];        // full-chunk decay products

// ---------------- f32x2 packed math helpers --------------------------------
__device__ __forceinline__ float2 ffma2(float2 a, float2 b, float2 c) {
    unsigned long long au = *reinterpret_cast<unsigned long long*>(&a);
    unsigned long long bu = *reinterpret_cast<unsigned long long*>(&b);
    unsigned long long cu = *reinterpret_cast<unsigned long long*>(&c);
    unsigned long long du;
    asm("fma.rn.f32x2 %0, %1, %2, %3;" : "=l"(du) : "l"(au), "l"(bu), "l"(cu));
    return *reinterpret_cast<float2*>(&du);
}
__device__ __forceinline__ float2 fmul2(float2 a, float2 b) {
    unsigned long long au = *reinterpret_cast<unsigned long long*>(&a);
    unsigned long long bu = *reinterpret_cast<unsigned long long*>(&b);
    unsigned long long du;
    asm("mul.rn.f32x2 %0, %1, %2;" : "=l"(du) : "l"(au), "l"(bu));
    return *reinterpret_cast<float2*>(&du);
}
__device__ __forceinline__ float sigmoidf_(float x) { return 1.f / (1.f + expf(-x)); }
__device__ __forceinline__ float softplusf_(float x) {
    return fmaxf(x, 0.f) + log1pf(expf(-fabsf(x)));
}
__device__ __forceinline__ void split_bf16(float v, __nv_bfloat16* hi, __nv_bfloat16* lo) {
    __nv_bfloat16 h = __float2bfloat16_rn(v);
    *hi = h;
    *lo = __float2bfloat16_rn(v - __bfloat162float(h));
}

// ---------------- warp-MMA helpers ------------------------------------------
__device__ __forceinline__ void ldsm4(unsigned& r0, unsigned& r1, unsigned& r2,
                                      unsigned& r3, unsigned addr) {
    asm volatile("ldmatrix.sync.aligned.m8n8.x4.shared.b16 {%0,%1,%2,%3}, [%4];"
                 : "=r"(r0), "=r"(r1), "=r"(r2), "=r"(r3) : "r"(addr));
}
__device__ __forceinline__ void mma16816(float* c, const unsigned* a,
                                         unsigned b0, unsigned b1) {
    asm volatile(
        "mma.sync.aligned.m16n8k16.row.col.f32.bf16.bf16.f32 "
        "{%0,%1,%2,%3}, {%4,%5,%6,%7}, {%8,%9}, {%0,%1,%2,%3};"
        : "+f"(c[0]), "+f"(c[1]), "+f"(c[2]), "+f"(c[3])
        : "r"(a[0]), "r"(a[1]), "r"(a[2]), "r"(a[3]), "r"(b0), "r"(b1));
}
#define CP16(dst, src) asm volatile("cp.async.cg.shared.global [%0], [%1], 16;" :: "r"(dst), "l"(src))
#define CPA16(dst, src) asm volatile("cp.async.ca.shared.global [%0], [%1], 16;" :: "r"(dst), "l"(src))

// ---------------- K1: causal depthwise conv (W=4) + SiLU + bf16 splits -----
__global__ void conv_silu_kernel(const float* __restrict__ x,
                                 const float* __restrict__ cw,
                                 const float* __restrict__ cb) {
    int d  = blockIdx.x * 256 + threadIdx.x;
    int t0 = blockIdx.y * 8;
    int b  = blockIdx.z;
    float4 w = *reinterpret_cast<const float4*>(cw + d * 4);
    float bias = cb[d];
    size_t base = ((size_t)b * Ll) * Dd + d;
    const float* xb = x + base;
    float* sp = g_shift + base;
    float xm3 = (t0 - 3 >= 0) ? xb[(size_t)(t0 - 3) * Dd] : 0.f;
    float xm2 = (t0 - 2 >= 0) ? xb[(size_t)(t0 - 2) * Dd] : 0.f;
    float xm1 = (t0 - 1 >= 0) ? xb[(size_t)(t0 - 1) * Dd] : 0.f;
#pragma unroll
    for (int i = 0; i < 8; i++) {
        int t = t0 + i;
        size_t o = base + (size_t)t * Dd;
        float xt = xb[(size_t)t * Dd];
        float y = xm3 * w.x + xm2 * w.y + xm1 * w.z + xt * w.w + bias;
        float s = y * sigmoidf_(y);
        sp[(size_t)t * Dd] = s;
        split_bf16(s,  &g_sh_hi[o], &g_sh_lo[o]);
        split_bf16(xt, &g_x_hi[o],  &g_x_lo[o]);
        xm3 = xm2; xm2 = xm1; xm1 = xt;
    }
}

// ---------------- K1b: weight splits ----------------------------------------
__global__ void wsplit_kernel(const float* __restrict__ w_in,
                              const float* __restrict__ w_mg,
                              const float* __restrict__ w_ch,
                              const float* __restrict__ w1) {
    int i = blockIdx.x * 256 + threadIdx.x;   // i < 256*2048
    float v = (i < 128 * Dd) ? w_in[i] : w_mg[i - 128 * Dd];
    split_bf16(v, &g_b01_hi[i], &g_b01_lo[i]);
    if (i < 128 * Dd) {
        split_bf16(w_ch[i], &g_b2_hi[i], &g_b2_lo[i]);
        split_bf16(w1[i],   &g_w1_hi[i], &g_w1_lo[i]);
    }
}

// ---------------- K2: tensor-core projections via mma.sync (3xBF16) --------
// Merged jobs: y=0: [rk|mg] = shift @ [W_in;W_mg]^T (N=256);
//              y=1: h = x @ W_ch0^T (N=128, bf16-split output).
// 64-token tiles, 2-stage ring, templated on NR for compile-time acc indexing.
#define SA 40                          // padded row stride (bf16 elems)
#define PSMEM 102400                   // 2 stages x (128+512)*SA elems * 2B

template<int NR>
__device__ __forceinline__ void proj_impl(
    const __nv_bfloat16* __restrict__ Ah, const __nv_bfloat16* __restrict__ Al,
    const __nv_bfloat16* __restrict__ Bh, const __nv_bfloat16* __restrict__ Bl,
    unsigned sbase, int tok0)
{
    constexpr int PST_    = (128 + 2 * NR) * SA;  // stage elems
    constexpr int OFF_AL_ = 64 * SA;
    constexpr int OFF_BH_ = 128 * SA;
    constexpr int OFF_BL_ = (128 + NR) * SA;
    constexpr int TOTC    = 512 + 8 * NR;          // 16B chunks per stage
    constexpr int NJ      = (TOTC + 255) / 256;
    constexpr int NSH     = (NR == 256) ? 10 : 9;
    constexpr int NT16    = NR / 64;               // per-warp 16-col groups

    const int tid = threadIdx.x;
    const int lane = tid & 31, wid = tid >> 5;
    const int wm = wid & 1, wn = wid >> 1;         // warp tile 32 tok x NR/4

    auto load_stage = [&](int s) {
        const int kb = s * 32;
        const unsigned st = sbase + (s & 1) * (PST_ * 2);
#pragma unroll
        for (int j = 0; j < NJ; j++) {
            int i = tid + j * 256;
            if (i < TOTC) {
                const __nv_bfloat16* src;
                unsigned dst;
                if (i < 512) {                      // A: 2 arrays x 64 rows x 4
                    int arr = i >> 8, rem = i & 255;
                    int row = rem >> 2, c = rem & 3;
                    src = (arr ? Al : Ah) + (size_t)(tok0 + row) * Dd + kb + c * 8;
                    dst = st + (arr ? OFF_AL_ * 2 : 0) + (row * SA + c * 8) * 2;
                } else {                            // B: 2 arrays x NR rows x 4
                    int i2 = i - 512;
                    int arr = i2 >> NSH, rem = i2 & ((1 << NSH) - 1);
                    int row = rem >> 2, c = rem & 3;
                    src = (arr ? Bl : Bh) + (size_t)row * Dd + kb + c * 8;
                    dst = st + (arr ? OFF_BL_ * 2 : OFF_BH_ * 2) + (row * SA + c * 8) * 2;
                }
                CP16(dst, src);
            }
        }
    };

    load_stage(0);
    asm volatile("cp.async.commit_group;" ::: "memory");
    load_stage(1);
    asm volatile("cp.async.commit_group;" ::: "memory");

    float acc[2][2 * NT16][4];
#pragma unroll
    for (int mt = 0; mt < 2; mt++)
#pragma unroll
        for (int nt = 0; nt < 2 * NT16; nt++)
#pragma unroll
            for (int q = 0; q < 4; q++) acc[mt][nt][q] = 0.f;

    const int lr = lane & 15, lc = lane >> 4;

    for (int s = 0; s < 64; s++) {
        asm volatile("cp.async.wait_group 1;" ::: "memory");
        __syncthreads();

        const unsigned st = sbase + (s & 1) * (PST_ * 2);
#pragma unroll
        for (int kk = 0; kk < 2; kk++) {
            const unsigned kofs = (kk * 16 + lc * 8) * 2;
            unsigned ah[2][4], al[2][4];
#pragma unroll
            for (int mt = 0; mt < 2; mt++) {
                int row = wm * 32 + mt * 16 + lr;
                ldsm4(ah[mt][0], ah[mt][1], ah[mt][2], ah[mt][3],
                      st + row * (SA * 2) + kofs);
                ldsm4(al[mt][0], al[mt][1], al[mt][2], al[mt][3],
                      st + OFF_AL_ * 2 + row * (SA * 2) + kofs);
            }
#pragma unroll
            for (int nt16 = 0; nt16 < NT16; nt16++) {
                int nrow = wn * (NR / 4) + nt16 * 16 + lr;
                unsigned bh[4], bl[4];
                ldsm4(bh[0], bh[1], bh[2], bh[3],
                      st + OFF_BH_ * 2 + nrow * (SA * 2) + kofs);
                ldsm4(bl[0], bl[1], bl[2], bl[3],
                      st + OFF_BL_ * 2 + nrow * (SA * 2) + kofs);
#pragma unroll
                for (int half = 0; half < 2; half++) {
                    unsigned bh0 = half ? bh[1] : bh[0], bh1 = half ? bh[3] : bh[2];
                    unsigned bl0 = half ? bl[1] : bl[0], bl1 = half ? bl[3] : bl[2];
                    int nt = nt16 * 2 + half;
#pragma unroll
                    for (int mt = 0; mt < 2; mt++) {
                        mma16816(acc[mt][nt], ah[mt], bh0, bh1);
                        mma16816(acc[mt][nt], ah[mt], bl0, bl1);
                        mma16816(acc[mt][nt], al[mt], bh0, bh1);
                    }
                }
            }
        }
        __syncthreads();
        if (s + 2 < 64) load_stage(s + 2);
        asm volatile("cp.async.commit_group;" ::: "memory");
    }

    const int g = lane >> 2, tig = lane & 3;
    if (NR == 256) {
        // [rk|mg] -> g_zp cols 0..255
#pragma unroll
        for (int mt = 0; mt < 2; mt++) {
            int token = tok0 + wm * 32 + mt * 16 + g;
#pragma unroll
            for (int nt = 0; nt < 2 * NT16; nt++) {
                int col = wn * (NR / 4) + nt * 8 + tig * 2;
                *reinterpret_cast<float2*>(g_zp + (size_t)token * 384 + col) =
                    make_float2(acc[mt][nt][0], acc[mt][nt][1]);
                *reinterpret_cast<float2*>(g_zp + (size_t)(token + 8) * 384 + col) =
                    make_float2(acc[mt][nt][2], acc[mt][nt][3]);
            }
        }
    } else {
        // h -> bf16 splits
#pragma unroll
        for (int mt = 0; mt < 2; mt++) {
            int token = tok0 + wm * 32 + mt * 16 + g;
#pragma unroll
            for (int nt = 0; nt < 2 * NT16; nt++) {
                int col = wn * (NR / 4) + nt * 8 + tig * 2;
                size_t o0 = (size_t)token * Rr + col;
                size_t o1 = (size_t)(token + 8) * Rr + col;
                split_bf16(acc[mt][nt][0], &g_h_hi[o0],     &g_h_lo[o0]);
                split_bf16(acc[mt][nt][1], &g_h_hi[o0 + 1], &g_h_lo[o0 + 1]);
                split_bf16(acc[mt][nt][2], &g_h_hi[o1],     &g_h_lo[o1]);
                split_bf16(acc[mt][nt][3], &g_h_hi[o1 + 1], &g_h_lo[o1 + 1]);
            }
        }
    }
}

__global__ __launch_bounds__(256, 2) void mma_proj_kernel() {
    extern __shared__ __align__(128) __nv_bfloat16 sm[];
    const unsigned sbase = (unsigned)__cvta_generic_to_shared(sm);
    const int tok0 = blockIdx.x * 64;
    if (blockIdx.y == 0)
        proj_impl<256>(g_sh_hi, g_sh_lo, g_b01_hi, g_b01_lo, sbase, tok0);
    else
        proj_impl<128>(g_x_hi, g_x_lo, g_b2_hi, g_b2_lo, sbase, tok0);
}

// ---------------- K3: u = sigmoid(h @ w1^T + b1) * x  (tensor core) --------
#define SA2 136                        // padded row stride for K=128 rows
#define UOFF_AL (128*SA2)
#define UOFF_BH (256*SA2)
#define UOFF_BL (320*SA2)
#define USMEM (384*SA2*2)              // 104448 B

__global__ __launch_bounds__(256, 2) void ugemm_mma_kernel(
    const float* __restrict__ x, const float* __restrict__ b1) {
    extern __shared__ __align__(128) __nv_bfloat16 sm[];
    const int tid = threadIdx.x;
    const int lane = tid & 31, wid = tid >> 5;
    const int wm = wid & 3, wn = wid >> 2;     // warp tile 32 tok x 32 d
    const int tok0 = blockIdx.x * 128;
    const int d0   = blockIdx.y * 64;

    const unsigned sbase = (unsigned)__cvta_generic_to_shared(sm);

#pragma unroll
    for (int j = 0; j < 24; j++) {
        int i = tid + j * 256;
        const __nv_bfloat16* src;
        unsigned dst;
        if (i < 4096) {
            int arr = i >> 11, rem = i & 2047;
            int row = rem >> 4, c = rem & 15;
            src = (arr ? g_h_lo : g_h_hi) + (size_t)(tok0 + row) * Rr + c * 8;
            dst = sbase + (arr ? UOFF_AL * 2 : 0) + (row * SA2 + c * 8) * 2;
        } else {
            int i2 = i - 4096;
            int arr = i2 >> 10, rem = i2 & 1023;
            int row = rem >> 4, c = rem & 15;
            src = (arr ? g_w1_lo : g_w1_hi) + (size_t)(d0 + row) * Rr + c * 8;
            dst = sbase + (arr ? UOFF_BL * 2 : UOFF_BH * 2) + (row * SA2 + c * 8) * 2;
        }
        CP16(dst, src);
    }
    asm volatile("cp.async.commit_group;" ::: "memory");
    asm volatile("cp.async.wait_group 0;" ::: "memory");
    __syncthreads();

    float acc[2][4][4];
#pragma unroll
    for (int mt = 0; mt < 2; mt++)
#pragma unroll
        for (int nt = 0; nt < 4; nt++)
#pragma unroll
            for (int q = 0; q < 4; q++) acc[mt][nt][q] = 0.f;

    const int lr = lane & 15, lc = lane >> 4;

#pragma unroll
    for (int kk = 0; kk < 8; kk++) {
        const unsigned kofs = (kk * 16 + lc * 8) * 2;
        unsigned ah[2][4], al[2][4];
#pragma unroll
        for (int mt = 0; mt < 2; mt++) {
            int row = wm * 32 + mt * 16 + lr;
            ldsm4(ah[mt][0], ah[mt][1], ah[mt][2], ah[mt][3],
                  sbase + row * (SA2 * 2) + kofs);
            ldsm4(al[mt][0], al[mt][1], al[mt][2], al[mt][3],
                  sbase + UOFF_AL * 2 + row * (SA2 * 2) + kofs);
        }
#pragma unroll
        for (int nt16 = 0; nt16 < 2; nt16++) {
            int nrow = wn * 32 + nt16 * 16 + lr;
            unsigned bh[4], bl[4];
            ldsm4(bh[0], bh[1], bh[2], bh[3],
                  sbase + UOFF_BH * 2 + nrow * (SA2 * 2) + kofs);
            ldsm4(bl[0], bl[1], bl[2], bl[3],
                  sbase + UOFF_BL * 2 + nrow * (SA2 * 2) + kofs);
#pragma unroll
            for (int half = 0; half < 2; half++) {
                unsigned bh0 = half ? bh[1] : bh[0], bh1 = half ? bh[3] : bh[2];
                unsigned bl0 = half ? bl[1] : bl[0], bl1 = half ? bl[3] : bl[2];
                int nt = nt16 * 2 + half;
#pragma unroll
                for (int mt = 0; mt < 2; mt++) {
                    mma16816(acc[mt][nt], ah[mt], bh0, bh1);
                    mma16816(acc[mt][nt], ah[mt], bl0, bl1);
                    mma16816(acc[mt][nt], al[mt], bh0, bh1);
                }
            }
        }
    }

    const int g = lane >> 2, tig = lane & 3;
#pragma unroll
    for (int mt = 0; mt < 2; mt++) {
        int token = tok0 + wm * 32 + mt * 16 + g;
#pragma unroll
        for (int nt = 0; nt < 4; nt++) {
            int col = d0 + wn * 32 + nt * 8 + tig * 2;
            float2 bb = *reinterpret_cast<const float2*>(b1 + col);
#pragma unroll
            for (int rr = 0; rr < 2; rr++) {
                int tk = token + rr * 8;
                float z0 = acc[mt][nt][rr * 2]     + bb.x;
                float z1 = acc[mt][nt][rr * 2 + 1] + bb.y;
                float2 xv = *reinterpret_cast<const float2*>(x + (size_t)tk * Dd + col);
                float2 uv = make_float2(sigmoidf_(z0) * xv.x, sigmoidf_(z1) * xv.y);
                *reinterpret_cast<float2*>(g_u + (size_t)tk * Dd + col) = uv;
            }
        }
    }
}

// ---------------- K4: gate math per token -----------------------------------
__global__ void gates_kernel(const float* __restrict__ mb) {
    int warp = threadIdx.x >> 5;
    int lane = threadIdx.x & 31;
    int token = blockIdx.x * 4 + warp;
    const float* zp = g_zp + (size_t)token * 384;

    float r_a = zp[lane],        r_b = zp[32 + lane];
    float k_a = zp[64 + lane],   k_b = zp[96 + lane];
    float m1a = zp[128 + lane] + mb[lane];
    float m1b = zp[160 + lane] + mb[32 + lane];
    float m2a = zp[192 + lane] + mb[64 + lane];
    float m2b = zp[224 + lane] + mb[96 + lane];

    float sela = softplusf_(m1a), selb = softplusf_(m1b);
    float taua = sigmoidf_(m2a),  taub = sigmoidf_(m2b);
    float ita = expf(taua * logf(sela));
    float itb = expf(taub * logf(selb));
    float ega = expf(-sela * taua);
    float egb = expf(-selb * taub);

    float ss = k_a * k_a + k_b * k_b;
#pragma unroll
    for (int o = 16; o > 0; o >>= 1) ss += __shfl_xor_sync(0xffffffffu, ss, o);
    float inv = 1.f / fmaxf(sqrtf(ss), 1e-12f);

    float* go = g_gates + (size_t)token * 192;
    go[lane]       = r_a;             go[32 + lane]  = r_b;
    go[64 + lane]  = k_a * inv * ita; go[96 + lane]  = k_b * inv * itb;
    go[128 + lane] = ega;             go[160 + lane] = egb;
}

// ---------------- K4b: r~ = r * cumdecay (per chunk) + chunk products -------
__global__ __launch_bounds__(128) void rtil_kernel() {
    int w = blockIdx.x * 4 + (threadIdx.x >> 5);
    int lane = threadIdx.x & 31;
    int c = w & 7;
    int bh = w >> 3;
    int b = bh >> 1, h = bh & 1;
    int m = h * 32 + lane;

    const float* gbase = g_gates + ((size_t)(b * Ll + c * CL)) * 192;
    float* rout = g_rtil + ((size_t)(b * Ll + c * CL)) * Mm + m;

    float P = 1.f;
    float ef[8], rf[8];
#pragma unroll
    for (int i = 0; i < 8; i++) {
        ef[i] = gbase[(size_t)i * 192 + 128 + m];
        rf[i] = gbase[(size_t)i * 192 + m];
    }
    for (int t = 0; t < CL; t++) {
        int j = t & 7;
        P *= ef[j];
        rout[(size_t)t * Mm] = rf[j] * P;
        if (t + 8 < CL) {
            ef[j] = gbase[(size_t)(t + 8) * 192 + 128 + m];
            rf[j] = gbase[(size_t)(t + 8) * 192 + m];
        }
    }
    g_Pc[(b * NC + c) * Mm + m] = P;
}

// ---------------- K5a: chunk-local scans (merged 64-m, no atomics) ----------
__global__ __launch_bounds__(64) void scanA_kernel(const float* __restrict__ rw,
                                                   float* __restrict__ out) {
    const int tid = threadIdx.x;
    const int w = tid >> 5, lane = tid & 31;
    const int d = blockIdx.x * 64 + tid;
    const int b = blockIdx.y;
    const int c = blockIdx.z;
    const int t0base = c * CL;

    __shared__ __align__(16) float sg[2][PF][192];

    const float* gb = g_gates + (size_t)b * Ll * 192;
    const unsigned sb0 = (unsigned)__cvta_generic_to_shared(&sg[w][0][lane * 4]);
    const unsigned sb1 = (unsigned)__cvta_generic_to_shared(&sg[w][0][(32 + lane) * 4]);

#pragma unroll
    for (int s = 0; s < PF - 1; s++) {
        const int t = t0base + s;
        const float* src = gb + (size_t)t * 192;
        unsigned o = (unsigned)(t & (PF - 1)) * 192 * 4;
        CPA16(sb0 + o, src + lane * 4);
        if (lane < 16) CPA16(sb1 + o, src + (32 + lane) * 4);
        asm volatile("cp.async.commit_group;" ::: "memory");
    }

    float2 S[32];
#pragma unroll
    for (int p = 0; p < 32; p++) S[p] = make_float2(0.f, 0.f);

    const float* ub = g_u + ((size_t)b * Ll) * Dd + d;
    const float* sb = g_shift + ((size_t)b * Ll) * Dd + d;
    float* ob = out + ((size_t)b * Ll) * Dd + d;
    const float rwd = rw[d];

    float upf[8], spf[8];
#pragma unroll
    for (int i = 0; i < 8; i++) {
        upf[i] = __ldcg(ub + (size_t)(t0base + i) * Dd);
        spf[i] = __ldcg(sb + (size_t)(t0base + i) * Dd);
    }

    for (int tb = 0; tb < CL; tb += 8) {
#pragma unroll
        for (int j = 0; j < 8; j++) {
            const int t = t0base + tb + j;
            asm volatile("cp.async.wait_group 2;" ::: "memory");
            __syncwarp();
            const float* g0 = &sg[w][t & (PF - 1)][0];

            float2 uu = make_float2(upf[j], upf[j]);
            float2 a0 = make_float2(0.f, 0.f), a1 = a0, a2 = a0, a3 = a0;
#pragma unroll
            for (int q = 0; q < 16; q++) {
                float4 r4 = *reinterpret_cast<const float4*>(g0 + q * 4);
                float4 k4 = *reinterpret_cast<const float4*>(g0 + 64 + q * 4);
                float4 e4 = *reinterpret_cast<const float4*>(g0 + 128 + q * 4);
                S[2 * q]     = ffma2(make_float2(e4.x, e4.y), S[2 * q],
                                     fmul2(make_float2(k4.x, k4.y), uu));
                S[2 * q + 1] = ffma2(make_float2(e4.z, e4.w), S[2 * q + 1],
                                     fmul2(make_float2(k4.z, k4.w), uu));
                if (q & 1) {
                    a0 = ffma2(make_float2(r4.x, r4.y), S[2 * q],     a0);
                    a1 = ffma2(make_float2(r4.z, r4.w), S[2 * q + 1], a1);
                } else {
                    a2 = ffma2(make_float2(r4.x, r4.y), S[2 * q],     a2);
                    a3 = ffma2(make_float2(r4.z, r4.w), S[2 * q + 1], a3);
                }
            }
            float sx = (a0.x + a1.x) + (a2.x + a3.x);
            float sy = (a0.y + a1.y) + (a2.y + a3.y);
            float o = OSCALE * (sx + sy) + spf[j] * rwd;
            ob[(size_t)t * Dd] = o;

            const int tn = t + PF - 1;
            if (tn < t0base + CL) {
                const float* src = gb + (size_t)tn * 192;
                unsigned oo = (unsigned)(tn & (PF - 1)) * 192 * 4;
                CPA16(sb0 + oo, src + lane * 4);
                if (lane < 16) CPA16(sb1 + oo, src + (32 + lane) * 4);
            }
            asm volatile("cp.async.commit_group;" ::: "memory");

            if (tb + j + 8 < CL) {
                upf[j] = __ldcg(ub + (size_t)(t + 8) * Dd);
                spf[j] = __ldcg(sb + (size_t)(t + 8) * Dd);
            }
        }
    }

    if (c < NC - 1) {
        float* se = g_Send + ((size_t)(b * NC + c) * Mm) * Dd + d;
#pragma unroll
        for (int p = 0; p < 32; p++) {
            se[(size_t)(2 * p) * Dd]     = S[p].x;
            se[(size_t)(2 * p + 1) * Dd] = S[p].y;
        }
    }
}

// ---------------- K5b: cross-chunk state propagation ------------------------
__global__ __launch_bounds__(64) void phaseB_kernel() {
    const int d = blockIdx.x * 64 + threadIdx.x;
    const int b = blockIdx.y;
    const int h = blockIdx.z;

    float Sin[32];
#pragma unroll
    for (int j = 0; j < 32; j++) Sin[j] = 0.f;

    for (int c = 0; c < NC - 1; c++) {
        const float* se = g_Send + ((size_t)(b * NC + c) * Mm + h * 32) * Dd + d;
        const float* pc = g_Pc + (b * NC + c) * Mm + h * 32;
        float* so = g_Sin + ((size_t)(b * NC + c + 1) * Mm + h * 32) * Dd + d;
#pragma unroll
        for (int j = 0; j < 32; j++) {
            Sin[j] = pc[j] * Sin[j] + se[(size_t)j * Dd];
            so[(size_t)j * Dd] = Sin[j];
        }
    }
}

// ---------------- K5c: correction GEMM out += OSCALE * rtil @ Sin -----------
__global__ __launch_bounds__(256) void phaseC_kernel(float* __restrict__ out) {
    const int idx = blockIdx.y;
    const int b = idx / (NC - 1);
    const int c = 1 + idx % (NC - 1);
    const int tt = blockIdx.x & 3, dt = blockIdx.x >> 2;
    const int t0 = c * CL + tt * 64;
    const int d0 = dt * 128;

    const float* A  = g_rtil + ((size_t)b * Ll + t0) * Mm;        // [64 t][64 k]
    const float* Bm = g_Sin + ((size_t)(b * NC + c) * Mm) * Dd + d0; // [64 k][Dd]

    __shared__ float As[2][16 * 68];
    __shared__ float Bs[2][16 * 132];

    const int tid = threadIdx.x;
    const int tg = tid >> 4, ng = tid & 15;
    const int a_t = tid >> 2, a_k = (tid & 3) * 4;
    const int b_kr = tid >> 4, b_nb = (tid & 15) * 8;

    float2 acc[4][4];
#pragma unroll
    for (int i = 0; i < 4; i++)
#pragma unroll
        for (int j = 0; j < 4; j++) acc[i][j] = make_float2(0.f, 0.f);

    const float* Aptr = A + (size_t)a_t * Mm + a_k;
    const float* Bptr = Bm + (size_t)b_kr * Dd + b_nb;

    float4 av  = *reinterpret_cast<const float4*>(Aptr);
    float4 bv0 = *reinterpret_cast<const float4*>(Bptr);
    float4 bv1 = *reinterpret_cast<const float4*>(Bptr + 4);

    const int NT = 4;   // K=64, BK=16
    for (int kt = 0; kt < NT; ++kt) {
        const int p = kt & 1;
        {
            float* as = As[p] + a_k * 68 + a_t;
            as[0] = av.x; as[68] = av.y; as[2 * 68] = av.z; as[3 * 68] = av.w;
            float* bs = Bs[p] + b_kr * 132 + b_nb;
            bs[0] = bv0.x; bs[1] = bv0.y; bs[2] = bv0.z; bs[3] = bv0.w;
            bs[4] = bv1.x; bs[5] = bv1.y; bs[6] = bv1.z; bs[7] = bv1.w;
        }
        __syncthreads();
        if (kt + 1 < NT) {
            av  = *reinterpret_cast<const float4*>(Aptr + (kt + 1) * 16);
            bv0 = *reinterpret_cast<const float4*>(Bptr + (size_t)(kt + 1) * 16 * Dd);
            bv1 = *reinterpret_cast<const float4*>(Bptr + (size_t)(kt + 1) * 16 * Dd + 4);
        }
#pragma unroll
        for (int k = 0; k < 16; k++) {
            float4 a4  = *reinterpret_cast<const float4*>(As[p] + k * 68 + tg * 4);
            float4 b40 = *reinterpret_cast<const float4*>(Bs[p] + k * 132 + ng * 8);
            float4 b41 = *reinterpret_cast<const float4*>(Bs[p] + k * 132 + ng * 8 + 4);
            float aval[4] = {a4.x, a4.y, a4.z, a4.w};
            float2 bp[4] = {make_float2(b40.x, b40.y), make_float2(b40.z, b40.w),
                            make_float2(b41.x, b41.y), make_float2(b41.z, b41.w)};
#pragma unroll
            for (int i = 0; i < 4; i++) {
                float2 aa = make_float2(aval[i], aval[i]);
#pragma unroll
                for (int j = 0; j < 4; j++) acc[i][j] = ffma2(aa, bp[j], acc[i][j]);
            }
        }
    }
#pragma unroll
    for (int i = 0; i < 4; i++) {
        int token = t0 + tg * 4 + i;
        float* op = out + ((size_t)b * Ll + token) * Dd + d0 + ng * 8;
#pragma unroll
        for (int j = 0; j < 4; j++) {
            float2 cur = *reinterpret_cast<float2*>(op + 2 * j);
            cur.x += OSCALE * acc[i][j].x;
            cur.y += OSCALE * acc[i][j].y;
            *reinterpret_cast<float2*>(op + 2 * j) = cur;
        }
    }
}

// ---------------- launch -----------------------------------------------------
extern "C" void kernel_launch(void* const* d_in, const int* in_sizes, int n_in,
                              void* d_out, int out_size) {
    const float* x        = (const float*)d_in[0];  // (B,L,D)
    const float* conv_w   = (const float*)d_in[1];  // (D,4)
    const float* conv_b   = (const float*)d_in[2];  // (D,)
    const float* in_proj  = (const float*)d_in[3];  // (128,D)
    const float* ch_w0    = (const float*)d_in[4];  // (128,D)
    const float* ch_w1    = (const float*)d_in[5];  // (D,128)
    const float* ch_b1    = (const float*)d_in[6];  // (D,)
    const float* mem_w    = (const float*)d_in[7];  // (128,D)
    const float* mem_b    = (const float*)d_in[8];  // (128,)
    const float* res_w    = (const float*)d_in[9];  // (D,)
    float* out = (float*)d_out;

    static bool attr_set = false;
    if (!attr_set) {
        cudaFuncSetAttribute(mma_proj_kernel,
                             cudaFuncAttributeMaxDynamicSharedMemorySize, PSMEM);
        cudaFuncSetAttribute(ugemm_mma_kernel,
                             cudaFuncAttributeMaxDynamicSharedMemorySize, USMEM);
        attr_set = true;
    }

    conv_silu_kernel<<<dim3(Dd / 256, Ll / 8, Bb), 256>>>(x, conv_w, conv_b);
    wsplit_kernel<<<dim3(256 * Dd / 256), 256>>>(in_proj, mem_w, ch_w0, ch_w1);
    mma_proj_kernel<<<dim3(BL / 64, 2), 256, PSMEM>>>();
    ugemm_mma_kernel<<<dim3(BL / 128, Dd / 64), 256, USMEM>>>(x, ch_b1);
    gates_kernel<<<dim3(BL / 4), 128>>>(mem_b);
    rtil_kernel<<<dim3(16), 128>>>();
    scanA_kernel<<<dim3(Dd / 64, Bb, NC), 64>>>(res_w, out);
    phaseB_kernel<<<dim3(Dd / 64, Bb, 2), 64>>>();
    phaseC_kernel<<<dim3(64, Bb * (NC - 1)), 256>>>(out);
}

// round 12
// speedup vs baseline: 3.5917x; 1.0042x over previous
#include <cuda_runtime.h>
#include <cuda_bf16.h>
#include <math.h>

// Problem constants
#define Bb 4
#define Ll 2048
#define Dd 2048
#define Mm 64
#define Rr 128
#define BL (Bb*Ll)
#define OSCALE 0.125f   // 1/sqrt(64)
#define PF 4            // scan gates prefetch stages (power of 2)
#define NC 8            // scan time chunks
#define CL 256          // chunk length

// ---------------- scratch (device globals; no allocation allowed) ----------
__device__ float g_shift[BL*Dd];     // silu(conv(x))  (residual, scan input)
__device__ float g_u[BL*Dd];         // ch * x
__device__ float g_zp[BL*384];       // [token][0..127]=rk, [128..255]=mg(pre-bias)
__device__ float g_gates[BL*192];    // [token][0..63]=r, [64..127]=k_hat, [128..191]=exp(g)

// bf16 splits for tensor-core 3xBF16 GEMMs
__device__ __nv_bfloat16 g_sh_hi[BL*Dd], g_sh_lo[BL*Dd];
__device__ __nv_bfloat16 g_x_hi[BL*Dd],  g_x_lo[BL*Dd];
__device__ __nv_bfloat16 g_b01_hi[256*Dd], g_b01_lo[256*Dd];  // [in_proj;mem_gate]
__device__ __nv_bfloat16 g_b2_hi[128*Dd],  g_b2_lo[128*Dd];   // ch_gate_w0
__device__ __nv_bfloat16 g_w1_hi[Dd*Rr],   g_w1_lo[Dd*Rr];    // ch_gate_w1
__device__ __nv_bfloat16 g_h_hi[BL*Rr],    g_h_lo[BL*Rr];     // h = x @ w0^T

// chunked-scan scratch
__device__ float g_Send[Bb*NC*Mm*Dd];   // local end-state per chunk
__device__ float g_Sin[Bb*NC*Mm*Dd];    // incoming state per chunk (c>=1)
__device__ float g_rtil[BL*Mm];         // r_t * cumdecay_within_chunk
__device__ float g_Pc[Bb*NC*Mm];        // full-chunk decay products

// ---------------- f32x2 packed math helpers --------------------------------
__device__ __forceinline__ float2 ffma2(float2 a, float2 b, float2 c) {
    unsigned long long au = *reinterpret_cast<unsigned long long*>(&a);
    unsigned long long bu = *reinterpret_cast<unsigned long long*>(&b);
    unsigned long long cu = *reinterpret_cast<unsigned long long*>(&c);
    unsigned long long du;
    asm("fma.rn.f32x2 %0, %1, %2, %3;" : "=l"(du) : "l"(au), "l"(bu), "l"(cu));
    return *reinterpret_cast<float2*>(&du);
}
__device__ __forceinline__ float2 fmul2(float2 a, float2 b) {
    unsigned long long au = *reinterpret_cast<unsigned long long*>(&a);
    unsigned long long bu = *reinterpret_cast<unsigned long long*>(&b);
    unsigned long long du;
    asm("mul.rn.f32x2 %0, %1, %2;" : "=l"(du) : "l"(au), "l"(bu));
    return *reinterpret_cast<float2*>(&du);
}
__device__ __forceinline__ float sigmoidf_(float x) { return 1.f / (1.f + expf(-x)); }
__device__ __forceinline__ float softplusf_(float x) {
    return fmaxf(x, 0.f) + log1pf(expf(-fabsf(x)));
}
__device__ __forceinline__ void split_bf16(float v, __nv_bfloat16* hi, __nv_bfloat16* lo) {
    __nv_bfloat16 h = __float2bfloat16_rn(v);
    *hi = h;
    *lo = __float2bfloat16_rn(v - __bfloat162float(h));
}

// ---------------- warp-MMA helpers ------------------------------------------
__device__ __forceinline__ void ldsm4(unsigned& r0, unsigned& r1, unsigned& r2,
                                      unsigned& r3, unsigned addr) {
    asm volatile("ldmatrix.sync.aligned.m8n8.x4.shared.b16 {%0,%1,%2,%3}, [%4];"
                 : "=r"(r0), "=r"(r1), "=r"(r2), "=r"(r3) : "r"(addr));
}
__device__ __forceinline__ void mma16816(float* c, const unsigned* a,
                                         unsigned b0, unsigned b1) {
    asm volatile(
        "mma.sync.aligned.m16n8k16.row.col.f32.bf16.bf16.f32 "
        "{%0,%1,%2,%3}, {%4,%5,%6,%7}, {%8,%9}, {%0,%1,%2,%3};"
        : "+f"(c[0]), "+f"(c[1]), "+f"(c[2]), "+f"(c[3])
        : "r"(a[0]), "r"(a[1]), "r"(a[2]), "r"(a[3]), "r"(b0), "r"(b1));
}
#define CP16(dst, src) asm volatile("cp.async.cg.shared.global [%0], [%1], 16;" :: "r"(dst), "l"(src))
#define CPA16(dst, src) asm volatile("cp.async.ca.shared.global [%0], [%1], 16;" :: "r"(dst), "l"(src))

// ---------------- K1: causal depthwise conv (W=4) + SiLU + bf16 splits -----
__global__ void conv_silu_kernel(const float* __restrict__ x,
                                 const float* __restrict__ cw,
                                 const float* __restrict__ cb) {
    int d  = blockIdx.x * 256 + threadIdx.x;
    int t0 = blockIdx.y * 8;
    int b  = blockIdx.z;
    float4 w = *reinterpret_cast<const float4*>(cw + d * 4);
    float bias = cb[d];
    size_t base = ((size_t)b * Ll) * Dd + d;
    const float* xb = x + base;
    float* sp = g_shift + base;
    float xm3 = (t0 - 3 >= 0) ? xb[(size_t)(t0 - 3) * Dd] : 0.f;
    float xm2 = (t0 - 2 >= 0) ? xb[(size_t)(t0 - 2) * Dd] : 0.f;
    float xm1 = (t0 - 1 >= 0) ? xb[(size_t)(t0 - 1) * Dd] : 0.f;
#pragma unroll
    for (int i = 0; i < 8; i++) {
        int t = t0 + i;
        size_t o = base + (size_t)t * Dd;
        float xt = xb[(size_t)t * Dd];
        float y = xm3 * w.x + xm2 * w.y + xm1 * w.z + xt * w.w + bias;
        float s = y * sigmoidf_(y);
        sp[(size_t)t * Dd] = s;
        split_bf16(s,  &g_sh_hi[o], &g_sh_lo[o]);
        split_bf16(xt, &g_x_hi[o],  &g_x_lo[o]);
        xm3 = xm2; xm2 = xm1; xm1 = xt;
    }
}

// ---------------- K1b: weight splits ----------------------------------------
__global__ void wsplit_kernel(const float* __restrict__ w_in,
                              const float* __restrict__ w_mg,
                              const float* __restrict__ w_ch,
                              const float* __restrict__ w1) {
    int i = blockIdx.x * 256 + threadIdx.x;   // i < 256*2048
    float v = (i < 128 * Dd) ? w_in[i] : w_mg[i - 128 * Dd];
    split_bf16(v, &g_b01_hi[i], &g_b01_lo[i]);
    if (i < 128 * Dd) {
        split_bf16(w_ch[i], &g_b2_hi[i], &g_b2_lo[i]);
        split_bf16(w1[i],   &g_w1_hi[i], &g_w1_lo[i]);
    }
}

// ---------------- K2: tensor-core projections via mma.sync (3xBF16) --------
#define SA 40                          // padded row stride (bf16 elems)
#define PSMEM 102400

template<int NR>
__device__ __forceinline__ void proj_impl(
    const __nv_bfloat16* __restrict__ Ah, const __nv_bfloat16* __restrict__ Al,
    const __nv_bfloat16* __restrict__ Bh, const __nv_bfloat16* __restrict__ Bl,
    unsigned sbase, int tok0)
{
    constexpr int PST_    = (128 + 2 * NR) * SA;  // stage elems
    constexpr int OFF_AL_ = 64 * SA;
    constexpr int OFF_BH_ = 128 * SA;
    constexpr int OFF_BL_ = (128 + NR) * SA;
    constexpr int TOTC    = 512 + 8 * NR;          // 16B chunks per stage
    constexpr int NJ      = (TOTC + 255) / 256;
    constexpr int NSH     = (NR == 256) ? 10 : 9;
    constexpr int NT16    = NR / 64;               // per-warp 16-col groups

    const int tid = threadIdx.x;
    const int lane = tid & 31, wid = tid >> 5;
    const int wm = wid & 1, wn = wid >> 1;         // warp tile 32 tok x NR/4

    auto load_stage = [&](int s) {
        const int kb = s * 32;
        const unsigned st = sbase + (s & 1) * (PST_ * 2);
#pragma unroll
        for (int j = 0; j < NJ; j++) {
            int i = tid + j * 256;
            if (i < TOTC) {
                const __nv_bfloat16* src;
                unsigned dst;
                if (i < 512) {
                    int arr = i >> 8, rem = i & 255;
                    int row = rem >> 2, c = rem & 3;
                    src = (arr ? Al : Ah) + (size_t)(tok0 + row) * Dd + kb + c * 8;
                    dst = st + (arr ? OFF_AL_ * 2 : 0) + (row * SA + c * 8) * 2;
                } else {
                    int i2 = i - 512;
                    int arr = i2 >> NSH, rem = i2 & ((1 << NSH) - 1);
                    int row = rem >> 2, c = rem & 3;
                    src = (arr ? Bl : Bh) + (size_t)row * Dd + kb + c * 8;
                    dst = st + (arr ? OFF_BL_ * 2 : OFF_BH_ * 2) + (row * SA + c * 8) * 2;
                }
                CP16(dst, src);
            }
        }
    };

    load_stage(0);
    asm volatile("cp.async.commit_group;" ::: "memory");
    load_stage(1);
    asm volatile("cp.async.commit_group;" ::: "memory");

    float acc[2][2 * NT16][4];
#pragma unroll
    for (int mt = 0; mt < 2; mt++)
#pragma unroll
        for (int nt = 0; nt < 2 * NT16; nt++)
#pragma unroll
            for (int q = 0; q < 4; q++) acc[mt][nt][q] = 0.f;

    const int lr = lane & 15, lc = lane >> 4;

    for (int s = 0; s < 64; s++) {
        asm volatile("cp.async.wait_group 1;" ::: "memory");
        __syncthreads();

        const unsigned st = sbase + (s & 1) * (PST_ * 2);
#pragma unroll
        for (int kk = 0; kk < 2; kk++) {
            const unsigned kofs = (kk * 16 + lc * 8) * 2;
            unsigned ah[2][4], al[2][4];
#pragma unroll
            for (int mt = 0; mt < 2; mt++) {
                int row = wm * 32 + mt * 16 + lr;
                ldsm4(ah[mt][0], ah[mt][1], ah[mt][2], ah[mt][3],
                      st + row * (SA * 2) + kofs);
                ldsm4(al[mt][0], al[mt][1], al[mt][2], al[mt][3],
                      st + OFF_AL_ * 2 + row * (SA * 2) + kofs);
            }
#pragma unroll
            for (int nt16 = 0; nt16 < NT16; nt16++) {
                int nrow = wn * (NR / 4) + nt16 * 16 + lr;
                unsigned bh[4], bl[4];
                ldsm4(bh[0], bh[1], bh[2], bh[3],
                      st + OFF_BH_ * 2 + nrow * (SA * 2) + kofs);
                ldsm4(bl[0], bl[1], bl[2], bl[3],
                      st + OFF_BL_ * 2 + nrow * (SA * 2) + kofs);
#pragma unroll
                for (int half = 0; half < 2; half++) {
                    unsigned bh0 = half ? bh[1] : bh[0], bh1 = half ? bh[3] : bh[2];
                    unsigned bl0 = half ? bl[1] : bl[0], bl1 = half ? bl[3] : bl[2];
                    int nt = nt16 * 2 + half;
#pragma unroll
                    for (int mt = 0; mt < 2; mt++) {
                        mma16816(acc[mt][nt], ah[mt], bh0, bh1);
                        mma16816(acc[mt][nt], ah[mt], bl0, bl1);
                        mma16816(acc[mt][nt], al[mt], bh0, bh1);
                    }
                }
            }
        }
        __syncthreads();
        if (s + 2 < 64) load_stage(s + 2);
        asm volatile("cp.async.commit_group;" ::: "memory");
    }

    const int g = lane >> 2, tig = lane & 3;
    if (NR == 256) {
#pragma unroll
        for (int mt = 0; mt < 2; mt++) {
            int token = tok0 + wm * 32 + mt * 16 + g;
#pragma unroll
            for (int nt = 0; nt < 2 * NT16; nt++) {
                int col = wn * (NR / 4) + nt * 8 + tig * 2;
                *reinterpret_cast<float2*>(g_zp + (size_t)token * 384 + col) =
                    make_float2(acc[mt][nt][0], acc[mt][nt][1]);
                *reinterpret_cast<float2*>(g_zp + (size_t)(token + 8) * 384 + col) =
                    make_float2(acc[mt][nt][2], acc[mt][nt][3]);
            }
        }
    } else {
#pragma unroll
        for (int mt = 0; mt < 2; mt++) {
            int token = tok0 + wm * 32 + mt * 16 + g;
#pragma unroll
            for (int nt = 0; nt < 2 * NT16; nt++) {
                int col = wn * (NR / 4) + nt * 8 + tig * 2;
                size_t o0 = (size_t)token * Rr + col;
                size_t o1 = (size_t)(token + 8) * Rr + col;
                split_bf16(acc[mt][nt][0], &g_h_hi[o0],     &g_h_lo[o0]);
                split_bf16(acc[mt][nt][1], &g_h_hi[o0 + 1], &g_h_lo[o0 + 1]);
                split_bf16(acc[mt][nt][2], &g_h_hi[o1],     &g_h_lo[o1]);
                split_bf16(acc[mt][nt][3], &g_h_hi[o1 + 1], &g_h_lo[o1 + 1]);
            }
        }
    }
}

__global__ __launch_bounds__(256, 2) void mma_projA_kernel() {
    extern __shared__ __align__(128) __nv_bfloat16 sm[];
    proj_impl<256>(g_sh_hi, g_sh_lo, g_b01_hi, g_b01_lo,
                   (unsigned)__cvta_generic_to_shared(sm), blockIdx.x * 64);
}
__global__ __launch_bounds__(256, 2) void mma_projH_kernel() {
    extern __shared__ __align__(128) __nv_bfloat16 sm[];
    proj_impl<128>(g_x_hi, g_x_lo, g_b2_hi, g_b2_lo,
                   (unsigned)__cvta_generic_to_shared(sm), blockIdx.x * 64);
}

// ---------------- K3: u = sigmoid(h @ w1^T + b1) * x  (tensor core) --------
#define SA2 136                        // padded row stride for K=128 rows
#define UOFF_AL (128*SA2)
#define UOFF_BH (256*SA2)
#define UOFF_BL (320*SA2)
#define USMEM (384*SA2*2)              // 104448 B

__global__ __launch_bounds__(256, 2) void ugemm_mma_kernel(
    const float* __restrict__ x, const float* __restrict__ b1) {
    extern __shared__ __align__(128) __nv_bfloat16 sm[];
    const int tid = threadIdx.x;
    const int lane = tid & 31, wid = tid >> 5;
    const int wm = wid & 3, wn = wid >> 2;     // warp tile 32 tok x 32 d
    const int tok0 = blockIdx.x * 128;
    const int d0   = blockIdx.y * 64;

    const unsigned sbase = (unsigned)__cvta_generic_to_shared(sm);

#pragma unroll
    for (int j = 0; j < 24; j++) {
        int i = tid + j * 256;
        const __nv_bfloat16* src;
        unsigned dst;
        if (i < 4096) {
            int arr = i >> 11, rem = i & 2047;
            int row = rem >> 4, c = rem & 15;
            src = (arr ? g_h_lo : g_h_hi) + (size_t)(tok0 + row) * Rr + c * 8;
            dst = sbase + (arr ? UOFF_AL * 2 : 0) + (row * SA2 + c * 8) * 2;
        } else {
            int i2 = i - 4096;
            int arr = i2 >> 10, rem = i2 & 1023;
            int row = rem >> 4, c = rem & 15;
            src = (arr ? g_w1_lo : g_w1_hi) + (size_t)(d0 + row) * Rr + c * 8;
            dst = sbase + (arr ? UOFF_BL * 2 : UOFF_BH * 2) + (row * SA2 + c * 8) * 2;
        }
        CP16(dst, src);
    }
    asm volatile("cp.async.commit_group;" ::: "memory");
    asm volatile("cp.async.wait_group 0;" ::: "memory");
    __syncthreads();

    float acc[2][4][4];
#pragma unroll
    for (int mt = 0; mt < 2; mt++)
#pragma unroll
        for (int nt = 0; nt < 4; nt++)
#pragma unroll
            for (int q = 0; q < 4; q++) acc[mt][nt][q] = 0.f;

    const int lr = lane & 15, lc = lane >> 4;

#pragma unroll
    for (int kk = 0; kk < 8; kk++) {
        const unsigned kofs = (kk * 16 + lc * 8) * 2;
        unsigned ah[2][4], al[2][4];
#pragma unroll
        for (int mt = 0; mt < 2; mt++) {
            int row = wm * 32 + mt * 16 + lr;
            ldsm4(ah[mt][0], ah[mt][1], ah[mt][2], ah[mt][3],
                  sbase + row * (SA2 * 2) + kofs);
            ldsm4(al[mt][0], al[mt][1], al[mt][2], al[mt][3],
                  sbase + UOFF_AL * 2 + row * (SA2 * 2) + kofs);
        }
#pragma unroll
        for (int nt16 = 0; nt16 < 2; nt16++) {
            int nrow = wn * 32 + nt16 * 16 + lr;
            unsigned bh[4], bl[4];
            ldsm4(bh[0], bh[1], bh[2], bh[3],
                  sbase + UOFF_BH * 2 + nrow * (SA2 * 2) + kofs);
            ldsm4(bl[0], bl[1], bl[2], bl[3],
                  sbase + UOFF_BL * 2 + nrow * (SA2 * 2) + kofs);
#pragma unroll
            for (int half = 0; half < 2; half++) {
                unsigned bh0 = half ? bh[1] : bh[0], bh1 = half ? bh[3] : bh[2];
                unsigned bl0 = half ? bl[1] : bl[0], bl1 = half ? bl[3] : bl[2];
                int nt = nt16 * 2 + half;
#pragma unroll
                for (int mt = 0; mt < 2; mt++) {
                    mma16816(acc[mt][nt], ah[mt], bh0, bh1);
                    mma16816(acc[mt][nt], ah[mt], bl0, bl1);
                    mma16816(acc[mt][nt], al[mt], bh0, bh1);
                }
            }
        }
    }

    const int g = lane >> 2, tig = lane & 3;
#pragma unroll
    for (int mt = 0; mt < 2; mt++) {
        int token = tok0 + wm * 32 + mt * 16 + g;
#pragma unroll
        for (int nt = 0; nt < 4; nt++) {
            int col = d0 + wn * 32 + nt * 8 + tig * 2;
            float2 bb = *reinterpret_cast<const float2*>(b1 + col);
#pragma unroll
            for (int rr = 0; rr < 2; rr++) {
                int tk = token + rr * 8;
                float z0 = acc[mt][nt][rr * 2]     + bb.x;
                float z1 = acc[mt][nt][rr * 2 + 1] + bb.y;
                float2 xv = *reinterpret_cast<const float2*>(x + (size_t)tk * Dd + col);
                float2 uv = make_float2(sigmoidf_(z0) * xv.x, sigmoidf_(z1) * xv.y);
                *reinterpret_cast<float2*>(g_u + (size_t)tk * Dd + col) = uv;
            }
        }
    }
}

// ---------------- K4: gate math per token -----------------------------------
__global__ void gates_kernel(const float* __restrict__ mb) {
    int warp = threadIdx.x >> 5;
    int lane = threadIdx.x & 31;
    int token = blockIdx.x * 4 + warp;
    const float* zp = g_zp + (size_t)token * 384;

    float r_a = zp[lane],        r_b = zp[32 + lane];
    float k_a = zp[64 + lane],   k_b = zp[96 + lane];
    float m1a = zp[128 + lane] + mb[lane];
    float m1b = zp[160 + lane] + mb[32 + lane];
    float m2a = zp[192 + lane] + mb[64 + lane];
    float m2b = zp[224 + lane] + mb[96 + lane];

    float sela = softplusf_(m1a), selb = softplusf_(m1b);
    float taua = sigmoidf_(m2a),  taub = sigmoidf_(m2b);
    float ita = expf(taua * logf(sela));
    float itb = expf(taub * logf(selb));
    float ega = expf(-sela * taua);
    float egb = expf(-selb * taub);

    float ss = k_a * k_a + k_b * k_b;
#pragma unroll
    for (int o = 16; o > 0; o >>= 1) ss += __shfl_xor_sync(0xffffffffu, ss, o);
    float inv = 1.f / fmaxf(sqrtf(ss), 1e-12f);

    float* go = g_gates + (size_t)token * 192;
    go[lane]       = r_a;             go[32 + lane]  = r_b;
    go[64 + lane]  = k_a * inv * ita; go[96 + lane]  = k_b * inv * itb;
    go[128 + lane] = ega;             go[160 + lane] = egb;
}

// ---------------- K4b: r~ = r * cumdecay (per chunk) + chunk products -------
__global__ __launch_bounds__(128) void rtil_kernel() {
    int w = blockIdx.x * 4 + (threadIdx.x >> 5);
    int lane = threadIdx.x & 31;
    int c = w & 7;
    int bh = w >> 3;
    int b = bh >> 1, h = bh & 1;
    int m = h * 32 + lane;

    const float* gbase = g_gates + ((size_t)(b * Ll + c * CL)) * 192;
    float* rout = g_rtil + ((size_t)(b * Ll + c * CL)) * Mm + m;

    float P = 1.f;
    float ef[8], rf[8];
#pragma unroll
    for (int i = 0; i < 8; i++) {
        ef[i] = gbase[(size_t)i * 192 + 128 + m];
        rf[i] = gbase[(size_t)i * 192 + m];
    }
    for (int t = 0; t < CL; t++) {
        int j = t & 7;
        P *= ef[j];
        rout[(size_t)t * Mm] = rf[j] * P;
        if (t + 8 < CL) {
            ef[j] = gbase[(size_t)(t + 8) * 192 + 128 + m];
            rf[j] = gbase[(size_t)(t + 8) * 192 + m];
        }
    }
    g_Pc[(b * NC + c) * Mm + m] = P;
}

// ---------------- K5a: chunk-local scans (merged 64-m, no atomics) ----------
__global__ __launch_bounds__(64) void scanA_kernel(const float* __restrict__ rw,
                                                   float* __restrict__ out) {
    const int tid = threadIdx.x;
    const int w = tid >> 5, lane = tid & 31;
    const int d = blockIdx.x * 64 + tid;
    const int b = blockIdx.y;
    const int c = blockIdx.z;
    const int t0base = c * CL;

    __shared__ __align__(16) float sg[2][PF][192];

    const float* gb = g_gates + (size_t)b * Ll * 192;
    const unsigned sb0 = (unsigned)__cvta_generic_to_shared(&sg[w][0][lane * 4]);
    const unsigned sb1 = (unsigned)__cvta_generic_to_shared(&sg[w][0][(32 + lane) * 4]);

#pragma unroll
    for (int s = 0; s < PF - 1; s++) {
        const int t = t0base + s;
        const float* src = gb + (size_t)t * 192;
        unsigned o = (unsigned)(t & (PF - 1)) * 192 * 4;
        CPA16(sb0 + o, src + lane * 4);
        if (lane < 16) CPA16(sb1 + o, src + (32 + lane) * 4);
        asm volatile("cp.async.commit_group;" ::: "memory");
    }

    float2 S[32];
#pragma unroll
    for (int p = 0; p < 32; p++) S[p] = make_float2(0.f, 0.f);

    const float* ub = g_u + ((size_t)b * Ll) * Dd + d;
    const float* sb = g_shift + ((size_t)b * Ll) * Dd + d;
    float* ob = out + ((size_t)b * Ll) * Dd + d;
    const float rwd = rw[d];

    float upf[8], spf[8];
#pragma unroll
    for (int i = 0; i < 8; i++) {
        upf[i] = __ldcg(ub + (size_t)(t0base + i) * Dd);
        spf[i] = __ldcg(sb + (size_t)(t0base + i) * Dd);
    }

    for (int tb = 0; tb < CL; tb += 8) {
#pragma unroll
        for (int j = 0; j < 8; j++) {
            const int t = t0base + tb + j;
            asm volatile("cp.async.wait_group 2;" ::: "memory");
            __syncwarp();
            const float* g0 = &sg[w][t & (PF - 1)][0];

            float2 uu = make_float2(upf[j], upf[j]);
            float2 a0 = make_float2(0.f, 0.f), a1 = a0, a2 = a0, a3 = a0;
#pragma unroll
            for (int q = 0; q < 16; q++) {
                float4 r4 = *reinterpret_cast<const float4*>(g0 + q * 4);
                float4 k4 = *reinterpret_cast<const float4*>(g0 + 64 + q * 4);
                float4 e4 = *reinterpret_cast<const float4*>(g0 + 128 + q * 4);
                S[2 * q]     = ffma2(make_float2(e4.x, e4.y), S[2 * q],
                                     fmul2(make_float2(k4.x, k4.y), uu));
                S[2 * q + 1] = ffma2(make_float2(e4.z, e4.w), S[2 * q + 1],
                                     fmul2(make_float2(k4.z, k4.w), uu));
                if (q & 1) {
                    a0 = ffma2(make_float2(r4.x, r4.y), S[2 * q],     a0);
                    a1 = ffma2(make_float2(r4.z, r4.w), S[2 * q + 1], a1);
                } else {
                    a2 = ffma2(make_float2(r4.x, r4.y), S[2 * q],     a2);
                    a3 = ffma2(make_float2(r4.z, r4.w), S[2 * q + 1], a3);
                }
            }
            float sx = (a0.x + a1.x) + (a2.x + a3.x);
            float sy = (a0.y + a1.y) + (a2.y + a3.y);
            float o = OSCALE * (sx + sy) + spf[j] * rwd;
            ob[(size_t)t * Dd] = o;

            const int tn = t + PF - 1;
            if (tn < t0base + CL) {
                const float* src = gb + (size_t)tn * 192;
                unsigned oo = (unsigned)(tn & (PF - 1)) * 192 * 4;
                CPA16(sb0 + oo, src + lane * 4);
                if (lane < 16) CPA16(sb1 + oo, src + (32 + lane) * 4);
            }
            asm volatile("cp.async.commit_group;" ::: "memory");

            if (tb + j + 8 < CL) {
                upf[j] = __ldcg(ub + (size_t)(t + 8) * Dd);
                spf[j] = __ldcg(sb + (size_t)(t + 8) * Dd);
            }
        }
    }

    if (c < NC - 1) {
        float* se = g_Send + ((size_t)(b * NC + c) * Mm) * Dd + d;
#pragma unroll
        for (int p = 0; p < 32; p++) {
            se[(size_t)(2 * p) * Dd]     = S[p].x;
            se[(size_t)(2 * p + 1) * Dd] = S[p].y;
        }
    }
}

// ---------------- K5b: cross-chunk state propagation ------------------------
__global__ __launch_bounds__(64) void phaseB_kernel() {
    const int d = blockIdx.x * 64 + threadIdx.x;
    const int b = blockIdx.y;
    const int h = blockIdx.z;

    float Sin[32];
#pragma unroll
    for (int j = 0; j < 32; j++) Sin[j] = 0.f;

    for (int c = 0; c < NC - 1; c++) {
        const float* se = g_Send + ((size_t)(b * NC + c) * Mm + h * 32) * Dd + d;
        const float* pc = g_Pc + (b * NC + c) * Mm + h * 32;
        float* so = g_Sin + ((size_t)(b * NC + c + 1) * Mm + h * 32) * Dd + d;
#pragma unroll
        for (int j = 0; j < 32; j++) {
            Sin[j] = pc[j] * Sin[j] + se[(size_t)j * Dd];
            so[(size_t)j * Dd] = Sin[j];
        }
    }
}

// ---------------- K5c: correction GEMM out += OSCALE * rtil @ Sin -----------
__global__ __launch_bounds__(256) void phaseC_kernel(float* __restrict__ out) {
    const int idx = blockIdx.y;
    const int b = idx / (NC - 1);
    const int c = 1 + idx % (NC - 1);
    const int tt = blockIdx.x & 3, dt = blockIdx.x >> 2;
    const int t0 = c * CL + tt * 64;
    const int d0 = dt * 128;

    const float* A  = g_rtil + ((size_t)b * Ll + t0) * Mm;        // [64 t][64 k]
    const float* Bm = g_Sin + ((size_t)(b * NC + c) * Mm) * Dd + d0; // [64 k][Dd]

    __shared__ float As[2][16 * 68];
    __shared__ float Bs[2][16 * 132];

    const int tid = threadIdx.x;
    const int tg = tid >> 4, ng = tid & 15;
    const int a_t = tid >> 2, a_k = (tid & 3) * 4;
    const int b_kr = tid >> 4, b_nb = (tid & 15) * 8;

    float2 acc[4][4];
#pragma unroll
    for (int i = 0; i < 4; i++)
#pragma unroll
        for (int j = 0; j < 4; j++) acc[i][j] = make_float2(0.f, 0.f);

    const float* Aptr = A + (size_t)a_t * Mm + a_k;
    const float* Bptr = Bm + (size_t)b_kr * Dd + b_nb;

    float4 av  = *reinterpret_cast<const float4*>(Aptr);
    float4 bv0 = *reinterpret_cast<const float4*>(Bptr);
    float4 bv1 = *reinterpret_cast<const float4*>(Bptr + 4);

    const int NT = 4;   // K=64, BK=16
    for (int kt = 0; kt < NT; ++kt) {
        const int p = kt & 1;
        {
            float* as = As[p] + a_k * 68 + a_t;
            as[0] = av.x; as[68] = av.y; as[2 * 68] = av.z; as[3 * 68] = av.w;
            float* bs = Bs[p] + b_kr * 132 + b_nb;
            bs[0] = bv0.x; bs[1] = bv0.y; bs[2] = bv0.z; bs[3] = bv0.w;
            bs[4] = bv1.x; bs[5] = bv1.y; bs[6] = bv1.z; bs[7] = bv1.w;
        }
        __syncthreads();
        if (kt + 1 < NT) {
            av  = *reinterpret_cast<const float4*>(Aptr + (kt + 1) * 16);
            bv0 = *reinterpret_cast<const float4*>(Bptr + (size_t)(kt + 1) * 16 * Dd);
            bv1 = *reinterpret_cast<const float4*>(Bptr + (size_t)(kt + 1) * 16 * Dd + 4);
        }
#pragma unroll
        for (int k = 0; k < 16; k++) {
            float4 a4  = *reinterpret_cast<const float4*>(As[p] + k * 68 + tg * 4);
            float4 b40 = *reinterpret_cast<const float4*>(Bs[p] + k * 132 + ng * 8);
            float4 b41 = *reinterpret_cast<const float4*>(Bs[p] + k * 132 + ng * 8 + 4);
            float aval[4] = {a4.x, a4.y, a4.z, a4.w};
            float2 bp[4] = {make_float2(b40.x, b40.y), make_float2(b40.z, b40.w),
                            make_float2(b41.x, b41.y), make_float2(b41.z, b41.w)};
#pragma unroll
            for (int i = 0; i < 4; i++) {
                float2 aa = make_float2(aval[i], aval[i]);
#pragma unroll
                for (int j = 0; j < 4; j++) acc[i][j] = ffma2(aa, bp[j], acc[i][j]);
            }
        }
    }
#pragma unroll
    for (int i = 0; i < 4; i++) {
        int token = t0 + tg * 4 + i;
        float* op = out + ((size_t)b * Ll + token) * Dd + d0 + ng * 8;
#pragma unroll
        for (int j = 0; j < 4; j++) {
            float2 cur = *reinterpret_cast<float2*>(op + 2 * j);
            cur.x += OSCALE * acc[i][j].x;
            cur.y += OSCALE * acc[i][j].y;
            *reinterpret_cast<float2*>(op + 2 * j) = cur;
        }
    }
}

// ---------------- launch (2-stream fork/join, graph-capturable) -------------
extern "C" void kernel_launch(void* const* d_in, const int* in_sizes, int n_in,
                              void* d_out, int out_size) {
    const float* x        = (const float*)d_in[0];  // (B,L,D)
    const float* conv_w   = (const float*)d_in[1];  // (D,4)
    const float* conv_b   = (const float*)d_in[2];  // (D,)
    const float* in_proj  = (const float*)d_in[3];  // (128,D)
    const float* ch_w0    = (const float*)d_in[4];  // (128,D)
    const float* ch_w1    = (const float*)d_in[5];  // (D,128)
    const float* ch_b1    = (const float*)d_in[6];  // (D,)
    const float* mem_w    = (const float*)d_in[7];  // (128,D)
    const float* mem_b    = (const float*)d_in[8];  // (128,)
    const float* res_w    = (const float*)d_in[9];  // (D,)
    float* out = (float*)d_out;

    static bool init_done = false;
    static cudaStream_t s1;
    static cudaEvent_t e0, e_conv, e_w, e_u;
    if (!init_done) {
        cudaFuncSetAttribute(mma_projA_kernel,
                             cudaFuncAttributeMaxDynamicSharedMemorySize, PSMEM);
        cudaFuncSetAttribute(mma_projH_kernel,
                             cudaFuncAttributeMaxDynamicSharedMemorySize, PSMEM);
        cudaFuncSetAttribute(ugemm_mma_kernel,
                             cudaFuncAttributeMaxDynamicSharedMemorySize, USMEM);
        cudaStreamCreateWithFlags(&s1, cudaStreamNonBlocking);
        cudaEventCreateWithFlags(&e0,     cudaEventDisableTiming);
        cudaEventCreateWithFlags(&e_conv, cudaEventDisableTiming);
        cudaEventCreateWithFlags(&e_w,    cudaEventDisableTiming);
        cudaEventCreateWithFlags(&e_u,    cudaEventDisableTiming);
        init_done = true;
    }

    // fork aux stream from the (captured) main stream
    cudaEventRecord(e0, 0);
    cudaStreamWaitEvent(s1, e0, 0);

    // main: conv (x -> shift + splits)       aux: weight splits
    conv_silu_kernel<<<dim3(Dd / 256, Ll / 8, Bb), 256, 0, 0>>>(x, conv_w, conv_b);
    wsplit_kernel<<<dim3(256 * Dd / 256), 256, 0, s1>>>(in_proj, mem_w, ch_w0, ch_w1);
    cudaEventRecord(e_w, s1);
    cudaEventRecord(e_conv, 0);

    // aux chain: projH (needs conv's x-splits + its own wsplit) -> ugemm
    cudaStreamWaitEvent(s1, e_conv, 0);
    mma_projH_kernel<<<dim3(BL / 64), 256, PSMEM, s1>>>();
    ugemm_mma_kernel<<<dim3(BL / 128, Dd / 64), 256, USMEM, s1>>>(x, ch_b1);
    cudaEventRecord(e_u, s1);

    // main chain: projA (needs conv + wsplit) -> gates -> rtil
    cudaStreamWaitEvent(0, e_w, 0);
    mma_projA_kernel<<<dim3(BL / 64), 256, PSMEM, 0>>>();
    gates_kernel<<<dim3(BL / 4), 128, 0, 0>>>(mem_b);
    rtil_kernel<<<dim3(16), 128, 0, 0>>>();

    // join: scan needs u (aux) + gates/shift (main)
    cudaStreamWaitEvent(0, e_u, 0);
    scanA_kernel<<<dim3(Dd / 64, Bb, NC), 64, 0, 0>>>(res_w, out);
    phaseB_kernel<<<dim3(Dd / 64, Bb, 2), 64, 0, 0>>>();
    phaseC_kernel<<<dim3(64, Bb * (NC - 1)), 256, 0, 0>>>(out);
}